// round 3
// baseline (speedup 1.0000x reference)
#include <cuda_runtime.h>
#include <cstdint>

#define H 128
#define NLABEL 5
#define DEPTH 18
#define NNODES ((1 << DEPTH) - 1)   /* 262143 */
#define NLEAF  (1 << (DEPTH - 1))   /* 131072 */

// ---------------- device scratch (static, no allocation) ----------------
__device__ float g_WxT[H * 512];     // k-major: WxT[d*512 + gate*128 + r], gates i,o,u,f
__device__ float g_b2[512];          // bix+bih, box+boh, bux+buh, bfx
__device__ float g_WhT[H * 384];     // k-major: WhT[d*384 + gate*128 + r], gates i,o,u
__device__ float g_WfhT[H * H];      // k-major
__device__ float g_bfh[H];
__device__ float g_XG[(size_t)NNODES * 512];   // gate preacts for ALL nodes
__device__ float g_FH[(size_t)NLEAF * H];      // Wfh @ child_h (+bfh) per child, per level
__device__ float g_hbuf[2][(size_t)NLEAF * H];
__device__ float g_cbuf[2][(size_t)NLEAF * H];
__device__ double g_loss[1024];

__device__ __forceinline__ float sigm(float x) { return 1.f / (1.f + expf(-x)); }

// ---------------- weight packing (transpose to k-major) + loss zeroing ----------------
__global__ void pack_kernel(
    const float* __restrict__ Wix, const float* __restrict__ Wox,
    const float* __restrict__ Wux, const float* __restrict__ Wfx,
    const float* __restrict__ bix, const float* __restrict__ box_,
    const float* __restrict__ bux, const float* __restrict__ bfx,
    const float* __restrict__ Wih, const float* __restrict__ Woh,
    const float* __restrict__ Wuh, const float* __restrict__ Wfh,
    const float* __restrict__ bih, const float* __restrict__ boh,
    const float* __restrict__ buh, const float* __restrict__ bfh)
{
    int idx = blockIdx.x * blockDim.x + threadIdx.x;
    if (idx < H * 512) {
        int d = idx >> 9, c = idx & 511, g = c >> 7, r = c & 127;
        const float* W = (g == 0) ? Wix : (g == 1) ? Wox : (g == 2) ? Wux : Wfx;
        g_WxT[idx] = W[r * H + d];
    }
    if (idx < H * 384) {
        int d = idx / 384, c = idx % 384, g = c >> 7, r = c & 127;
        const float* W = (g == 0) ? Wih : (g == 1) ? Woh : Wuh;
        g_WhT[idx] = W[r * H + d];
    }
    if (idx < H * H) {
        int d = idx >> 7, r = idx & 127;
        g_WfhT[idx] = Wfh[r * H + d];
    }
    if (idx < 1024) g_loss[idx] = 0.0;
    if (idx < 512) {
        int g = idx >> 7, r = idx & 127;
        float v;
        if (g == 0) v = bix[r] + bih[r];
        else if (g == 1) v = box_[r] + boh[r];
        else if (g == 2) v = bux[r] + buh[r];
        else v = bfx[r];
        g_b2[idx] = v;
    }
    if (idx < H) g_bfh[idx] = bfh[idx];
}

// ---------------- GEMM block: C[128x128 tile] = op(A) @ WT + bias ----------------
// K = 128, BK = 16. WT is k-major [128][ldb]. 256 threads, 8x8 per thread.
// MODE 0: A row m = A + m*128
// MODE 1: A row m = A + ridx[m]*128    (embedding gather)
// MODE 2: A row m = A[2m] + A[2m+1]    (child-h pair sum)
template <int MODE, bool ACC, bool BIAS>
__device__ __forceinline__ void gemm_block(
    float* As, float* Bs,
    const float* __restrict__ A, const int* __restrict__ ridx,
    const float* __restrict__ WT, int ldb, const float* __restrict__ bias,
    float* __restrict__ C, int ldc, int M, int brow, int bcol)
{
    const int t    = threadIdx.x;
    const int lrow = t >> 1;           // 0..127, A-loader row
    const int lk   = (t & 1) * 8;      // 0 or 8
    const int bk   = t >> 4;           // 0..15, B-loader k
    const int bc8  = (t & 15) * 8;     // B-loader col
    const int ty   = t >> 4;           // 0..15
    const int tx   = t & 15;           // 0..15

    const int arow = brow + lrow;
    const bool av  = arow < M;
    const float* ap  = A;
    const float* ap2 = A;
    if (av) {
        if (MODE == 0)      ap = A + (size_t)arow * H;
        else if (MODE == 1) ap = A + (size_t)ridx[arow] * H;
        else { ap = A + (size_t)(2 * arow) * H; ap2 = ap + H; }
    }
    const float* wp = WT + (size_t)bk * ldb + bcol + bc8;

    float acc[8][8] = {};

    #pragma unroll
    for (int kb = 0; kb < H; kb += 16) {
        float4 a0 = make_float4(0.f, 0.f, 0.f, 0.f), a1 = a0;
        if (av) {
            a0 = *(const float4*)(ap + kb + lk);
            a1 = *(const float4*)(ap + kb + lk + 4);
            if (MODE == 2) {
                float4 c0 = *(const float4*)(ap2 + kb + lk);
                float4 c1 = *(const float4*)(ap2 + kb + lk + 4);
                a0.x += c0.x; a0.y += c0.y; a0.z += c0.z; a0.w += c0.w;
                a1.x += c1.x; a1.y += c1.y; a1.z += c1.z; a1.w += c1.w;
            }
        }
        float4 w0 = *(const float4*)(wp + (size_t)kb * ldb);
        float4 w1 = *(const float4*)(wp + (size_t)kb * ldb + 4);
        __syncthreads();
        As[(lk + 0) * 132 + lrow] = a0.x;
        As[(lk + 1) * 132 + lrow] = a0.y;
        As[(lk + 2) * 132 + lrow] = a0.z;
        As[(lk + 3) * 132 + lrow] = a0.w;
        As[(lk + 4) * 132 + lrow] = a1.x;
        As[(lk + 5) * 132 + lrow] = a1.y;
        As[(lk + 6) * 132 + lrow] = a1.z;
        As[(lk + 7) * 132 + lrow] = a1.w;
        *(float4*)&Bs[bk * 128 + bc8]     = w0;
        *(float4*)&Bs[bk * 128 + bc8 + 4] = w1;
        __syncthreads();
        #pragma unroll
        for (int k = 0; k < 16; k++) {
            float a[8], b[8];
            *(float4*)&a[0] = *(const float4*)&As[k * 132 + ty * 8];
            *(float4*)&a[4] = *(const float4*)&As[k * 132 + ty * 8 + 4];
            *(float4*)&b[0] = *(const float4*)&Bs[k * 128 + tx * 8];
            *(float4*)&b[4] = *(const float4*)&Bs[k * 128 + tx * 8 + 4];
            #pragma unroll
            for (int i = 0; i < 8; i++)
                #pragma unroll
                for (int jj = 0; jj < 8; jj++)
                    acc[i][jj] += a[i] * b[jj];
        }
    }

    #pragma unroll
    for (int i = 0; i < 8; i++) {
        int row = brow + ty * 8 + i;
        if (row < M) {
            float* cr = C + (size_t)row * ldc + bcol + tx * 8;
            #pragma unroll
            for (int jj = 0; jj < 8; jj++) {
                float v = acc[i][jj];
                if (BIAS) v += bias[bcol + tx * 8 + jj];
                if (ACC) cr[jj] += v; else cr[jj] = v;
            }
        }
    }
}

// ---------------- one-shot x-GEMM over ALL nodes ----------------
__global__ void __launch_bounds__(256) xgemm_kernel(
    const float* __restrict__ embeds, const int* __restrict__ words)
{
    __shared__ float As[16 * 132];
    __shared__ float Bs[16 * 128];
    gemm_block<1, false, true>(As, Bs, embeds, words, g_WxT, 512, g_b2,
                               g_XG, 512, NNODES,
                               (int)blockIdx.y * 128, (int)blockIdx.x * 128);
}

// ---------------- per-level h-GEMM (pairsum, acc) + f-GEMM fused launch ----------------
__global__ void __launch_bounds__(256) level_gemm(int n, int off, int chd)
{
    __shared__ float As[16 * 132];
    __shared__ float Bs[16 * 128];
    const float* h_ch = g_hbuf[chd];
    const int nbm = (n + 127) >> 7;
    const int bx  = blockIdx.x;
    if (bx < nbm * 3) {
        gemm_block<2, true, false>(As, Bs, h_ch, nullptr, g_WhT, 384, nullptr,
                                   g_XG + (size_t)off * 512, 512, n,
                                   (bx / 3) * 128, (bx % 3) * 128);
    } else {
        int fb = bx - nbm * 3;
        gemm_block<0, false, true>(As, Bs, h_ch, nullptr, g_WfhT, 128, g_bfh,
                                   g_FH, 128, 2 * n, fb * 128, 0);
    }
}

// ---------------- logits + log-softmax loss (per node, 128 threads) ----------------
__device__ __forceinline__ void logits_loss(
    float h, int k, int slot,
    const float* __restrict__ Wout, const float* __restrict__ bout,
    int label, float* __restrict__ logp_out)
{
    float p[NLABEL];
    #pragma unroll
    for (int l = 0; l < NLABEL; l++) p[l] = h * Wout[l * H + k];
    #pragma unroll
    for (int offx = 16; offx; offx >>= 1) {
        #pragma unroll
        for (int l = 0; l < NLABEL; l++)
            p[l] += __shfl_down_sync(0xffffffffu, p[l], offx);
    }
    __shared__ float sw[4][NLABEL];
    int wid = k >> 5, lane = k & 31;
    if (lane == 0) {
        #pragma unroll
        for (int l = 0; l < NLABEL; l++) sw[wid][l] = p[l];
    }
    __syncthreads();
    if (k == 0) {
        float lg[NLABEL], m = -1e30f;
        #pragma unroll
        for (int l = 0; l < NLABEL; l++) {
            lg[l] = sw[0][l] + sw[1][l] + sw[2][l] + sw[3][l] + bout[l];
            m = fmaxf(m, lg[l]);
        }
        float s = 0.f;
        #pragma unroll
        for (int l = 0; l < NLABEL; l++) s += expf(lg[l] - m);
        float lse = m + logf(s);
        atomicAdd(&g_loss[slot & 1023], (double)(lse - lg[label]));
        if (logp_out) {
            #pragma unroll
            for (int l = 0; l < NLABEL; l++) logp_out[l] = lg[l] - lse;
        }
    }
}

// ---------------- per-node gates + cell + loss (big levels) ----------------
__global__ void __launch_bounds__(128) node_update(
    int off, int cur, int chd, int isLeaf,
    const int* __restrict__ labels,
    const float* __restrict__ Wout, const float* __restrict__ bout,
    float* __restrict__ logp_out)
{
    const int j = blockIdx.x;
    const int k = threadIdx.x;
    const float* xg = g_XG + (size_t)(off + j) * 512;

    float gi = sigm(xg[k]);
    float go = sigm(xg[128 + k]);
    float gu = tanhf(xg[256 + k]);
    float c = gi * gu;
    if (!isLeaf) {
        float xf = xg[384 + k];
        size_t c0 = (size_t)(2 * j) * H + k;
        c += sigm(xf + g_FH[c0])     * g_cbuf[chd][c0]
           + sigm(xf + g_FH[c0 + H]) * g_cbuf[chd][c0 + H];
    }
    float h = go * tanhf(c);
    g_cbuf[cur][(size_t)j * H + k] = c;
    g_hbuf[cur][(size_t)j * H + k] = h;

    logits_loss(h, k, off + j, Wout, bout, labels[j], logp_out);
}

// ---------------- fully fused small level (n <= 64): GEMV + gates + loss ----------------
__global__ void __launch_bounds__(128) small_level(
    int off, int cur, int chd,
    const int* __restrict__ labels,
    const float* __restrict__ Wout, const float* __restrict__ bout,
    float* __restrict__ logp_out)
{
    const int j = blockIdx.x;
    const int k = threadIdx.x;
    __shared__ float hs[H], h0s[H], h1s[H];

    size_t cb = (size_t)(2 * j) * H + k;
    float h0 = g_hbuf[chd][cb], h1 = g_hbuf[chd][cb + H];
    h0s[k] = h0; h1s[k] = h1; hs[k] = h0 + h1;
    __syncthreads();

    const float* xg = g_XG + (size_t)(off + j) * 512;
    float ai = xg[k], ao = xg[128 + k], au = xg[256 + k], xf = xg[384 + k];
    float f0 = g_bfh[k], f1 = g_bfh[k];
    #pragma unroll 8
    for (int d = 0; d < H; d++) {
        float hd = hs[d];
        ai += hd * g_WhT[d * 384 + k];
        ao += hd * g_WhT[d * 384 + 128 + k];
        au += hd * g_WhT[d * 384 + 256 + k];
        float w = g_WfhT[d * 128 + k];
        f0 += h0s[d] * w;
        f1 += h1s[d] * w;
    }
    float gi = sigm(ai), go = sigm(ao), gu = tanhf(au);
    float c = gi * gu + sigm(xf + f0) * g_cbuf[chd][cb]
                      + sigm(xf + f1) * g_cbuf[chd][cb + H];
    float h = go * tanhf(c);
    g_cbuf[cur][(size_t)j * H + k] = c;
    g_hbuf[cur][(size_t)j * H + k] = h;

    logits_loss(h, k, off + j, Wout, bout, labels[j], logp_out);
}

// ---------------- loss reduction ----------------
__global__ void finalize_kernel(float* __restrict__ d_out, int out_size)
{
    __shared__ double s[256];
    int t = threadIdx.x;
    s[t] = g_loss[t] + g_loss[t + 256] + g_loss[t + 512] + g_loss[t + 768];
    __syncthreads();
    for (int offx = 128; offx; offx >>= 1) {
        if (t < offx) s[t] += s[t + offx];
        __syncthreads();
    }
    if (t == 0) {
        if (out_size >= NLABEL + 1) d_out[NLABEL] = (float)s[0];
        else                        d_out[0]      = (float)s[0];
    }
}

// ---------------- launch ----------------
extern "C" void kernel_launch(void* const* d_in, const int* in_sizes, int n_in,
                              void* d_out, int out_size)
{
    const float* embeds = (const float*)d_in[0];
    const int*   words  = (const int*)d_in[1];
    const int*   labels = (const int*)d_in[2];
    const float* Wix = (const float*)d_in[5];
    const float* bix = (const float*)d_in[6];
    const float* Wih = (const float*)d_in[7];
    const float* bih = (const float*)d_in[8];
    const float* Wfx = (const float*)d_in[9];
    const float* bfx = (const float*)d_in[10];
    const float* Wfh = (const float*)d_in[11];
    const float* bfh = (const float*)d_in[12];
    const float* Wox = (const float*)d_in[13];
    const float* box_ = (const float*)d_in[14];
    const float* Woh = (const float*)d_in[15];
    const float* boh = (const float*)d_in[16];
    const float* Wux = (const float*)d_in[17];
    const float* bux = (const float*)d_in[18];
    const float* Wuh = (const float*)d_in[19];
    const float* buh = (const float*)d_in[20];
    const float* Wout = (const float*)d_in[21];
    const float* bout = (const float*)d_in[22];
    float* out = (float*)d_out;

    pack_kernel<<<256, 256>>>(Wix, Wox, Wux, Wfx, bix, box_, bux, bfx,
                              Wih, Woh, Wuh, Wfh, bih, boh, buh, bfh);

    dim3 gx(4, (NNODES + 127) / 128);
    xgemm_kernel<<<gx, 256>>>(embeds, words);

    for (int l = DEPTH - 1; l >= 0; --l) {
        int n   = 1 << l;
        int off = n - 1;
        int cur = l & 1, chd = cur ^ 1;
        float* logp_dst = (l == 0 && out_size >= NLABEL + 1) ? out : nullptr;

        if (l == DEPTH - 1) {
            node_update<<<n, 128>>>(off, cur, chd, 1, labels + off, Wout, bout, nullptr);
        } else if (n >= 128) {
            int nbm = (n + 127) / 128;
            int nbf = (2 * n + 127) / 128;
            level_gemm<<<nbm * 3 + nbf, 256>>>(n, off, chd);
            node_update<<<n, 128>>>(off, cur, chd, 0, labels + off, Wout, bout, logp_dst);
        } else {
            small_level<<<n, 128>>>(off, cur, chd, labels + off, Wout, bout, logp_dst);
        }
    }
    finalize_kernel<<<1, 256>>>(out, out_size);
}

// round 4
// speedup vs baseline: 1.8794x; 1.8794x over previous
#include <cuda_runtime.h>
#include <cstdint>

#define H 128
#define NLABEL 5
#define DEPTH 18
#define NNODES ((1 << DEPTH) - 1)   /* 262143 */
#define NLEAF  (1 << (DEPTH - 1))   /* 131072 */

// ---------------- device scratch (static, no allocation) ----------------
__device__ float g_WxT[H * 512];     // k-major: WxT[d*512 + gate*128 + r], gates i,o,u,f
__device__ float g_b2[512];          // bix+bih, box+boh, bux+buh, bfx
__device__ float g_WhT[H * 384];     // k-major: WhT[d*384 + gate*128 + r], gates i,o,u
__device__ float g_WfhT[H * H];      // k-major
__device__ float g_bfh[H];
__device__ float g_XG[(size_t)NNODES * 512];   // gate preacts for ALL nodes
__device__ float g_FH[(size_t)NLEAF * H];      // Wfh @ child_h (+bfh) per child, per level
__device__ float g_hbuf[2][(size_t)NLEAF * H];
__device__ float g_cbuf[2][(size_t)NLEAF * H];
__device__ double g_loss[1024];

__device__ __forceinline__ float sigm(float x) { return 1.f / (1.f + expf(-x)); }

// ---------------- weight packing (transpose to k-major) + loss zeroing ----------------
__global__ void pack_kernel(
    const float* __restrict__ Wix, const float* __restrict__ Wox,
    const float* __restrict__ Wux, const float* __restrict__ Wfx,
    const float* __restrict__ bix, const float* __restrict__ box_,
    const float* __restrict__ bux, const float* __restrict__ bfx,
    const float* __restrict__ Wih, const float* __restrict__ Woh,
    const float* __restrict__ Wuh, const float* __restrict__ Wfh,
    const float* __restrict__ bih, const float* __restrict__ boh,
    const float* __restrict__ buh, const float* __restrict__ bfh)
{
    int idx = blockIdx.x * blockDim.x + threadIdx.x;
    if (idx < H * 512) {
        int d = idx >> 9, c = idx & 511, g = c >> 7, r = c & 127;
        const float* W = (g == 0) ? Wix : (g == 1) ? Wox : (g == 2) ? Wux : Wfx;
        g_WxT[idx] = W[r * H + d];
    }
    if (idx < H * 384) {
        int d = idx / 384, c = idx % 384, g = c >> 7, r = c & 127;
        const float* W = (g == 0) ? Wih : (g == 1) ? Woh : Wuh;
        g_WhT[idx] = W[r * H + d];
    }
    if (idx < H * H) {
        int d = idx >> 7, r = idx & 127;
        g_WfhT[idx] = Wfh[r * H + d];
    }
    if (idx < 1024) g_loss[idx] = 0.0;
    if (idx < 512) {
        int g = idx >> 7, r = idx & 127;
        float v;
        if (g == 0) v = bix[r] + bih[r];
        else if (g == 1) v = box_[r] + boh[r];
        else if (g == 2) v = bux[r] + buh[r];
        else v = bfx[r];
        g_b2[idx] = v;
    }
    if (idx < H) g_bfh[idx] = bfh[idx];
}

// ---------------- GEMM block: C[128x64 tile] = op(A) @ WT + bias ----------------
// K = 128, BK = 16, BM = 128, BN = 64. WT is k-major [128][ldb].
// 256 threads, 8x4 per thread. Double-buffered smem.
// MODE 0: A row m = A + m*128
// MODE 1: A row m = A + ridx[m]*128    (embedding gather)
// MODE 2: A row m = A[2m] + A[2m+1]    (child-h pair sum)
#define AS_LD 132
#define BS_LD 64
template <int MODE, bool ACC, bool BIAS>
__device__ __forceinline__ void gemm_block(
    float* As, float* Bs,       // As[2][16*AS_LD], Bs[2][16*BS_LD]
    const float* __restrict__ A, const int* __restrict__ ridx,
    const float* __restrict__ WT, int ldb, const float* __restrict__ bias,
    float* __restrict__ C, int ldc, int M, int brow, int bcol)
{
    const int t    = threadIdx.x;
    const int lrow = t >> 1;           // 0..127, A-loader row
    const int lk   = (t & 1) * 8;      // 0 or 8
    const int bk   = t >> 4;           // 0..15, B-loader k
    const int bc4  = (t & 15) * 4;     // B-loader col
    const int ty   = t >> 4;           // 0..15  (8 rows each)
    const int tx   = t & 15;           // 0..15  (4 cols each)

    const int arow = brow + lrow;
    const bool av  = arow < M;
    const float* ap  = A;
    const float* ap2 = A;
    if (av) {
        if (MODE == 0)      ap = A + (size_t)arow * H;
        else if (MODE == 1) ap = A + (size_t)ridx[arow] * H;
        else { ap = A + (size_t)(2 * arow) * H; ap2 = ap + H; }
    }
    const float* wp = WT + (size_t)bk * ldb + bcol + bc4;

    float acc[8][4] = {};

    // prefetch k-block 0
    float4 pa0 = make_float4(0.f,0.f,0.f,0.f), pa1 = pa0;
    if (av) {
        pa0 = *(const float4*)(ap + lk);
        pa1 = *(const float4*)(ap + lk + 4);
        if (MODE == 2) {
            float4 q0 = *(const float4*)(ap2 + lk);
            float4 q1 = *(const float4*)(ap2 + lk + 4);
            pa0.x += q0.x; pa0.y += q0.y; pa0.z += q0.z; pa0.w += q0.w;
            pa1.x += q1.x; pa1.y += q1.y; pa1.z += q1.z; pa1.w += q1.w;
        }
    }
    float4 pw = *(const float4*)wp;

    {   // store k-block 0
        float* as0 = As;
        as0[(lk + 0) * AS_LD + lrow] = pa0.x;
        as0[(lk + 1) * AS_LD + lrow] = pa0.y;
        as0[(lk + 2) * AS_LD + lrow] = pa0.z;
        as0[(lk + 3) * AS_LD + lrow] = pa0.w;
        as0[(lk + 4) * AS_LD + lrow] = pa1.x;
        as0[(lk + 5) * AS_LD + lrow] = pa1.y;
        as0[(lk + 6) * AS_LD + lrow] = pa1.z;
        as0[(lk + 7) * AS_LD + lrow] = pa1.w;
        *(float4*)&Bs[bk * BS_LD + bc4] = pw;
    }
    __syncthreads();

    #pragma unroll
    for (int kb = 0; kb < 8; kb++) {
        const int cur = kb & 1;
        // prefetch next k-block
        if (kb < 7) {
            const int ko = (kb + 1) * 16;
            pa0 = make_float4(0.f,0.f,0.f,0.f); pa1 = pa0;
            if (av) {
                pa0 = *(const float4*)(ap + ko + lk);
                pa1 = *(const float4*)(ap + ko + lk + 4);
                if (MODE == 2) {
                    float4 q0 = *(const float4*)(ap2 + ko + lk);
                    float4 q1 = *(const float4*)(ap2 + ko + lk + 4);
                    pa0.x += q0.x; pa0.y += q0.y; pa0.z += q0.z; pa0.w += q0.w;
                    pa1.x += q1.x; pa1.y += q1.y; pa1.z += q1.z; pa1.w += q1.w;
                }
            }
            pw = *(const float4*)(wp + (size_t)ko * ldb);
        }
        // compute on buffer cur
        const float* as = As + cur * (16 * AS_LD);
        const float* bs = Bs + cur * (16 * BS_LD);
        #pragma unroll
        for (int k = 0; k < 16; k++) {
            float a[8], b[4];
            *(float4*)&a[0] = *(const float4*)&as[k * AS_LD + ty * 8];
            *(float4*)&a[4] = *(const float4*)&as[k * AS_LD + ty * 8 + 4];
            *(float4*)&b[0] = *(const float4*)&bs[k * BS_LD + tx * 4];
            #pragma unroll
            for (int i = 0; i < 8; i++)
                #pragma unroll
                for (int jj = 0; jj < 4; jj++)
                    acc[i][jj] += a[i] * b[jj];
        }
        // store next into alternate buffer (safe: one sync/iter)
        if (kb < 7) {
            float* asn = As + (1 - cur) * (16 * AS_LD);
            float* bsn = Bs + (1 - cur) * (16 * BS_LD);
            asn[(lk + 0) * AS_LD + lrow] = pa0.x;
            asn[(lk + 1) * AS_LD + lrow] = pa0.y;
            asn[(lk + 2) * AS_LD + lrow] = pa0.z;
            asn[(lk + 3) * AS_LD + lrow] = pa0.w;
            asn[(lk + 4) * AS_LD + lrow] = pa1.x;
            asn[(lk + 5) * AS_LD + lrow] = pa1.y;
            asn[(lk + 6) * AS_LD + lrow] = pa1.z;
            asn[(lk + 7) * AS_LD + lrow] = pa1.w;
            *(float4*)&bsn[bk * BS_LD + bc4] = pw;
            __syncthreads();
        }
    }

    #pragma unroll
    for (int i = 0; i < 8; i++) {
        int row = brow + ty * 8 + i;
        if (row < M) {
            float* cr = C + (size_t)row * ldc + bcol + tx * 4;
            #pragma unroll
            for (int jj = 0; jj < 4; jj++) {
                float v = acc[i][jj];
                if (BIAS) v += bias[bcol + tx * 4 + jj];
                if (ACC) cr[jj] += v; else cr[jj] = v;
            }
        }
    }
}

#define GEMM_SMEM \
    __shared__ float As[2 * 16 * AS_LD]; \
    __shared__ float Bs[2 * 16 * BS_LD];

// ---------------- one-shot x-GEMM over ALL nodes ----------------
__global__ void __launch_bounds__(256, 2) xgemm_kernel(
    const float* __restrict__ embeds, const int* __restrict__ words)
{
    GEMM_SMEM
    gemm_block<1, false, true>(As, Bs, embeds, words, g_WxT, 512, g_b2,
                               g_XG, 512, NNODES,
                               (int)blockIdx.y * 128, (int)blockIdx.x * 64);
}

// ---------------- per-level h-GEMM (pairsum, acc) + f-GEMM fused launch ----------------
__global__ void __launch_bounds__(256, 2) level_gemm(int n, int off, int chd)
{
    GEMM_SMEM
    const float* h_ch = g_hbuf[chd];
    const int nbm = (n + 127) >> 7;
    const int bx  = blockIdx.x;
    if (bx < nbm * 6) {
        gemm_block<2, true, false>(As, Bs, h_ch, nullptr, g_WhT, 384, nullptr,
                                   g_XG + (size_t)off * 512, 512, n,
                                   (bx / 6) * 128, (bx % 6) * 64);
    } else {
        int fb = bx - nbm * 6;
        gemm_block<0, false, true>(As, Bs, h_ch, nullptr, g_WfhT, 128, g_bfh,
                                   g_FH, 128, 2 * n, (fb >> 1) * 128, (fb & 1) * 64);
    }
}

// ---------------- logits + log-softmax loss (per node, 128 threads) ----------------
__device__ __forceinline__ void logits_loss(
    float h, int k, int slot,
    const float* __restrict__ Wout, const float* __restrict__ bout,
    int label, float* __restrict__ logp_out)
{
    float p[NLABEL];
    #pragma unroll
    for (int l = 0; l < NLABEL; l++) p[l] = h * Wout[l * H + k];
    #pragma unroll
    for (int offx = 16; offx; offx >>= 1) {
        #pragma unroll
        for (int l = 0; l < NLABEL; l++)
            p[l] += __shfl_down_sync(0xffffffffu, p[l], offx);
    }
    __shared__ float sw[4][NLABEL];
    int wid = k >> 5, lane = k & 31;
    if (lane == 0) {
        #pragma unroll
        for (int l = 0; l < NLABEL; l++) sw[wid][l] = p[l];
    }
    __syncthreads();
    if (k == 0) {
        float lg[NLABEL], m = -1e30f;
        #pragma unroll
        for (int l = 0; l < NLABEL; l++) {
            lg[l] = sw[0][l] + sw[1][l] + sw[2][l] + sw[3][l] + bout[l];
            m = fmaxf(m, lg[l]);
        }
        float s = 0.f;
        #pragma unroll
        for (int l = 0; l < NLABEL; l++) s += expf(lg[l] - m);
        float lse = m + logf(s);
        atomicAdd(&g_loss[slot & 1023], (double)(lse - lg[label]));
        if (logp_out) {
            #pragma unroll
            for (int l = 0; l < NLABEL; l++) logp_out[l] = lg[l] - lse;
        }
    }
}

// ---------------- per-node gates + cell + loss (big levels) ----------------
__global__ void __launch_bounds__(128) node_update(
    int off, int cur, int chd, int isLeaf,
    const int* __restrict__ labels,
    const float* __restrict__ Wout, const float* __restrict__ bout,
    float* __restrict__ logp_out)
{
    const int j = blockIdx.x;
    const int k = threadIdx.x;
    const float* xg = g_XG + (size_t)(off + j) * 512;

    float gi = sigm(xg[k]);
    float go = sigm(xg[128 + k]);
    float gu = tanhf(xg[256 + k]);
    float c = gi * gu;
    if (!isLeaf) {
        float xf = xg[384 + k];
        size_t c0 = (size_t)(2 * j) * H + k;
        c += sigm(xf + g_FH[c0])     * g_cbuf[chd][c0]
           + sigm(xf + g_FH[c0 + H]) * g_cbuf[chd][c0 + H];
    }
    float h = go * tanhf(c);
    g_cbuf[cur][(size_t)j * H + k] = c;
    g_hbuf[cur][(size_t)j * H + k] = h;

    logits_loss(h, k, off + j, Wout, bout, labels[j], logp_out);
}

// ---------------- fully fused small level (n <= 64): GEMV + gates + loss ----------------
__global__ void __launch_bounds__(128) small_level(
    int off, int cur, int chd,
    const int* __restrict__ labels,
    const float* __restrict__ Wout, const float* __restrict__ bout,
    float* __restrict__ logp_out)
{
    const int j = blockIdx.x;
    const int k = threadIdx.x;
    __shared__ float hs[H], h0s[H], h1s[H];

    size_t cb = (size_t)(2 * j) * H + k;
    float h0 = g_hbuf[chd][cb], h1 = g_hbuf[chd][cb + H];
    h0s[k] = h0; h1s[k] = h1; hs[k] = h0 + h1;
    __syncthreads();

    const float* xg = g_XG + (size_t)(off + j) * 512;
    float ai = xg[k], ao = xg[128 + k], au = xg[256 + k], xf = xg[384 + k];
    float f0 = g_bfh[k], f1 = g_bfh[k];
    #pragma unroll 8
    for (int d = 0; d < H; d++) {
        float hd = hs[d];
        ai += hd * g_WhT[d * 384 + k];
        ao += hd * g_WhT[d * 384 + 128 + k];
        au += hd * g_WhT[d * 384 + 256 + k];
        float w = g_WfhT[d * 128 + k];
        f0 += h0s[d] * w;
        f1 += h1s[d] * w;
    }
    float gi = sigm(ai), go = sigm(ao), gu = tanhf(au);
    float c = gi * gu + sigm(xf + f0) * g_cbuf[chd][cb]
                      + sigm(xf + f1) * g_cbuf[chd][cb + H];
    float h = go * tanhf(c);
    g_cbuf[cur][(size_t)j * H + k] = c;
    g_hbuf[cur][(size_t)j * H + k] = h;

    logits_loss(h, k, off + j, Wout, bout, labels[j], logp_out);
}

// ---------------- loss reduction ----------------
__global__ void finalize_kernel(float* __restrict__ d_out, int out_size)
{
    __shared__ double s[256];
    int t = threadIdx.x;
    s[t] = g_loss[t] + g_loss[t + 256] + g_loss[t + 512] + g_loss[t + 768];
    __syncthreads();
    for (int offx = 128; offx; offx >>= 1) {
        if (t < offx) s[t] += s[t + offx];
        __syncthreads();
    }
    if (t == 0) {
        if (out_size >= NLABEL + 1) d_out[NLABEL] = (float)s[0];
        else                        d_out[0]      = (float)s[0];
    }
}

// ---------------- launch ----------------
extern "C" void kernel_launch(void* const* d_in, const int* in_sizes, int n_in,
                              void* d_out, int out_size)
{
    const float* embeds = (const float*)d_in[0];
    const int*   words  = (const int*)d_in[1];
    const int*   labels = (const int*)d_in[2];
    const float* Wix = (const float*)d_in[5];
    const float* bix = (const float*)d_in[6];
    const float* Wih = (const float*)d_in[7];
    const float* bih = (const float*)d_in[8];
    const float* Wfx = (const float*)d_in[9];
    const float* bfx = (const float*)d_in[10];
    const float* Wfh = (const float*)d_in[11];
    const float* bfh = (const float*)d_in[12];
    const float* Wox = (const float*)d_in[13];
    const float* box_ = (const float*)d_in[14];
    const float* Woh = (const float*)d_in[15];
    const float* boh = (const float*)d_in[16];
    const float* Wux = (const float*)d_in[17];
    const float* bux = (const float*)d_in[18];
    const float* Wuh = (const float*)d_in[19];
    const float* buh = (const float*)d_in[20];
    const float* Wout = (const float*)d_in[21];
    const float* bout = (const float*)d_in[22];
    float* out = (float*)d_out;

    pack_kernel<<<256, 256>>>(Wix, Wox, Wux, Wfx, bix, box_, bux, bfx,
                              Wih, Woh, Wuh, Wfh, bih, boh, buh, bfh);

    dim3 gx(8, (NNODES + 127) / 128);
    xgemm_kernel<<<gx, 256>>>(embeds, words);

    for (int l = DEPTH - 1; l >= 0; --l) {
        int n   = 1 << l;
        int off = n - 1;
        int cur = l & 1, chd = cur ^ 1;
        float* logp_dst = (l == 0 && out_size >= NLABEL + 1) ? out : nullptr;

        if (l == DEPTH - 1) {
            node_update<<<n, 128>>>(off, cur, chd, 1, labels + off, Wout, bout, nullptr);
        } else if (n >= 128) {
            int nbm = (n + 127) / 128;
            int nbf = ((2 * n + 127) / 128) * 2;
            level_gemm<<<nbm * 6 + nbf, 256>>>(n, off, chd);
            node_update<<<n, 128>>>(off, cur, chd, 0, labels + off, Wout, bout, logp_dst);
        } else {
            small_level<<<n, 128>>>(off, cur, chd, labels + off, Wout, bout, logp_dst);
        }
    }
    finalize_kernel<<<1, 256>>>(out, out_size);
}

// round 5
// speedup vs baseline: 3.0421x; 1.6187x over previous
#include <cuda_runtime.h>
#include <cstdint>

#define H 128
#define NLABEL 5
#define DEPTH 18
#define NNODES ((1 << DEPTH) - 1)   /* 262143 */
#define NLEAF  (1 << (DEPTH - 1))   /* 131072 */

// ---------------- device scratch (static, no allocation) ----------------
__device__ float g_WxT[H * 512];     // k-major: WxT[d*512 + gate*128 + r], gates i,o,u,f
__device__ float g_b2[512];          // bix+bih, box+boh, bux+buh, bfx
__device__ float g_WhT[H * 384];     // k-major: WhT[d*384 + gate*128 + r], gates i,o,u
__device__ float g_WfhT[H * H];      // k-major
__device__ float g_bfh[H];
__device__ float g_XG[(size_t)NNODES * 512];   // gate preacts for ALL nodes
__device__ float g_FH[(size_t)NLEAF * H];      // Wfh @ child_h (+bfh) per child, per level
__device__ float g_hbuf[2][(size_t)NLEAF * H];
__device__ float g_cbuf[2][(size_t)NLEAF * H];
__device__ double g_loss[1024];

__device__ __forceinline__ float sigm(float x) { return 1.f / (1.f + expf(-x)); }

__device__ __forceinline__ uint32_t f2tf(float x) {
    uint32_t r;
    asm("cvt.rna.tf32.f32 %0, %1;" : "=r"(r) : "f"(x));
    return r;
}

__device__ __forceinline__ void mma_tf32(float c[4],
    uint32_t a0, uint32_t a1, uint32_t a2, uint32_t a3,
    uint32_t b0, uint32_t b1)
{
    asm volatile(
        "mma.sync.aligned.m16n8k8.row.col.f32.tf32.tf32.f32 "
        "{%0,%1,%2,%3},{%4,%5,%6,%7},{%8,%9},{%0,%1,%2,%3};"
        : "+f"(c[0]), "+f"(c[1]), "+f"(c[2]), "+f"(c[3])
        : "r"(a0), "r"(a1), "r"(a2), "r"(a3), "r"(b0), "r"(b1));
}

// ---------------- weight packing (transpose to k-major) + loss zeroing ----------------
__global__ void pack_kernel(
    const float* __restrict__ Wix, const float* __restrict__ Wox,
    const float* __restrict__ Wux, const float* __restrict__ Wfx,
    const float* __restrict__ bix, const float* __restrict__ box_,
    const float* __restrict__ bux, const float* __restrict__ bfx,
    const float* __restrict__ Wih, const float* __restrict__ Woh,
    const float* __restrict__ Wuh, const float* __restrict__ Wfh,
    const float* __restrict__ bih, const float* __restrict__ boh,
    const float* __restrict__ buh, const float* __restrict__ bfh)
{
    int idx = blockIdx.x * blockDim.x + threadIdx.x;
    if (idx < H * 512) {
        int d = idx >> 9, c = idx & 511, g = c >> 7, r = c & 127;
        const float* W = (g == 0) ? Wix : (g == 1) ? Wox : (g == 2) ? Wux : Wfx;
        g_WxT[idx] = W[r * H + d];
    }
    if (idx < H * 384) {
        int d = idx / 384, c = idx % 384, g = c >> 7, r = c & 127;
        const float* W = (g == 0) ? Wih : (g == 1) ? Woh : Wuh;
        g_WhT[idx] = W[r * H + d];
    }
    if (idx < H * H) {
        int d = idx >> 7, r = idx & 127;
        g_WfhT[idx] = Wfh[r * H + d];
    }
    if (idx < 1024) g_loss[idx] = 0.0;
    if (idx < 512) {
        int g = idx >> 7, r = idx & 127;
        float v;
        if (g == 0) v = bix[r] + bih[r];
        else if (g == 1) v = box_[r] + boh[r];
        else if (g == 2) v = bux[r] + buh[r];
        else v = bfx[r];
        g_b2[idx] = v;
    }
    if (idx < H) g_bfh[idx] = bfh[idx];
}

// ---------------- tf32 MMA GEMM block: C[128x128 tile] = op(A) @ WT (+bias) ----------------
// K = 128, BK = 16 double-buffered. WT k-major [128][ldb]. 256 threads = 8 warps (2m x 4n),
// warp tile 64x32 = 4 m-frags x 4 n-frags of mma.m16n8k8.
// MODE 0: A row m = A + m*128
// MODE 1: A row m = A + ridx[m]*128    (embedding gather)
// MODE 2: A row m = A[2m] + A[2m+1]    (child-h pair sum)
#define AS_LD 20      /* floats per A smem row (16 + pad) */
#define BS_LD 136     /* floats per B smem k-row (128 + pad) */
#define AS_BUF (128 * AS_LD)
#define BS_BUF (16 * BS_LD)

template <int MODE, bool ACC, bool BIAS>
__device__ __forceinline__ void gemm_block_mma(
    uint32_t* AsU, uint32_t* BsU,
    const float* __restrict__ A, const int* __restrict__ ridx,
    const float* __restrict__ WT, int ldb, const float* __restrict__ bias,
    float* __restrict__ C, int ldc, int M, int brow, int bcol)
{
    const int t    = threadIdx.x;
    const int lane = t & 31;
    const int warp = t >> 5;
    const int mw   = warp & 1;      // 0..1
    const int nw   = warp >> 1;     // 0..3
    const int g    = lane >> 2;     // 0..7
    const int t4   = lane & 3;      // 0..3

    const int lrow = t >> 1;        // 0..127 A-loader row
    const int lk   = (t & 1) * 8;   // 0 or 8
    const int bk_  = t >> 4;        // 0..15 B-loader k
    const int bn   = (t & 15) * 8;  // 0..120 B-loader col

    const int arow = brow + lrow;
    const bool av  = arow < M;
    const float* ap  = A;
    const float* ap2 = A;
    if (av) {
        if (MODE == 0)      ap = A + (size_t)arow * H;
        else if (MODE == 1) ap = A + (size_t)ridx[arow] * H;
        else { ap = A + (size_t)(2 * arow) * H; ap2 = ap + H; }
    }
    const float* wp = WT + (size_t)bk_ * ldb + bcol + bn;

    float acc[4][4][4];
    #pragma unroll
    for (int i = 0; i < 4; i++)
        #pragma unroll
        for (int j = 0; j < 4; j++)
            #pragma unroll
            for (int q = 0; q < 4; q++) acc[i][j][q] = 0.f;

    uint32_t pa[8], pb[8];

    auto fetch = [&](int kb) {
        float4 x0 = make_float4(0.f,0.f,0.f,0.f), x1 = x0;
        if (av) {
            x0 = *(const float4*)(ap + kb + lk);
            x1 = *(const float4*)(ap + kb + lk + 4);
            if (MODE == 2) {
                float4 y0 = *(const float4*)(ap2 + kb + lk);
                float4 y1 = *(const float4*)(ap2 + kb + lk + 4);
                x0.x += y0.x; x0.y += y0.y; x0.z += y0.z; x0.w += y0.w;
                x1.x += y1.x; x1.y += y1.y; x1.z += y1.z; x1.w += y1.w;
            }
        }
        pa[0]=f2tf(x0.x); pa[1]=f2tf(x0.y); pa[2]=f2tf(x0.z); pa[3]=f2tf(x0.w);
        pa[4]=f2tf(x1.x); pa[5]=f2tf(x1.y); pa[6]=f2tf(x1.z); pa[7]=f2tf(x1.w);
        float4 w0 = *(const float4*)(wp + (size_t)kb * ldb);
        float4 w1 = *(const float4*)(wp + (size_t)kb * ldb + 4);
        pb[0]=f2tf(w0.x); pb[1]=f2tf(w0.y); pb[2]=f2tf(w0.z); pb[3]=f2tf(w0.w);
        pb[4]=f2tf(w1.x); pb[5]=f2tf(w1.y); pb[6]=f2tf(w1.z); pb[7]=f2tf(w1.w);
    };
    auto stage = [&](int buf) {
        uint32_t* as = AsU + buf * AS_BUF;
        uint32_t* bs = BsU + buf * BS_BUF;
        *(uint4*)&as[lrow * AS_LD + lk]     = make_uint4(pa[0], pa[1], pa[2], pa[3]);
        *(uint4*)&as[lrow * AS_LD + lk + 4] = make_uint4(pa[4], pa[5], pa[6], pa[7]);
        *(uint4*)&bs[bk_ * BS_LD + bn]      = make_uint4(pb[0], pb[1], pb[2], pb[3]);
        *(uint4*)&bs[bk_ * BS_LD + bn + 4]  = make_uint4(pb[4], pb[5], pb[6], pb[7]);
    };

    fetch(0);
    stage(0);
    __syncthreads();

    #pragma unroll
    for (int kb = 0; kb < 8; kb++) {
        const int cur = kb & 1;
        if (kb < 7) fetch((kb + 1) * 16);
        const uint32_t* as = AsU + cur * AS_BUF;
        const uint32_t* bs = BsU + cur * BS_BUF;
        #pragma unroll
        for (int ks = 0; ks < 2; ks++) {
            uint32_t bf[4][2];
            #pragma unroll
            for (int nf = 0; nf < 4; nf++) {
                int ncol = nw * 32 + nf * 8 + g;
                bf[nf][0] = bs[(ks * 8 + t4) * BS_LD + ncol];
                bf[nf][1] = bs[(ks * 8 + t4 + 4) * BS_LD + ncol];
            }
            #pragma unroll
            for (int mf = 0; mf < 4; mf++) {
                int r0 = (mw * 64 + mf * 16 + g) * AS_LD + ks * 8 + t4;
                uint32_t a0 = as[r0];
                uint32_t a1 = as[r0 + 8 * AS_LD];
                uint32_t a2 = as[r0 + 4];
                uint32_t a3 = as[r0 + 8 * AS_LD + 4];
                #pragma unroll
                for (int nf = 0; nf < 4; nf++)
                    mma_tf32(acc[mf][nf], a0, a1, a2, a3, bf[nf][0], bf[nf][1]);
            }
        }
        if (kb < 7) {
            stage(1 - cur);
            __syncthreads();
        }
    }

    // epilogue
    #pragma unroll
    for (int mf = 0; mf < 4; mf++) {
        #pragma unroll
        for (int nf = 0; nf < 4; nf++) {
            int row = brow + mw * 64 + mf * 16 + g;
            int col = bcol + nw * 32 + nf * 8 + 2 * t4;
            float b0 = 0.f, b1 = 0.f;
            if (BIAS) { b0 = bias[col]; b1 = bias[col + 1]; }
            if (row < M) {
                float* p = C + (size_t)row * ldc + col;
                float v0 = acc[mf][nf][0] + b0;
                float v1 = acc[mf][nf][1] + b1;
                if (ACC) { v0 += p[0]; v1 += p[1]; }
                p[0] = v0; p[1] = v1;
            }
            if (row + 8 < M) {
                float* p = C + (size_t)(row + 8) * ldc + col;
                float v0 = acc[mf][nf][2] + b0;
                float v1 = acc[mf][nf][3] + b1;
                if (ACC) { v0 += p[0]; v1 += p[1]; }
                p[0] = v0; p[1] = v1;
            }
        }
    }
}

#define GEMM_SMEM \
    __shared__ __align__(16) uint32_t AsU[2 * AS_BUF]; \
    __shared__ __align__(16) uint32_t BsU[2 * BS_BUF];

// ---------------- one-shot x-GEMM over ALL nodes ----------------
__global__ void __launch_bounds__(256, 2) xgemm_kernel(
    const float* __restrict__ embeds, const int* __restrict__ words)
{
    GEMM_SMEM
    gemm_block_mma<1, false, true>(AsU, BsU, embeds, words, g_WxT, 512, g_b2,
                                   g_XG, 512, NNODES,
                                   (int)blockIdx.y * 128, (int)blockIdx.x * 128);
}

// ---------------- per-level h-GEMM (pairsum, acc) + f-GEMM fused launch ----------------
__global__ void __launch_bounds__(256, 2) level_gemm(int n, int off, int chd)
{
    GEMM_SMEM
    const float* h_ch = g_hbuf[chd];
    const int nbm = n >> 7;
    const int bx  = blockIdx.x;
    if (bx < nbm * 3) {
        gemm_block_mma<2, true, false>(AsU, BsU, h_ch, nullptr, g_WhT, 384, nullptr,
                                       g_XG + (size_t)off * 512, 512, n,
                                       (bx / 3) * 128, (bx % 3) * 128);
    } else {
        int fb = bx - nbm * 3;
        gemm_block_mma<0, false, true>(AsU, BsU, h_ch, nullptr, g_WfhT, 128, g_bfh,
                                       g_FH, 128, 2 * n, fb * 128, 0);
    }
}

// ---------------- logits + log-softmax loss (per node, 128 threads) ----------------
__device__ __forceinline__ void logits_loss(
    float h, int k, int slot,
    const float* __restrict__ Wout, const float* __restrict__ bout,
    int label, float* __restrict__ logp_out)
{
    float p[NLABEL];
    #pragma unroll
    for (int l = 0; l < NLABEL; l++) p[l] = h * Wout[l * H + k];
    #pragma unroll
    for (int offx = 16; offx; offx >>= 1) {
        #pragma unroll
        for (int l = 0; l < NLABEL; l++)
            p[l] += __shfl_down_sync(0xffffffffu, p[l], offx);
    }
    __shared__ float sw[4][NLABEL];
    int wid = k >> 5, lane = k & 31;
    if (lane == 0) {
        #pragma unroll
        for (int l = 0; l < NLABEL; l++) sw[wid][l] = p[l];
    }
    __syncthreads();
    if (k == 0) {
        float lg[NLABEL], m = -1e30f;
        #pragma unroll
        for (int l = 0; l < NLABEL; l++) {
            lg[l] = sw[0][l] + sw[1][l] + sw[2][l] + sw[3][l] + bout[l];
            m = fmaxf(m, lg[l]);
        }
        float s = 0.f;
        #pragma unroll
        for (int l = 0; l < NLABEL; l++) s += expf(lg[l] - m);
        float lse = m + logf(s);
        atomicAdd(&g_loss[slot & 1023], (double)(lse - lg[label]));
        if (logp_out) {
            #pragma unroll
            for (int l = 0; l < NLABEL; l++) logp_out[l] = lg[l] - lse;
        }
    }
}

// ---------------- per-node gates + cell + loss (big levels) ----------------
__global__ void __launch_bounds__(128) node_update(
    int off, int cur, int chd, int isLeaf,
    const int* __restrict__ labels,
    const float* __restrict__ Wout, const float* __restrict__ bout,
    float* __restrict__ logp_out)
{
    const int j = blockIdx.x;
    const int k = threadIdx.x;
    const float* xg = g_XG + (size_t)(off + j) * 512;

    float gi = sigm(xg[k]);
    float go = sigm(xg[128 + k]);
    float gu = tanhf(xg[256 + k]);
    float c = gi * gu;
    if (!isLeaf) {
        float xf = xg[384 + k];
        size_t c0 = (size_t)(2 * j) * H + k;
        c += sigm(xf + g_FH[c0])     * g_cbuf[chd][c0]
           + sigm(xf + g_FH[c0 + H]) * g_cbuf[chd][c0 + H];
    }
    float h = go * tanhf(c);
    g_cbuf[cur][(size_t)j * H + k] = c;
    g_hbuf[cur][(size_t)j * H + k] = h;

    logits_loss(h, k, off + j, Wout, bout, labels[j], logp_out);
}

// ---------------- fully fused small level (n <= 64): GEMV + gates + loss ----------------
__global__ void __launch_bounds__(128) small_level(
    int off, int cur, int chd,
    const int* __restrict__ labels,
    const float* __restrict__ Wout, const float* __restrict__ bout,
    float* __restrict__ logp_out)
{
    const int j = blockIdx.x;
    const int k = threadIdx.x;
    __shared__ float hs[H], h0s[H], h1s[H];

    size_t cb = (size_t)(2 * j) * H + k;
    float h0 = g_hbuf[chd][cb], h1 = g_hbuf[chd][cb + H];
    h0s[k] = h0; h1s[k] = h1; hs[k] = h0 + h1;
    __syncthreads();

    const float* xg = g_XG + (size_t)(off + j) * 512;
    float ai = xg[k], ao = xg[128 + k], au = xg[256 + k], xf = xg[384 + k];
    float f0 = g_bfh[k], f1 = g_bfh[k];
    #pragma unroll 8
    for (int d = 0; d < H; d++) {
        float hd = hs[d];
        ai += hd * g_WhT[d * 384 + k];
        ao += hd * g_WhT[d * 384 + 128 + k];
        au += hd * g_WhT[d * 384 + 256 + k];
        float w = g_WfhT[d * 128 + k];
        f0 += h0s[d] * w;
        f1 += h1s[d] * w;
    }
    float gi = sigm(ai), go = sigm(ao), gu = tanhf(au);
    float c = gi * gu + sigm(xf + f0) * g_cbuf[chd][cb]
                      + sigm(xf + f1) * g_cbuf[chd][cb + H];
    float h = go * tanhf(c);
    g_cbuf[cur][(size_t)j * H + k] = c;
    g_hbuf[cur][(size_t)j * H + k] = h;

    logits_loss(h, k, off + j, Wout, bout, labels[j], logp_out);
}

// ---------------- loss reduction ----------------
__global__ void finalize_kernel(float* __restrict__ d_out, int out_size)
{
    __shared__ double s[256];
    int t = threadIdx.x;
    s[t] = g_loss[t] + g_loss[t + 256] + g_loss[t + 512] + g_loss[t + 768];
    __syncthreads();
    for (int offx = 128; offx; offx >>= 1) {
        if (t < offx) s[t] += s[t + offx];
        __syncthreads();
    }
    if (t == 0) {
        if (out_size >= NLABEL + 1) d_out[NLABEL] = (float)s[0];
        else                        d_out[0]      = (float)s[0];
    }
}

// ---------------- launch ----------------
extern "C" void kernel_launch(void* const* d_in, const int* in_sizes, int n_in,
                              void* d_out, int out_size)
{
    const float* embeds = (const float*)d_in[0];
    const int*   words  = (const int*)d_in[1];
    const int*   labels = (const int*)d_in[2];
    const float* Wix = (const float*)d_in[5];
    const float* bix = (const float*)d_in[6];
    const float* Wih = (const float*)d_in[7];
    const float* bih = (const float*)d_in[8];
    const float* Wfx = (const float*)d_in[9];
    const float* bfx = (const float*)d_in[10];
    const float* Wfh = (const float*)d_in[11];
    const float* bfh = (const float*)d_in[12];
    const float* Wox = (const float*)d_in[13];
    const float* box_ = (const float*)d_in[14];
    const float* Woh = (const float*)d_in[15];
    const float* boh = (const float*)d_in[16];
    const float* Wux = (const float*)d_in[17];
    const float* bux = (const float*)d_in[18];
    const float* Wuh = (const float*)d_in[19];
    const float* buh = (const float*)d_in[20];
    const float* Wout = (const float*)d_in[21];
    const float* bout = (const float*)d_in[22];
    float* out = (float*)d_out;

    pack_kernel<<<256, 256>>>(Wix, Wox, Wux, Wfx, bix, box_, bux, bfx,
                              Wih, Woh, Wuh, Wfh, bih, boh, buh, bfh);

    dim3 gx(4, (NNODES + 127) / 128);
    xgemm_kernel<<<gx, 256>>>(embeds, words);

    for (int l = DEPTH - 1; l >= 0; --l) {
        int n   = 1 << l;
        int off = n - 1;
        int cur = l & 1, chd = cur ^ 1;
        float* logp_dst = (l == 0 && out_size >= NLABEL + 1) ? out : nullptr;

        if (l == DEPTH - 1) {
            node_update<<<n, 128>>>(off, cur, chd, 1, labels + off, Wout, bout, nullptr);
        } else if (n >= 128) {
            int nbm = n >> 7;
            int nbf = (2 * n) >> 7;
            level_gemm<<<nbm * 3 + nbf, 256>>>(n, off, chd);
            node_update<<<n, 128>>>(off, cur, chd, 0, labels + off, Wout, bout, logp_dst);
        } else {
            small_level<<<n, 128>>>(off, cur, chd, labels + off, Wout, bout, logp_dst);
        }
    }
    finalize_kernel<<<1, 256>>>(out, out_size);
}

// round 6
// speedup vs baseline: 3.5371x; 1.1627x over previous
#include <cuda_runtime.h>
#include <cuda_bf16.h>
#include <cstdint>

#define H 128
#define NLABEL 5
#define DEPTH 18
#define NNODES ((1 << DEPTH) - 1)   /* 262143 */
#define NLEAF  (1 << (DEPTH - 1))   /* 131072 */

// ---------------- device scratch (static, no allocation) ----------------
// bf16 pair-packed weights for MMA: WP[kp][n] = {W[n][2kp], W[n][2kp+1]}
__device__ __align__(16) uint32_t g_WxP[64 * 512];
__device__ __align__(16) uint32_t g_WhP[64 * 384];
__device__ __align__(16) uint32_t g_WfP[64 * 128];
// fp32 k-major copies for the scalar small-level kernel
__device__ float g_WhT[H * 384];
__device__ float g_WfhT[H * H];
__device__ float g_b2[512];          // bix+bih, box+boh, bux+buh, bfx
__device__ float g_bfh[H];
__device__ float g_XG[(size_t)NNODES * 512];   // gate preacts for ALL nodes (fp32)
__device__ float g_FH[(size_t)NLEAF * H];      // Wfh @ child_h + bfh per child
__device__ __align__(16) __nv_bfloat16 g_hbuf[2][(size_t)NLEAF * H];
__device__ float g_cbuf[2][(size_t)NLEAF * H];
__device__ double g_loss[1024];

__device__ __forceinline__ float sigm(float x) { return 1.f / (1.f + expf(-x)); }

__device__ __forceinline__ uint32_t f2b2(float lo, float hi) {
    __nv_bfloat162 r = __floats2bfloat162_rn(lo, hi);
    return *(uint32_t*)&r;
}
__device__ __forceinline__ uint32_t badd2(uint32_t a, uint32_t b) {
    __nv_bfloat162 r = __hadd2(*(__nv_bfloat162*)&a, *(__nv_bfloat162*)&b);
    return *(uint32_t*)&r;
}

__device__ __forceinline__ void mma_bf16(float c[4],
    uint32_t a0, uint32_t a1, uint32_t a2, uint32_t a3,
    uint32_t b0, uint32_t b1)
{
    asm volatile(
        "mma.sync.aligned.m16n8k16.row.col.f32.bf16.bf16.f32 "
        "{%0,%1,%2,%3},{%4,%5,%6,%7},{%8,%9},{%0,%1,%2,%3};"
        : "+f"(c[0]), "+f"(c[1]), "+f"(c[2]), "+f"(c[3])
        : "r"(a0), "r"(a1), "r"(a2), "r"(a3), "r"(b0), "r"(b1));
}

// ---------------- weight packing + loss zeroing ----------------
__global__ void pack_kernel(
    const float* __restrict__ Wix, const float* __restrict__ Wox,
    const float* __restrict__ Wux, const float* __restrict__ Wfx,
    const float* __restrict__ bix, const float* __restrict__ box_,
    const float* __restrict__ bux, const float* __restrict__ bfx,
    const float* __restrict__ Wih, const float* __restrict__ Woh,
    const float* __restrict__ Wuh, const float* __restrict__ Wfh,
    const float* __restrict__ bih, const float* __restrict__ boh,
    const float* __restrict__ buh, const float* __restrict__ bfh)
{
    int idx = blockIdx.x * blockDim.x + threadIdx.x;
    if (idx < 64 * 512) {
        int kp = idx >> 9, c = idx & 511, g = c >> 7, r = c & 127;
        const float* W = (g == 0) ? Wix : (g == 1) ? Wox : (g == 2) ? Wux : Wfx;
        g_WxP[idx] = f2b2(W[r * H + 2 * kp], W[r * H + 2 * kp + 1]);
    }
    if (idx < 64 * 384) {
        int kp = idx / 384, c = idx % 384, g = c >> 7, r = c & 127;
        const float* W = (g == 0) ? Wih : (g == 1) ? Woh : Wuh;
        g_WhP[idx] = f2b2(W[r * H + 2 * kp], W[r * H + 2 * kp + 1]);
    }
    if (idx < 64 * 128) {
        int kp = idx >> 7, r = idx & 127;
        g_WfP[idx] = f2b2(Wfh[r * H + 2 * kp], Wfh[r * H + 2 * kp + 1]);
    }
    if (idx < H * 384) {
        int d = idx / 384, c = idx % 384, g = c >> 7, r = c & 127;
        const float* W = (g == 0) ? Wih : (g == 1) ? Woh : Wuh;
        g_WhT[idx] = W[r * H + d];
    }
    if (idx < H * H) {
        int d = idx >> 7, r = idx & 127;
        g_WfhT[idx] = Wfh[r * H + d];
    }
    if (idx < 1024) g_loss[idx] = 0.0;
    if (idx < 512) {
        int g = idx >> 7, r = idx & 127;
        float v;
        if (g == 0) v = bix[r] + bih[r];
        else if (g == 1) v = box_[r] + boh[r];
        else if (g == 2) v = bux[r] + buh[r];
        else v = bfx[r];
        g_b2[idx] = v;
    }
    if (idx < H) g_bfh[idx] = bfh[idx];
}

// ---------------- bf16 MMA GEMM block: C[128x128 tile] = op(A) @ W^T (+bias) ----------------
// K = 128, chunks of BK = 16 (one m16n8k16 per frag pair), double-buffered.
// 256 threads = 8 warps (2m x 4n), warp tile 64x32 = 4 m-frags x 4 n-frags.
// MODE 0: A row m = hbuf bf16 row m
// MODE 1: A row m = embeds fp32 row ridx[m]   (gather + convert)
// MODE 2: A row m = hbuf[2m] + hbuf[2m+1]     (bf16 pair sum)
#define AS_LD 12
#define BS_LD 136
#define AS_BUF (128 * AS_LD)
#define BS_BUF (8 * BS_LD)

template <int MODE, bool ACC, bool BIAS>
__device__ __forceinline__ void gemm_block_bf16(
    uint32_t* AsU, uint32_t* BsU,
    const void* Av, const int* __restrict__ ridx,
    const uint32_t* __restrict__ WP, int ldbp, const float* __restrict__ bias,
    float* __restrict__ C, int ldc, int M, int brow, int bcol)
{
    const int t    = threadIdx.x;
    const int lane = t & 31;
    const int warp = t >> 5;
    const int mw   = warp & 1;
    const int nw   = warp >> 1;
    const int g    = lane >> 2;
    const int t4   = lane & 3;

    const int lrow = t >> 1;        // A-loader row 0..127
    const int lk   = (t & 1) * 4;   // A-loader u32 half (0 or 4)
    const int kr   = t >> 5;        // B-loader kp row 0..7
    const int bn   = (t & 31) * 4;  // B-loader col

    const int arow = brow + lrow;
    const bool av  = arow < M;
    const float*    apf = nullptr;
    const uint32_t* ap0 = nullptr;
    const uint32_t* ap1 = nullptr;
    if (av) {
        if (MODE == 1)      apf = (const float*)Av + (size_t)ridx[arow] * H;
        else if (MODE == 0) ap0 = (const uint32_t*)((const __nv_bfloat16*)Av + (size_t)arow * H);
        else {
            ap0 = (const uint32_t*)((const __nv_bfloat16*)Av + (size_t)(2 * arow) * H);
            ap1 = ap0 + (H / 2);
        }
    }
    const uint32_t* wp = WP + (size_t)kr * ldbp + bcol + bn;

    float acc[4][4][4];
    #pragma unroll
    for (int i = 0; i < 4; i++)
        #pragma unroll
        for (int j = 0; j < 4; j++)
            #pragma unroll
            for (int q = 0; q < 4; q++) acc[i][j][q] = 0.f;

    uint32_t pa[4];
    uint4 pb;

    auto fetch = [&](int kb) {   // kb = chunk index 0..7 (16 k each, 8 u32 pairs)
        pa[0] = pa[1] = pa[2] = pa[3] = 0u;
        if (MODE == 1) {
            if (av) {
                float4 x0 = *(const float4*)(apf + kb * 16 + lk * 2);
                float4 x1 = *(const float4*)(apf + kb * 16 + lk * 2 + 4);
                pa[0] = f2b2(x0.x, x0.y); pa[1] = f2b2(x0.z, x0.w);
                pa[2] = f2b2(x1.x, x1.y); pa[3] = f2b2(x1.z, x1.w);
            }
        } else if (MODE == 0) {
            if (av) {
                uint4 u = *(const uint4*)(ap0 + kb * 8 + lk);
                pa[0] = u.x; pa[1] = u.y; pa[2] = u.z; pa[3] = u.w;
            }
        } else {
            if (av) {
                uint4 u = *(const uint4*)(ap0 + kb * 8 + lk);
                uint4 v = *(const uint4*)(ap1 + kb * 8 + lk);
                pa[0] = badd2(u.x, v.x); pa[1] = badd2(u.y, v.y);
                pa[2] = badd2(u.z, v.z); pa[3] = badd2(u.w, v.w);
            }
        }
        pb = *(const uint4*)(wp + (size_t)(kb * 8) * ldbp);
    };
    auto stage = [&](int buf) {
        uint32_t* as = AsU + buf * AS_BUF;
        uint32_t* bs = BsU + buf * BS_BUF;
        *(uint4*)&as[lrow * AS_LD + lk] = make_uint4(pa[0], pa[1], pa[2], pa[3]);
        *(uint4*)&bs[kr * BS_LD + bn]   = pb;
    };

    fetch(0);
    stage(0);
    __syncthreads();

    #pragma unroll
    for (int kb = 0; kb < 8; kb++) {
        const int cur = kb & 1;
        if (kb < 7) fetch(kb + 1);
        const uint32_t* as = AsU + cur * AS_BUF;
        const uint32_t* bs = BsU + cur * BS_BUF;
        uint32_t bf[4][2];
        #pragma unroll
        for (int nf = 0; nf < 4; nf++) {
            int ncol = nw * 32 + nf * 8 + g;
            bf[nf][0] = bs[t4 * BS_LD + ncol];
            bf[nf][1] = bs[(t4 + 4) * BS_LD + ncol];
        }
        #pragma unroll
        for (int mf = 0; mf < 4; mf++) {
            int rb = (mw * 64 + mf * 16 + g) * AS_LD + t4;
            uint32_t a0 = as[rb];
            uint32_t a1 = as[rb + 8 * AS_LD];
            uint32_t a2 = as[rb + 4];
            uint32_t a3 = as[rb + 8 * AS_LD + 4];
            #pragma unroll
            for (int nf = 0; nf < 4; nf++)
                mma_bf16(acc[mf][nf], a0, a1, a2, a3, bf[nf][0], bf[nf][1]);
        }
        if (kb < 7) {
            stage(1 - cur);
            __syncthreads();
        }
    }

    // epilogue (fp32)
    #pragma unroll
    for (int mf = 0; mf < 4; mf++) {
        #pragma unroll
        for (int nf = 0; nf < 4; nf++) {
            int row = brow + mw * 64 + mf * 16 + g;
            int col = bcol + nw * 32 + nf * 8 + 2 * t4;
            float b0 = 0.f, b1 = 0.f;
            if (BIAS) { b0 = bias[col]; b1 = bias[col + 1]; }
            if (row < M) {
                float* p = C + (size_t)row * ldc + col;
                float v0 = acc[mf][nf][0] + b0;
                float v1 = acc[mf][nf][1] + b1;
                if (ACC) { v0 += p[0]; v1 += p[1]; }
                p[0] = v0; p[1] = v1;
            }
            if (row + 8 < M) {
                float* p = C + (size_t)(row + 8) * ldc + col;
                float v0 = acc[mf][nf][2] + b0;
                float v1 = acc[mf][nf][3] + b1;
                if (ACC) { v0 += p[0]; v1 += p[1]; }
                p[0] = v0; p[1] = v1;
            }
        }
    }
}

#define GEMM_SMEM \
    __shared__ __align__(16) uint32_t AsU[2 * AS_BUF]; \
    __shared__ __align__(16) uint32_t BsU[2 * BS_BUF];

// ---------------- one-shot x-GEMM over ALL nodes ----------------
__global__ void __launch_bounds__(256, 2) xgemm_kernel(
    const float* __restrict__ embeds, const int* __restrict__ words)
{
    GEMM_SMEM
    gemm_block_bf16<1, false, true>(AsU, BsU, embeds, words, g_WxP, 512, g_b2,
                                    g_XG, 512, NNODES,
                                    (int)blockIdx.y * 128, (int)blockIdx.x * 128);
}

// ---------------- per-level h-GEMM (pairsum, acc) + f-GEMM fused launch ----------------
__global__ void __launch_bounds__(256, 2) level_gemm(int n, int off, int chd)
{
    GEMM_SMEM
    const __nv_bfloat16* h_ch = g_hbuf[chd];
    const int nbm = n >> 7;
    const int bx  = blockIdx.x;
    if (bx < nbm * 3) {
        gemm_block_bf16<2, true, false>(AsU, BsU, h_ch, nullptr, g_WhP, 384, nullptr,
                                        g_XG + (size_t)off * 512, 512, n,
                                        (bx / 3) * 128, (bx % 3) * 128);
    } else {
        int fb = bx - nbm * 3;
        gemm_block_bf16<0, false, true>(AsU, BsU, h_ch, nullptr, g_WfP, 128, g_bfh,
                                        g_FH, 128, 2 * n, fb * 128, 0);
    }
}

// ---------------- logits + log-softmax loss (per node, 128 threads) ----------------
__device__ __forceinline__ void logits_loss(
    float h, int k, int slot,
    const float* __restrict__ Wout, const float* __restrict__ bout,
    int label, float* __restrict__ logp_out)
{
    float p[NLABEL];
    #pragma unroll
    for (int l = 0; l < NLABEL; l++) p[l] = h * Wout[l * H + k];
    #pragma unroll
    for (int offx = 16; offx; offx >>= 1) {
        #pragma unroll
        for (int l = 0; l < NLABEL; l++)
            p[l] += __shfl_down_sync(0xffffffffu, p[l], offx);
    }
    __shared__ float sw[4][NLABEL];
    int wid = k >> 5, lane = k & 31;
    if (lane == 0) {
        #pragma unroll
        for (int l = 0; l < NLABEL; l++) sw[wid][l] = p[l];
    }
    __syncthreads();
    if (k == 0) {
        float lg[NLABEL], m = -1e30f;
        #pragma unroll
        for (int l = 0; l < NLABEL; l++) {
            lg[l] = sw[0][l] + sw[1][l] + sw[2][l] + sw[3][l] + bout[l];
            m = fmaxf(m, lg[l]);
        }
        float s = 0.f;
        #pragma unroll
        for (int l = 0; l < NLABEL; l++) s += expf(lg[l] - m);
        float lse = m + logf(s);
        atomicAdd(&g_loss[slot & 1023], (double)(lse - lg[label]));
        if (logp_out) {
            #pragma unroll
            for (int l = 0; l < NLABEL; l++) logp_out[l] = lg[l] - lse;
        }
    }
}

// ---------------- per-node gates + cell + loss (big levels) ----------------
__global__ void __launch_bounds__(128) node_update(
    int off, int cur, int chd, int isLeaf,
    const int* __restrict__ labels,
    const float* __restrict__ Wout, const float* __restrict__ bout,
    float* __restrict__ logp_out)
{
    const int j = blockIdx.x;
    const int k = threadIdx.x;
    const float* xg = g_XG + (size_t)(off + j) * 512;

    float gi = sigm(xg[k]);
    float go = sigm(xg[128 + k]);
    float gu = tanhf(xg[256 + k]);
    float c = gi * gu;
    if (!isLeaf) {
        float xf = xg[384 + k];
        size_t c0 = (size_t)(2 * j) * H + k;
        c += sigm(xf + g_FH[c0])     * g_cbuf[chd][c0]
           + sigm(xf + g_FH[c0 + H]) * g_cbuf[chd][c0 + H];
    }
    float h = go * tanhf(c);
    g_cbuf[cur][(size_t)j * H + k] = c;
    g_hbuf[cur][(size_t)j * H + k] = __float2bfloat16(h);

    logits_loss(h, k, off + j, Wout, bout, labels[j], logp_out);
}

// ---------------- fully fused small level (n <= 64): GEMV + gates + loss ----------------
__global__ void __launch_bounds__(128) small_level(
    int off, int cur, int chd,
    const int* __restrict__ labels,
    const float* __restrict__ Wout, const float* __restrict__ bout,
    float* __restrict__ logp_out)
{
    const int j = blockIdx.x;
    const int k = threadIdx.x;
    __shared__ float hs[H], h0s[H], h1s[H];

    size_t cb = (size_t)(2 * j) * H + k;
    float h0 = __bfloat162float(g_hbuf[chd][cb]);
    float h1 = __bfloat162float(g_hbuf[chd][cb + H]);
    h0s[k] = h0; h1s[k] = h1; hs[k] = h0 + h1;
    __syncthreads();

    const float* xg = g_XG + (size_t)(off + j) * 512;
    float ai = xg[k], ao = xg[128 + k], au = xg[256 + k], xf = xg[384 + k];
    float f0 = g_bfh[k], f1 = g_bfh[k];
    #pragma unroll 8
    for (int d = 0; d < H; d++) {
        float hd = hs[d];
        ai += hd * g_WhT[d * 384 + k];
        ao += hd * g_WhT[d * 384 + 128 + k];
        au += hd * g_WhT[d * 384 + 256 + k];
        float w = g_WfhT[d * 128 + k];
        f0 += h0s[d] * w;
        f1 += h1s[d] * w;
    }
    float gi = sigm(ai), go = sigm(ao), gu = tanhf(au);
    float c = gi * gu + sigm(xf + f0) * g_cbuf[chd][cb]
                      + sigm(xf + f1) * g_cbuf[chd][cb + H];
    float h = go * tanhf(c);
    g_cbuf[cur][(size_t)j * H + k] = c;
    g_hbuf[cur][(size_t)j * H + k] = __float2bfloat16(h);

    logits_loss(h, k, off + j, Wout, bout, labels[j], logp_out);
}

// ---------------- loss reduction ----------------
__global__ void finalize_kernel(float* __restrict__ d_out, int out_size)
{
    __shared__ double s[256];
    int t = threadIdx.x;
    s[t] = g_loss[t] + g_loss[t + 256] + g_loss[t + 512] + g_loss[t + 768];
    __syncthreads();
    for (int offx = 128; offx; offx >>= 1) {
        if (t < offx) s[t] += s[t + offx];
        __syncthreads();
    }
    if (t == 0) {
        if (out_size >= NLABEL + 1) d_out[NLABEL] = (float)s[0];
        else                        d_out[0]      = (float)s[0];
    }
}

// ---------------- launch ----------------
extern "C" void kernel_launch(void* const* d_in, const int* in_sizes, int n_in,
                              void* d_out, int out_size)
{
    const float* embeds = (const float*)d_in[0];
    const int*   words  = (const int*)d_in[1];
    const int*   labels = (const int*)d_in[2];
    const float* Wix = (const float*)d_in[5];
    const float* bix = (const float*)d_in[6];
    const float* Wih = (const float*)d_in[7];
    const float* bih = (const float*)d_in[8];
    const float* Wfx = (const float*)d_in[9];
    const float* bfx = (const float*)d_in[10];
    const float* Wfh = (const float*)d_in[11];
    const float* bfh = (const float*)d_in[12];
    const float* Wox = (const float*)d_in[13];
    const float* box_ = (const float*)d_in[14];
    const float* Woh = (const float*)d_in[15];
    const float* boh = (const float*)d_in[16];
    const float* Wux = (const float*)d_in[17];
    const float* bux = (const float*)d_in[18];
    const float* Wuh = (const float*)d_in[19];
    const float* buh = (const float*)d_in[20];
    const float* Wout = (const float*)d_in[21];
    const float* bout = (const float*)d_in[22];
    float* out = (float*)d_out;

    pack_kernel<<<256, 256>>>(Wix, Wox, Wux, Wfx, bix, box_, bux, bfx,
                              Wih, Woh, Wuh, Wfh, bih, boh, buh, bfh);

    dim3 gx(4, (NNODES + 127) / 128);
    xgemm_kernel<<<gx, 256>>>(embeds, words);

    for (int l = DEPTH - 1; l >= 0; --l) {
        int n   = 1 << l;
        int off = n - 1;
        int cur = l & 1, chd = cur ^ 1;
        float* logp_dst = (l == 0 && out_size >= NLABEL + 1) ? out : nullptr;

        if (l == DEPTH - 1) {
            node_update<<<n, 128>>>(off, cur, chd, 1, labels + off, Wout, bout, nullptr);
        } else if (n >= 128) {
            int nbm = n >> 7;
            int nbf = (2 * n) >> 7;
            level_gemm<<<nbm * 3 + nbf, 256>>>(n, off, chd);
            node_update<<<n, 128>>>(off, cur, chd, 0, labels + off, Wout, bout, logp_dst);
        } else {
            small_level<<<n, 128>>>(off, cur, chd, labels + off, Wout, bout, logp_dst);
        }
    }
    finalize_kernel<<<1, 256>>>(out, out_size);
}

// round 9
// speedup vs baseline: 3.6058x; 1.0194x over previous
#include <cuda_runtime.h>
#include <cuda_bf16.h>
#include <cstdint>

#define H 128
#define NLABEL 5
#define DEPTH 18
#define NNODES ((1 << DEPTH) - 1)   /* 262143 */
#define NLEAF  (1 << (DEPTH - 1))   /* 131072 */
#define NITILE 1024                 /* m-tiles fully covering internal nodes */
#define NMTILE 2048                 /* ceil(NNODES/128) */

// ---------------- device scratch (static, no allocation) ----------------
// bf16 pair-packed weights for MMA: WP[kp][n] = {W[n][2kp], W[n][2kp+1]}
__device__ __align__(16) uint32_t g_WxP[64 * 512];
__device__ __align__(16) uint32_t g_WhP[64 * 384];
__device__ __align__(16) uint32_t g_WfP[64 * 128];
// fp32 k-major copies for the scalar small-level kernel
__device__ float g_WhT[H * 384];
__device__ float g_WfhT[H * H];
__device__ float g_b2[512];          // bix+bih, box+boh, bux+buh, bfx
__device__ float g_bfh[H];
__device__ float g_XG[(size_t)NNODES * 512];   // gate preacts for ALL nodes (fp32)
__device__ float g_FH[(size_t)NLEAF * H];      // Wfh @ child_h + bfh per child
__device__ __align__(16) __nv_bfloat16 g_hbuf[2][(size_t)NLEAF * H];
__device__ float g_cbuf[2][(size_t)NLEAF * H];
__device__ double g_loss[1024];

__device__ __forceinline__ float sigm(float x) { return 1.f / (1.f + expf(-x)); }

__device__ __forceinline__ uint32_t f2b2(float lo, float hi) {
    __nv_bfloat162 r = __floats2bfloat162_rn(lo, hi);
    return *(uint32_t*)&r;
}
__device__ __forceinline__ uint32_t badd2(uint32_t a, uint32_t b) {
    __nv_bfloat162 r = __hadd2(*(__nv_bfloat162*)&a, *(__nv_bfloat162*)&b);
    return *(uint32_t*)&r;
}

__device__ __forceinline__ void mma_bf16(float c[4],
    uint32_t a0, uint32_t a1, uint32_t a2, uint32_t a3,
    uint32_t b0, uint32_t b1)
{
    asm volatile(
        "mma.sync.aligned.m16n8k16.row.col.f32.bf16.bf16.f32 "
        "{%0,%1,%2,%3},{%4,%5,%6,%7},{%8,%9},{%0,%1,%2,%3};"
        : "+f"(c[0]), "+f"(c[1]), "+f"(c[2]), "+f"(c[3])
        : "r"(a0), "r"(a1), "r"(a2), "r"(a3), "r"(b0), "r"(b1));
}

// ---------------- weight packing + loss zeroing ----------------
__global__ void pack_kernel(
    const float* __restrict__ Wix, const float* __restrict__ Wox,
    const float* __restrict__ Wux, const float* __restrict__ Wfx,
    const float* __restrict__ bix, const float* __restrict__ box_,
    const float* __restrict__ bux, const float* __restrict__ bfx,
    const float* __restrict__ Wih, const float* __restrict__ Woh,
    const float* __restrict__ Wuh, const float* __restrict__ Wfh,
    const float* __restrict__ bih, const float* __restrict__ boh,
    const float* __restrict__ buh, const float* __restrict__ bfh)
{
    int idx = blockIdx.x * blockDim.x + threadIdx.x;
    if (idx < 64 * 512) {
        int kp = idx >> 9, c = idx & 511, g = c >> 7, r = c & 127;
        const float* W = (g == 0) ? Wix : (g == 1) ? Wox : (g == 2) ? Wux : Wfx;
        g_WxP[idx] = f2b2(W[r * H + 2 * kp], W[r * H + 2 * kp + 1]);
    }
    if (idx < 64 * 384) {
        int kp = idx / 384, c = idx % 384, g = c >> 7, r = c & 127;
        const float* W = (g == 0) ? Wih : (g == 1) ? Woh : Wuh;
        g_WhP[idx] = f2b2(W[r * H + 2 * kp], W[r * H + 2 * kp + 1]);
    }
    if (idx < 64 * 128) {
        int kp = idx >> 7, r = idx & 127;
        g_WfP[idx] = f2b2(Wfh[r * H + 2 * kp], Wfh[r * H + 2 * kp + 1]);
    }
    if (idx < H * 384) {
        int d = idx / 384, c = idx % 384, g = c >> 7, r = c & 127;
        const float* W = (g == 0) ? Wih : (g == 1) ? Woh : Wuh;
        g_WhT[idx] = W[r * H + d];
    }
    if (idx < H * H) {
        int d = idx >> 7, r = idx & 127;
        g_WfhT[idx] = Wfh[r * H + d];
    }
    if (idx < 1024) g_loss[idx] = 0.0;
    if (idx < 512) {
        int g = idx >> 7, r = idx & 127;
        float v;
        if (g == 0) v = bix[r] + bih[r];
        else if (g == 1) v = box_[r] + boh[r];
        else if (g == 2) v = bux[r] + buh[r];
        else v = bfx[r];
        g_b2[idx] = v;
    }
    if (idx < H) g_bfh[idx] = bfh[idx];
}

// ---------------- bf16 MMA GEMM block: C[128x128 tile] = op(A) @ W^T (+bias) ----------------
// K = 128, chunks of BK = 16 (one m16n8k16 per frag pair), double-buffered.
// 256 threads = 8 warps (2m x 4n), warp tile 64x32 = 4 m-frags x 4 n-frags.
// MODE 0: A row m = hbuf bf16 row m
// MODE 1: A row m = embeds fp32 row ridx[m]   (gather + convert)
// MODE 2: A row m = hbuf[2m] + hbuf[2m+1]     (bf16 pair sum)
#define AS_LD 12
#define BS_LD 136
#define AS_BUF (128 * AS_LD)
#define BS_BUF (8 * BS_LD)

template <int MODE, bool ACC, bool BIAS>
__device__ __forceinline__ void gemm_block_bf16(
    uint32_t* AsU, uint32_t* BsU,
    const void* Av, const int* __restrict__ ridx,
    const uint32_t* __restrict__ WP, int ldbp, const float* __restrict__ bias,
    float* __restrict__ C, int ldc, int M, int brow, int bcol)
{
    const int t    = threadIdx.x;
    const int lane = t & 31;
    const int warp = t >> 5;
    const int mw   = warp & 1;
    const int nw   = warp >> 1;
    const int g    = lane >> 2;
    const int t4   = lane & 3;

    const int lrow = t >> 1;        // A-loader row 0..127
    const int lk   = (t & 1) * 4;   // A-loader u32 half (0 or 4)
    const int kr   = t >> 5;        // B-loader kp row 0..7
    const int bn   = (t & 31) * 4;  // B-loader col

    const int arow = brow + lrow;
    const bool av  = arow < M;
    const float*    apf = nullptr;
    const uint32_t* ap0 = nullptr;
    const uint32_t* ap1 = nullptr;
    if (av) {
        if (MODE == 1)      apf = (const float*)Av + (size_t)ridx[arow] * H;
        else if (MODE == 0) ap0 = (const uint32_t*)((const __nv_bfloat16*)Av + (size_t)arow * H);
        else {
            ap0 = (const uint32_t*)((const __nv_bfloat16*)Av + (size_t)(2 * arow) * H);
            ap1 = ap0 + (H / 2);
        }
    }
    const uint32_t* wp = WP + (size_t)kr * ldbp + bcol + bn;

    float acc[4][4][4];
    #pragma unroll
    for (int i = 0; i < 4; i++)
        #pragma unroll
        for (int j = 0; j < 4; j++)
            #pragma unroll
            for (int q = 0; q < 4; q++) acc[i][j][q] = 0.f;

    uint32_t pa[4];
    uint4 pb;

    auto fetch = [&](int kb) {   // kb = chunk index 0..7 (16 k each, 8 u32 pairs)
        pa[0] = pa[1] = pa[2] = pa[3] = 0u;
        if (MODE == 1) {
            if (av) {
                float4 x0 = *(const float4*)(apf + kb * 16 + lk * 2);
                float4 x1 = *(const float4*)(apf + kb * 16 + lk * 2 + 4);
                pa[0] = f2b2(x0.x, x0.y); pa[1] = f2b2(x0.z, x0.w);
                pa[2] = f2b2(x1.x, x1.y); pa[3] = f2b2(x1.z, x1.w);
            }
        } else if (MODE == 0) {
            if (av) {
                uint4 u = *(const uint4*)(ap0 + kb * 8 + lk);
                pa[0] = u.x; pa[1] = u.y; pa[2] = u.z; pa[3] = u.w;
            }
        } else {
            if (av) {
                uint4 u = *(const uint4*)(ap0 + kb * 8 + lk);
                uint4 v = *(const uint4*)(ap1 + kb * 8 + lk);
                pa[0] = badd2(u.x, v.x); pa[1] = badd2(u.y, v.y);
                pa[2] = badd2(u.z, v.z); pa[3] = badd2(u.w, v.w);
            }
        }
        pb = *(const uint4*)(wp + (size_t)(kb * 8) * ldbp);
    };
    auto stage = [&](int buf) {
        uint32_t* as = AsU + buf * AS_BUF;
        uint32_t* bs = BsU + buf * BS_BUF;
        *(uint4*)&as[lrow * AS_LD + lk] = make_uint4(pa[0], pa[1], pa[2], pa[3]);
        *(uint4*)&bs[kr * BS_LD + bn]   = pb;
    };

    fetch(0);
    stage(0);
    __syncthreads();

    #pragma unroll
    for (int kb = 0; kb < 8; kb++) {
        const int cur = kb & 1;
        if (kb < 7) fetch(kb + 1);
        const uint32_t* as = AsU + cur * AS_BUF;
        const uint32_t* bs = BsU + cur * BS_BUF;
        uint32_t bf[4][2];
        #pragma unroll
        for (int nf = 0; nf < 4; nf++) {
            int ncol = nw * 32 + nf * 8 + g;
            bf[nf][0] = bs[t4 * BS_LD + ncol];
            bf[nf][1] = bs[(t4 + 4) * BS_LD + ncol];
        }
        #pragma unroll
        for (int mf = 0; mf < 4; mf++) {
            int rb = (mw * 64 + mf * 16 + g) * AS_LD + t4;
            uint32_t a0 = as[rb];
            uint32_t a1 = as[rb + 8 * AS_LD];
            uint32_t a2 = as[rb + 4];
            uint32_t a3 = as[rb + 8 * AS_LD + 4];
            #pragma unroll
            for (int nf = 0; nf < 4; nf++)
                mma_bf16(acc[mf][nf], a0, a1, a2, a3, bf[nf][0], bf[nf][1]);
        }
        if (kb < 7) {
            stage(1 - cur);
            __syncthreads();
        }
    }

    // epilogue (fp32)
    #pragma unroll
    for (int mf = 0; mf < 4; mf++) {
        #pragma unroll
        for (int nf = 0; nf < 4; nf++) {
            int row = brow + mw * 64 + mf * 16 + g;
            int col = bcol + nw * 32 + nf * 8 + 2 * t4;
            float b0 = 0.f, b1 = 0.f;
            if (BIAS) { b0 = bias[col]; b1 = bias[col + 1]; }
            if (row < M) {
                float* p = C + (size_t)row * ldc + col;
                float v0 = acc[mf][nf][0] + b0;
                float v1 = acc[mf][nf][1] + b1;
                if (ACC) { v0 += p[0]; v1 += p[1]; }
                p[0] = v0; p[1] = v1;
            }
            if (row + 8 < M) {
                float* p = C + (size_t)(row + 8) * ldc + col;
                float v0 = acc[mf][nf][2] + b0;
                float v1 = acc[mf][nf][3] + b1;
                if (ACC) { v0 += p[0]; v1 += p[1]; }
                p[0] = v0; p[1] = v1;
            }
        }
    }
}

#define GEMM_SMEM \
    __shared__ __align__(16) uint32_t AsU[2 * AS_BUF]; \
    __shared__ __align__(16) uint32_t BsU[2 * BS_BUF];

// ---------------- one-shot x-GEMM over ALL nodes (leaf m-tiles skip the f-gate n-tile) ----------------
__global__ void __launch_bounds__(256, 2) xgemm_kernel(
    const float* __restrict__ embeds, const int* __restrict__ words)
{
    GEMM_SMEM
    int bx = blockIdx.x, m, nt;
    if (bx < NITILE * 4) { m = bx >> 2; nt = bx & 3; }
    else { int r2 = bx - NITILE * 4; m = NITILE + r2 / 3; nt = r2 % 3; }
    gemm_block_bf16<1, false, true>(AsU, BsU, embeds, words, g_WxP, 512, g_b2,
                                    g_XG, 512, NNODES, m * 128, nt * 128);
}

// ---------------- per-level h-GEMM (pairsum, acc) + f-GEMM fused launch ----------------
__global__ void __launch_bounds__(256, 2) level_gemm(int n, int off, int chd)
{
    GEMM_SMEM
    const __nv_bfloat16* h_ch = g_hbuf[chd];
    const int nbm = n >> 7;
    const int bx  = blockIdx.x;
    if (bx < nbm * 3) {
        gemm_block_bf16<2, true, false>(AsU, BsU, h_ch, nullptr, g_WhP, 384, nullptr,
                                        g_XG + (size_t)off * 512, 512, n,
                                        (bx / 3) * 128, (bx % 3) * 128);
    } else {
        int fb = bx - nbm * 3;
        gemm_block_bf16<0, false, true>(AsU, BsU, h_ch, nullptr, g_WfP, 128, g_bfh,
                                        g_FH, 128, 2 * n, fb * 128, 0);
    }
}

// ---------------- logits + log-softmax loss (per node, 128 threads) ----------------
__device__ __forceinline__ void logits_loss(
    float h, int k, int slot,
    const float* __restrict__ Wout, const float* __restrict__ bout,
    int label, float* __restrict__ logp_out)
{
    float p[NLABEL];
    #pragma unroll
    for (int l = 0; l < NLABEL; l++) p[l] = h * Wout[l * H + k];
    #pragma unroll
    for (int offx = 16; offx; offx >>= 1) {
        #pragma unroll
        for (int l = 0; l < NLABEL; l++)
            p[l] += __shfl_down_sync(0xffffffffu, p[l], offx);
    }
    __shared__ float sw[4][NLABEL];
    int wid = k >> 5, lane = k & 31;
    if (lane == 0) {
        #pragma unroll
        for (int l = 0; l < NLABEL; l++) sw[wid][l] = p[l];
    }
    __syncthreads();
    if (k == 0) {
        float lg[NLABEL], m = -1e30f;
        #pragma unroll
        for (int l = 0; l < NLABEL; l++) {
            lg[l] = sw[0][l] + sw[1][l] + sw[2][l] + sw[3][l] + bout[l];
            m = fmaxf(m, lg[l]);
        }
        float s = 0.f;
        #pragma unroll
        for (int l = 0; l < NLABEL; l++) s += expf(lg[l] - m);
        float lse = m + logf(s);
        atomicAdd(&g_loss[slot & 1023], (double)(lse - lg[label]));
        if (logp_out) {
            #pragma unroll
            for (int l = 0; l < NLABEL; l++) logp_out[l] = lg[l] - lse;
        }
    }
}

// ---------------- per-node gates + cell + loss (big levels) ----------------
__global__ void __launch_bounds__(128) node_update(
    int off, int cur, int chd, int isLeaf,
    const int* __restrict__ labels,
    const float* __restrict__ Wout, const float* __restrict__ bout,
    float* __restrict__ logp_out)
{
    const int j = blockIdx.x;
    const int k = threadIdx.x;
    const float* xg = g_XG + (size_t)(off + j) * 512;

    float gi = sigm(xg[k]);
    float go = sigm(xg[128 + k]);
    float gu = tanhf(xg[256 + k]);
    float c = gi * gu;
    if (!isLeaf) {
        float xf = xg[384 + k];
        size_t c0 = (size_t)(2 * j) * H + k;
        c += sigm(xf + g_FH[c0])     * g_cbuf[chd][c0]
           + sigm(xf + g_FH[c0 + H]) * g_cbuf[chd][c0 + H];
    }
    float h = go * tanhf(c);
    g_cbuf[cur][(size_t)j * H + k] = c;
    g_hbuf[cur][(size_t)j * H + k] = __float2bfloat16(h);

    logits_loss(h, k, off + j, Wout, bout, labels[j], logp_out);
}

// ---------------- fully fused small level (n <= 64): GEMV + gates + loss ----------------
__global__ void __launch_bounds__(128) small_level(
    int off, int cur, int chd,
    const int* __restrict__ labels,
    const float* __restrict__ Wout, const float* __restrict__ bout,
    float* __restrict__ logp_out)
{
    const int j = blockIdx.x;
    const int k = threadIdx.x;
    __shared__ float hs[H], h0s[H], h1s[H];

    size_t cb = (size_t)(2 * j) * H + k;
    float h0 = __bfloat162float(g_hbuf[chd][cb]);
    float h1 = __bfloat162float(g_hbuf[chd][cb + H]);
    h0s[k] = h0; h1s[k] = h1; hs[k] = h0 + h1;
    __syncthreads();

    const float* xg = g_XG + (size_t)(off + j) * 512;
    float ai = xg[k], ao = xg[128 + k], au = xg[256 + k], xf = xg[384 + k];
    float f0 = g_bfh[k], f1 = g_bfh[k];
    #pragma unroll 8
    for (int d = 0; d < H; d++) {
        float hd = hs[d];
        ai += hd * g_WhT[d * 384 + k];
        ao += hd * g_WhT[d * 384 + 128 + k];
        au += hd * g_WhT[d * 384 + 256 + k];
        float w = g_WfhT[d * 128 + k];
        f0 += h0s[d] * w;
        f1 += h1s[d] * w;
    }
    float gi = sigm(ai), go = sigm(ao), gu = tanhf(au);
    float c = gi * gu + sigm(xf + f0) * g_cbuf[chd][cb]
                      + sigm(xf + f1) * g_cbuf[chd][cb + H];
    float h = go * tanhf(c);
    g_cbuf[cur][(size_t)j * H + k] = c;
    g_hbuf[cur][(size_t)j * H + k] = __float2bfloat16(h);

    logits_loss(h, k, off + j, Wout, bout, labels[j], logp_out);
}

// ---------------- loss reduction ----------------
__global__ void finalize_kernel(float* __restrict__ d_out, int out_size)
{
    __shared__ double s[256];
    int t = threadIdx.x;
    s[t] = g_loss[t] + g_loss[t + 256] + g_loss[t + 512] + g_loss[t + 768];
    __syncthreads();
    for (int offx = 128; offx; offx >>= 1) {
        if (t < offx) s[t] += s[t + offx];
        __syncthreads();
    }
    if (t == 0) {
        if (out_size >= NLABEL + 1) d_out[NLABEL] = (float)s[0];
        else                        d_out[0]      = (float)s[0];
    }
}

// ---------------- launch ----------------
extern "C" void kernel_launch(void* const* d_in, const int* in_sizes, int n_in,
                              void* d_out, int out_size)
{
    const float* embeds = (const float*)d_in[0];
    const int*   words  = (const int*)d_in[1];
    const int*   labels = (const int*)d_in[2];
    const float* Wix = (const float*)d_in[5];
    const float* bix = (const float*)d_in[6];
    const float* Wih = (const float*)d_in[7];
    const float* bih = (const float*)d_in[8];
    const float* Wfx = (const float*)d_in[9];
    const float* bfx = (const float*)d_in[10];
    const float* Wfh = (const float*)d_in[11];
    const float* bfh = (const float*)d_in[12];
    const float* Wox = (const float*)d_in[13];
    const float* box_ = (const float*)d_in[14];
    const float* Woh = (const float*)d_in[15];
    const float* boh = (const float*)d_in[16];
    const float* Wux = (const float*)d_in[17];
    const float* bux = (const float*)d_in[18];
    const float* Wuh = (const float*)d_in[19];
    const float* buh = (const float*)d_in[20];
    const float* Wout = (const float*)d_in[21];
    const float* bout = (const float*)d_in[22];
    float* out = (float*)d_out;

    pack_kernel<<<256, 256>>>(Wix, Wox, Wux, Wfx, bix, box_, bux, bfx,
                              Wih, Woh, Wuh, Wfh, bih, boh, buh, bfh);

    xgemm_kernel<<<NITILE * 4 + (NMTILE - NITILE) * 3, 256>>>(embeds, words);

    for (int l = DEPTH - 1; l >= 0; --l) {
        int n   = 1 << l;
        int off = n - 1;
        int cur = l & 1, chd = cur ^ 1;
        float* logp_dst = (l == 0 && out_size >= NLABEL + 1) ? out : nullptr;

        if (l == DEPTH - 1) {
            node_update<<<n, 128>>>(off, cur, chd, 1, labels + off, Wout, bout, nullptr);
        } else if (n >= 128) {
            int nbm = n >> 7;
            int nbf = (2 * n) >> 7;
            level_gemm<<<nbm * 3 + nbf, 256>>>(n, off, chd);
            node_update<<<n, 128>>>(off, cur, chd, 0, labels + off, Wout, bout, logp_dst);
        } else {
            small_level<<<n, 128>>>(off, cur, chd, labels + off, Wout, bout, logp_dst);
        }
    }
    finalize_kernel<<<1, 256>>>(out, out_size);
}

// round 10
// speedup vs baseline: 3.8847x; 1.0773x over previous
#include <cuda_runtime.h>
#include <cuda_bf16.h>
#include <cstdint>

#define H 128
#define NLABEL 5
#define DEPTH 18
#define NNODES ((1 << DEPTH) - 1)   /* 262143 */
#define NLEAF  (1 << (DEPTH - 1))   /* 131072 */
#define NITILE 1024                 /* m-tiles fully covering internal nodes */
#define NMTILE 2048                 /* ceil(NNODES/128) */

#define ALD 68                      /* u32 per A smem row (64 + 4 pad) */
#define BLD 136                     /* u32 per B smem kp-row (128 + 8 pad) */
#define A_U32 (128 * ALD)           /* 8704 */
#define B_U32 (64 * BLD)            /* 8704 */
#define SMEM_DYN ((A_U32 + B_U32) * 4)   /* 69632 B */

// ---------------- device scratch (static, no allocation) ----------------
// Pre-padded bf16-pair weight blobs, layout identical to the SMEM B image:
// blob[kp * BLD + n] = {W[n][2kp], W[n][2kp+1]}
__device__ __align__(16) uint32_t g_WxS[4 * B_U32];   // gates i,o,u,f
__device__ __align__(16) uint32_t g_WhS[3 * B_U32];   // gates i,o,u
__device__ __align__(16) uint32_t g_WfS[B_U32];       // Wfh
__device__ float g_WhT[H * 384];     // fp32 k-major for scalar small levels
__device__ float g_WfhT[H * H];
__device__ float g_b2[512];          // bix+bih, box+boh, bux+buh, bfx
__device__ float g_bfh[H];
__device__ float g_XG[(size_t)NNODES * 512];
__device__ float g_FH[(size_t)NLEAF * H];
__device__ __align__(16) __nv_bfloat16 g_hbuf[2][(size_t)NLEAF * H];
__device__ float g_cbuf[2][(size_t)NLEAF * H];
__device__ double g_loss[1024];

__device__ __forceinline__ float sigm(float x) { return 1.f / (1.f + expf(-x)); }
__device__ __forceinline__ uint32_t f2b2(float lo, float hi) {
    __nv_bfloat162 r = __floats2bfloat162_rn(lo, hi);
    return *(uint32_t*)&r;
}
__device__ __forceinline__ uint32_t badd2(uint32_t a, uint32_t b) {
    __nv_bfloat162 r = __hadd2(*(__nv_bfloat162*)&a, *(__nv_bfloat162*)&b);
    return *(uint32_t*)&r;
}
__device__ __forceinline__ void mma_bf16(float c[4],
    uint32_t a0, uint32_t a1, uint32_t a2, uint32_t a3,
    uint32_t b0, uint32_t b1)
{
    asm volatile(
        "mma.sync.aligned.m16n8k16.row.col.f32.bf16.bf16.f32 "
        "{%0,%1,%2,%3},{%4,%5,%6,%7},{%8,%9},{%0,%1,%2,%3};"
        : "+f"(c[0]), "+f"(c[1]), "+f"(c[2]), "+f"(c[3])
        : "r"(a0), "r"(a1), "r"(a2), "r"(a3), "r"(b0), "r"(b1));
}

// ---------------- weight packing + loss zeroing ----------------
__global__ void pack_kernel(
    const float* __restrict__ Wix, const float* __restrict__ Wox,
    const float* __restrict__ Wux, const float* __restrict__ Wfx,
    const float* __restrict__ bix, const float* __restrict__ box_,
    const float* __restrict__ bux, const float* __restrict__ bfx,
    const float* __restrict__ Wih, const float* __restrict__ Woh,
    const float* __restrict__ Wuh, const float* __restrict__ Wfh,
    const float* __restrict__ bih, const float* __restrict__ boh,
    const float* __restrict__ buh, const float* __restrict__ bfh)
{
    int idx = blockIdx.x * blockDim.x + threadIdx.x;
    if (idx < 4 * 64 * 128) {        // Wx blobs
        int nt = idx >> 13, rem = idx & 8191, kp = rem >> 7, n = rem & 127;
        const float* W = (nt == 0) ? Wix : (nt == 1) ? Wox : (nt == 2) ? Wux : Wfx;
        g_WxS[(size_t)nt * B_U32 + kp * BLD + n] = f2b2(W[n * H + 2 * kp], W[n * H + 2 * kp + 1]);
    }
    if (idx < 3 * 64 * 128) {        // Wh blobs
        int nt = idx >> 13, rem = idx & 8191, kp = rem >> 7, n = rem & 127;
        const float* W = (nt == 0) ? Wih : (nt == 1) ? Woh : Wuh;
        g_WhS[(size_t)nt * B_U32 + kp * BLD + n] = f2b2(W[n * H + 2 * kp], W[n * H + 2 * kp + 1]);
    }
    if (idx < 64 * 128) {            // Wfh blob
        int kp = idx >> 7, n = idx & 127;
        g_WfS[kp * BLD + n] = f2b2(Wfh[n * H + 2 * kp], Wfh[n * H + 2 * kp + 1]);
    }
    if (idx < H * 384) {
        int d = idx / 384, c = idx % 384, g = c >> 7, r = c & 127;
        const float* W = (g == 0) ? Wih : (g == 1) ? Woh : Wuh;
        g_WhT[idx] = W[r * H + d];
    }
    if (idx < H * H) {
        int d = idx >> 7, r = idx & 127;
        g_WfhT[idx] = Wfh[r * H + d];
    }
    if (idx < 1024) g_loss[idx] = 0.0;
    if (idx < 512) {
        int g = idx >> 7, r = idx & 127;
        float v;
        if (g == 0) v = bix[r] + bih[r];
        else if (g == 1) v = box_[r] + boh[r];
        else if (g == 2) v = bux[r] + buh[r];
        else v = bfx[r];
        g_b2[idx] = v;
    }
    if (idx < H) g_bfh[idx] = bfh[idx];
}

// ---------------- bf16 MMA tile: C[128 x 128] = op(A) @ W^T (+bias) ----------------
// Single-stage: full A (128x128 bf16) + full B staged once, ONE __syncthreads,
// then 8 K-chunks of m16n8k16 with no further barriers.
// 256 threads = 8 warps (2m x 4n), warp tile 64x32.
// NOTE: bias is indexed with the GLOBAL column (bcol included) — pass the full array.
// MODE 0: A row m = hbuf bf16 row m
// MODE 1: A row m = embeds fp32 row ridx[m] (gather + convert)
// MODE 2: A row m = hbuf[2m] + hbuf[2m+1]   (bf16 pair sum)
template <int MODE, bool ACC, bool BIAS>
__device__ __forceinline__ void gemm_tile(
    uint32_t* As, uint32_t* Bs,
    const void* Av, const int* __restrict__ ridx,
    const uint32_t* __restrict__ Wblob, const float* __restrict__ bias,
    float* __restrict__ C, int ldc, int M, int brow, int bcol)
{
    const int t    = threadIdx.x;
    const int lane = t & 31;
    const int warp = t >> 5;
    const int mw   = warp & 1;
    const int nw   = warp >> 1;
    const int g    = lane >> 2;
    const int t4   = lane & 3;

    // ---- stage B: linear copy of pre-padded blob (2176 uint4) ----
    {
        const uint4* src = (const uint4*)Wblob;
        uint4* dst = (uint4*)Bs;
        #pragma unroll
        for (int i = 0; i < 9; i++) {
            int idx = t + i * 256;
            if (idx < B_U32 / 4) dst[idx] = src[idx];
        }
    }
    // ---- stage A: 2048 uint4, row-major padded ----
    #pragma unroll
    for (int i = 0; i < 8; i++) {
        int lin = t + i * 256;            // 0..2047
        int row = lin >> 4;               // 0..127
        int c   = lin & 15;               // uint4 slot (8 bf16 each)
        uint4 val = make_uint4(0u, 0u, 0u, 0u);
        if (brow + row < M) {
            if (MODE == 1) {
                const float* s = (const float*)Av + (size_t)ridx[brow + row] * H + c * 8;
                float4 f0 = *(const float4*)s;
                float4 f1 = *(const float4*)(s + 4);
                val.x = f2b2(f0.x, f0.y); val.y = f2b2(f0.z, f0.w);
                val.z = f2b2(f1.x, f1.y); val.w = f2b2(f1.z, f1.w);
            } else if (MODE == 0) {
                val = *(const uint4*)((const __nv_bfloat16*)Av + (size_t)(brow + row) * H + c * 8);
            } else {
                const __nv_bfloat16* p0 = (const __nv_bfloat16*)Av + (size_t)(2 * (brow + row)) * H + c * 8;
                uint4 u = *(const uint4*)p0;
                uint4 v = *(const uint4*)(p0 + H);
                val.x = badd2(u.x, v.x); val.y = badd2(u.y, v.y);
                val.z = badd2(u.z, v.z); val.w = badd2(u.w, v.w);
            }
        }
        *(uint4*)&As[row * ALD + c * 4] = val;
    }
    __syncthreads();

    float acc[4][4][4];
    #pragma unroll
    for (int i = 0; i < 4; i++)
        #pragma unroll
        for (int j = 0; j < 4; j++)
            #pragma unroll
            for (int q = 0; q < 4; q++) acc[i][j][q] = 0.f;

    #pragma unroll
    for (int kb = 0; kb < 8; kb++) {
        uint32_t bf[4][2];
        #pragma unroll
        for (int nf = 0; nf < 4; nf++) {
            int ncol = nw * 32 + nf * 8 + g;
            bf[nf][0] = Bs[(kb * 8 + t4) * BLD + ncol];
            bf[nf][1] = Bs[(kb * 8 + t4 + 4) * BLD + ncol];
        }
        #pragma unroll
        for (int mf = 0; mf < 4; mf++) {
            int rb = (mw * 64 + mf * 16 + g) * ALD + kb * 8 + t4;
            uint32_t a0 = As[rb];
            uint32_t a1 = As[rb + 8 * ALD];
            uint32_t a2 = As[rb + 4];
            uint32_t a3 = As[rb + 8 * ALD + 4];
            #pragma unroll
            for (int nf = 0; nf < 4; nf++)
                mma_bf16(acc[mf][nf], a0, a1, a2, a3, bf[nf][0], bf[nf][1]);
        }
    }

    // ---- epilogue (fp32) ----
    #pragma unroll
    for (int mf = 0; mf < 4; mf++) {
        #pragma unroll
        for (int nf = 0; nf < 4; nf++) {
            int row = brow + mw * 64 + mf * 16 + g;
            int col = bcol + nw * 32 + nf * 8 + 2 * t4;
            float b0 = 0.f, b1 = 0.f;
            if (BIAS) { b0 = bias[col]; b1 = bias[col + 1]; }
            if (row < M) {
                float* p = C + (size_t)row * ldc + col;
                float v0 = acc[mf][nf][0] + b0;
                float v1 = acc[mf][nf][1] + b1;
                if (ACC) { v0 += p[0]; v1 += p[1]; }
                p[0] = v0; p[1] = v1;
            }
            if (row + 8 < M) {
                float* p = C + (size_t)(row + 8) * ldc + col;
                float v0 = acc[mf][nf][2] + b0;
                float v1 = acc[mf][nf][3] + b1;
                if (ACC) { v0 += p[0]; v1 += p[1]; }
                p[0] = v0; p[1] = v1;
            }
        }
    }
}

// ---------------- one-shot x-GEMM over ALL nodes (leaf tiles skip f-gate) ----------------
__global__ void __launch_bounds__(256, 2) xgemm_mm(
    const float* __restrict__ embeds, const int* __restrict__ words)
{
    extern __shared__ uint32_t smu[];
    uint32_t* As = smu;
    uint32_t* Bs = smu + A_U32;
    int bx = blockIdx.x, m, nt;
    if (bx < NITILE * 4) { m = bx >> 2; nt = bx & 3; }
    else { int r2 = bx - NITILE * 4; m = NITILE + r2 / 3; nt = r2 % 3; }
    gemm_tile<1, false, true>(As, Bs, embeds, words, g_WxS + (size_t)nt * B_U32,
                              g_b2, g_XG, 512, NNODES, m * 128, nt * 128);
}

// ---------------- per-level h-GEMM (pairsum, acc) + f-GEMM fused launch ----------------
__global__ void __launch_bounds__(256, 2) level_mm(int n, int off, int chd)
{
    extern __shared__ uint32_t smu[];
    uint32_t* As = smu;
    uint32_t* Bs = smu + A_U32;
    const __nv_bfloat16* h_ch = g_hbuf[chd];
    int nbm = n >> 7;
    int bx = blockIdx.x;
    if (bx < nbm * 3) {
        int m = bx / 3, nt = bx % 3;
        gemm_tile<2, true, false>(As, Bs, h_ch, nullptr, g_WhS + (size_t)nt * B_U32, nullptr,
                                  g_XG + (size_t)off * 512, 512, n, m * 128, nt * 128);
    } else {
        int m = bx - nbm * 3;
        gemm_tile<0, false, true>(As, Bs, h_ch, nullptr, g_WfS, g_bfh,
                                  g_FH, 128, 2 * n, m * 128, 0);
    }
}

// ---------------- logits + log-softmax loss (per node, 128 threads) ----------------
__device__ __forceinline__ void logits_loss(
    float h, int k, int slot,
    const float* __restrict__ Wout, const float* __restrict__ bout,
    int label, float* __restrict__ logp_out)
{
    float p[NLABEL];
    #pragma unroll
    for (int l = 0; l < NLABEL; l++) p[l] = h * Wout[l * H + k];
    #pragma unroll
    for (int offx = 16; offx; offx >>= 1) {
        #pragma unroll
        for (int l = 0; l < NLABEL; l++)
            p[l] += __shfl_down_sync(0xffffffffu, p[l], offx);
    }
    __shared__ float sw[4][NLABEL];
    int wid = k >> 5, lane = k & 31;
    if (lane == 0) {
        #pragma unroll
        for (int l = 0; l < NLABEL; l++) sw[wid][l] = p[l];
    }
    __syncthreads();
    if (k == 0) {
        float lg[NLABEL], m = -1e30f;
        #pragma unroll
        for (int l = 0; l < NLABEL; l++) {
            lg[l] = sw[0][l] + sw[1][l] + sw[2][l] + sw[3][l] + bout[l];
            m = fmaxf(m, lg[l]);
        }
        float s = 0.f;
        #pragma unroll
        for (int l = 0; l < NLABEL; l++) s += expf(lg[l] - m);
        float lse = m + logf(s);
        atomicAdd(&g_loss[slot & 1023], (double)(lse - lg[label]));
        if (logp_out) {
            #pragma unroll
            for (int l = 0; l < NLABEL; l++) logp_out[l] = lg[l] - lse;
        }
    }
}

// ---------------- per-node gates + cell + loss (big levels) ----------------
__global__ void __launch_bounds__(128) node_update(
    int off, int cur, int chd, int isLeaf,
    const int* __restrict__ labels,
    const float* __restrict__ Wout, const float* __restrict__ bout,
    float* __restrict__ logp_out)
{
    const int j = blockIdx.x;
    const int k = threadIdx.x;
    const float* xg = g_XG + (size_t)(off + j) * 512;

    float gi = sigm(xg[k]);
    float go = sigm(xg[128 + k]);
    float gu = tanhf(xg[256 + k]);
    float c = gi * gu;
    if (!isLeaf) {
        float xf = xg[384 + k];
        size_t c0 = (size_t)(2 * j) * H + k;
        c += sigm(xf + g_FH[c0])     * g_cbuf[chd][c0]
           + sigm(xf + g_FH[c0 + H]) * g_cbuf[chd][c0 + H];
    }
    float h = go * tanhf(c);
    g_cbuf[cur][(size_t)j * H + k] = c;
    g_hbuf[cur][(size_t)j * H + k] = __float2bfloat16(h);

    logits_loss(h, k, off + j, Wout, bout, labels[j], logp_out);
}

// ---------------- fully fused small level (n <= 64): GEMV + gates + loss ----------------
__global__ void __launch_bounds__(128) small_level(
    int off, int cur, int chd,
    const int* __restrict__ labels,
    const float* __restrict__ Wout, const float* __restrict__ bout,
    float* __restrict__ logp_out)
{
    const int j = blockIdx.x;
    const int k = threadIdx.x;
    __shared__ float hs[H], h0s[H], h1s[H];

    size_t cb = (size_t)(2 * j) * H + k;
    float h0 = __bfloat162float(g_hbuf[chd][cb]);
    float h1 = __bfloat162float(g_hbuf[chd][cb + H]);
    h0s[k] = h0; h1s[k] = h1; hs[k] = h0 + h1;
    __syncthreads();

    const float* xg = g_XG + (size_t)(off + j) * 512;
    float ai = xg[k], ao = xg[128 + k], au = xg[256 + k], xf = xg[384 + k];
    float f0 = g_bfh[k], f1 = g_bfh[k];
    #pragma unroll 8
    for (int d = 0; d < H; d++) {
        float hd = hs[d];
        ai += hd * g_WhT[d * 384 + k];
        ao += hd * g_WhT[d * 384 + 128 + k];
        au += hd * g_WhT[d * 384 + 256 + k];
        float w = g_WfhT[d * 128 + k];
        f0 += h0s[d] * w;
        f1 += h1s[d] * w;
    }
    float gi = sigm(ai), go = sigm(ao), gu = tanhf(au);
    float c = gi * gu + sigm(xf + f0) * g_cbuf[chd][cb]
                      + sigm(xf + f1) * g_cbuf[chd][cb + H];
    float h = go * tanhf(c);
    g_cbuf[cur][(size_t)j * H + k] = c;
    g_hbuf[cur][(size_t)j * H + k] = __float2bfloat16(h);

    logits_loss(h, k, off + j, Wout, bout, labels[j], logp_out);
}

// ---------------- loss reduction ----------------
__global__ void finalize_kernel(float* __restrict__ d_out, int out_size)
{
    __shared__ double s[256];
    int t = threadIdx.x;
    s[t] = g_loss[t] + g_loss[t + 256] + g_loss[t + 512] + g_loss[t + 768];
    __syncthreads();
    for (int offx = 128; offx; offx >>= 1) {
        if (t < offx) s[t] += s[t + offx];
        __syncthreads();
    }
    if (t == 0) {
        if (out_size >= NLABEL + 1) d_out[NLABEL] = (float)s[0];
        else                        d_out[0]      = (float)s[0];
    }
}

// ---------------- launch ----------------
extern "C" void kernel_launch(void* const* d_in, const int* in_sizes, int n_in,
                              void* d_out, int out_size)
{
    const float* embeds = (const float*)d_in[0];
    const int*   words  = (const int*)d_in[1];
    const int*   labels = (const int*)d_in[2];
    const float* Wix = (const float*)d_in[5];
    const float* bix = (const float*)d_in[6];
    const float* Wih = (const float*)d_in[7];
    const float* bih = (const float*)d_in[8];
    const float* Wfx = (const float*)d_in[9];
    const float* bfx = (const float*)d_in[10];
    const float* Wfh = (const float*)d_in[11];
    const float* bfh = (const float*)d_in[12];
    const float* Wox = (const float*)d_in[13];
    const float* box_ = (const float*)d_in[14];
    const float* Woh = (const float*)d_in[15];
    const float* boh = (const float*)d_in[16];
    const float* Wux = (const float*)d_in[17];
    const float* bux = (const float*)d_in[18];
    const float* Wuh = (const float*)d_in[19];
    const float* buh = (const float*)d_in[20];
    const float* Wout = (const float*)d_in[21];
    const float* bout = (const float*)d_in[22];
    float* out = (float*)d_out;

    cudaFuncSetAttribute(xgemm_mm, cudaFuncAttributeMaxDynamicSharedMemorySize, SMEM_DYN);
    cudaFuncSetAttribute(level_mm, cudaFuncAttributeMaxDynamicSharedMemorySize, SMEM_DYN);

    pack_kernel<<<256, 256>>>(Wix, Wox, Wux, Wfx, bix, box_, bux, bfx,
                              Wih, Woh, Wuh, Wfh, bih, boh, buh, bfh);

    xgemm_mm<<<NITILE * 4 + (NMTILE - NITILE) * 3, 256, SMEM_DYN>>>(embeds, words);

    for (int l = DEPTH - 1; l >= 0; --l) {
        int n   = 1 << l;
        int off = n - 1;
        int cur = l & 1, chd = cur ^ 1;
        float* logp_dst = (l == 0 && out_size >= NLABEL + 1) ? out : nullptr;

        if (l == DEPTH - 1) {
            node_update<<<n, 128>>>(off, cur, chd, 1, labels + off, Wout, bout, nullptr);
        } else if (n >= 128) {
            int nbm = n >> 7;
            level_mm<<<nbm * 5, 256, SMEM_DYN>>>(n, off, chd);
            node_update<<<n, 128>>>(off, cur, chd, 0, labels + off, Wout, bout, logp_dst);
        } else {
            small_level<<<n, 128>>>(off, cur, chd, labels + off, Wout, bout, logp_dst);
        }
    }
    finalize_kernel<<<1, 256>>>(out, out_size);
}

// round 11
// speedup vs baseline: 4.3423x; 1.1178x over previous
#include <cuda_runtime.h>
#include <cuda_bf16.h>
#include <cstdint>

#define H 128
#define NLABEL 5
#define DEPTH 18
#define NNODES ((1 << DEPTH) - 1)   /* 262143 */
#define NLEAF  (1 << (DEPTH - 1))   /* 131072 */
#define NITILE 1024                 /* m-tiles fully covering internal nodes */
#define NMTILE 2048                 /* ceil(NNODES/128) */

#define ALD 68                      /* u32 per A smem row (64 + 4 pad) */
#define BLD 136                     /* u32 per B smem kp-row (128 + 8 pad) */
#define A_U32 (128 * ALD)           /* 8704 */
#define B_U32 (64 * BLD)            /* 8704 */
#define SMEM_DYN ((A_U32 + B_U32) * 4)   /* 69632 B */

// ---------------- device scratch (static, no allocation) ----------------
__device__ __align__(16) uint32_t g_WxS[4 * B_U32];   // gates i,o,u,f  (pre-padded blobs)
__device__ __align__(16) uint32_t g_WhS[3 * B_U32];   // gates i,o,u
__device__ __align__(16) uint32_t g_WfS[B_U32];       // Wfh
__device__ float g_WhT[H * 384];     // fp32 k-major for scalar small levels
__device__ float g_WfhT[H * H];
__device__ float g_b2[512];          // bix+bih, box+boh, bux+buh, bfx
__device__ float g_bfh[H];
__device__ __align__(16) __nv_bfloat16 g_XG[(size_t)NNODES * 512];  // preacts, bf16
__device__ __align__(16) __nv_bfloat16 g_FH[(size_t)NLEAF * H];     // f contributions, bf16
__device__ __align__(16) __nv_bfloat16 g_hbuf[2][(size_t)NLEAF * H];
__device__ float g_cbuf[2][(size_t)NLEAF * H];
__device__ double g_loss[1024];

__device__ __forceinline__ float sigm(float x) { return 1.f / (1.f + expf(-x)); }
__device__ __forceinline__ uint32_t f2b2(float lo, float hi) {
    __nv_bfloat162 r = __floats2bfloat162_rn(lo, hi);
    return *(uint32_t*)&r;
}
__device__ __forceinline__ uint32_t badd2(uint32_t a, uint32_t b) {
    __nv_bfloat162 r = __hadd2(*(__nv_bfloat162*)&a, *(__nv_bfloat162*)&b);
    return *(uint32_t*)&r;
}
__device__ __forceinline__ float bf_lo(uint32_t u) {
    return __bfloat162float(((__nv_bfloat162*)&u)->x);
}
__device__ __forceinline__ float bf_hi(uint32_t u) {
    return __bfloat162float(((__nv_bfloat162*)&u)->y);
}
__device__ __forceinline__ void mma_bf16(float c[4],
    uint32_t a0, uint32_t a1, uint32_t a2, uint32_t a3,
    uint32_t b0, uint32_t b1)
{
    asm volatile(
        "mma.sync.aligned.m16n8k16.row.col.f32.bf16.bf16.f32 "
        "{%0,%1,%2,%3},{%4,%5,%6,%7},{%8,%9},{%0,%1,%2,%3};"
        : "+f"(c[0]), "+f"(c[1]), "+f"(c[2]), "+f"(c[3])
        : "r"(a0), "r"(a1), "r"(a2), "r"(a3), "r"(b0), "r"(b1));
}

// ---------------- weight packing + loss zeroing ----------------
__global__ void pack_kernel(
    const float* __restrict__ Wix, const float* __restrict__ Wox,
    const float* __restrict__ Wux, const float* __restrict__ Wfx,
    const float* __restrict__ bix, const float* __restrict__ box_,
    const float* __restrict__ bux, const float* __restrict__ bfx,
    const float* __restrict__ Wih, const float* __restrict__ Woh,
    const float* __restrict__ Wuh, const float* __restrict__ Wfh,
    const float* __restrict__ bih, const float* __restrict__ boh,
    const float* __restrict__ buh, const float* __restrict__ bfh)
{
    int idx = blockIdx.x * blockDim.x + threadIdx.x;
    if (idx < 4 * 64 * 128) {        // Wx blobs
        int nt = idx >> 13, rem = idx & 8191, kp = rem >> 7, n = rem & 127;
        const float* W = (nt == 0) ? Wix : (nt == 1) ? Wox : (nt == 2) ? Wux : Wfx;
        g_WxS[(size_t)nt * B_U32 + kp * BLD + n] = f2b2(W[n * H + 2 * kp], W[n * H + 2 * kp + 1]);
    }
    if (idx < 3 * 64 * 128) {        // Wh blobs
        int nt = idx >> 13, rem = idx & 8191, kp = rem >> 7, n = rem & 127;
        const float* W = (nt == 0) ? Wih : (nt == 1) ? Woh : Wuh;
        g_WhS[(size_t)nt * B_U32 + kp * BLD + n] = f2b2(W[n * H + 2 * kp], W[n * H + 2 * kp + 1]);
    }
    if (idx < 64 * 128) {            // Wfh blob
        int kp = idx >> 7, n = idx & 127;
        g_WfS[kp * BLD + n] = f2b2(Wfh[n * H + 2 * kp], Wfh[n * H + 2 * kp + 1]);
    }
    if (idx < H * 384) {
        int d = idx / 384, c = idx % 384, g = c >> 7, r = c & 127;
        const float* W = (g == 0) ? Wih : (g == 1) ? Woh : Wuh;
        g_WhT[idx] = W[r * H + d];
    }
    if (idx < H * H) {
        int d = idx >> 7, r = idx & 127;
        g_WfhT[idx] = Wfh[r * H + d];
    }
    if (idx < 1024) g_loss[idx] = 0.0;
    if (idx < 512) {
        int g = idx >> 7, r = idx & 127;
        float v;
        if (g == 0) v = bix[r] + bih[r];
        else if (g == 1) v = box_[r] + boh[r];
        else if (g == 2) v = bux[r] + buh[r];
        else v = bfx[r];
        g_b2[idx] = v;
    }
    if (idx < H) g_bfh[idx] = bfh[idx];
}

// ---------------- bf16 MMA tile: C_bf16[128 x 128] = op(A) @ W^T (+bias) ----------------
// Single-stage full-K staging, one __syncthreads, 8 barrier-free K-chunks.
// Output C is bf16 (packed bf16x2 stores; ldc in ELEMENTS, even).
// bias indexed with GLOBAL column.
// MODE 0: A row m = hbuf bf16 row m
// MODE 1: A row m = embeds fp32 row ridx[m] (gather + convert)
// MODE 2: A row m = hbuf[2m] + hbuf[2m+1]   (bf16 pair sum)
template <int MODE, bool ACC, bool BIAS>
__device__ __forceinline__ void gemm_tile(
    uint32_t* As, uint32_t* Bs,
    const void* Av, const int* __restrict__ ridx,
    const uint32_t* __restrict__ Wblob, const float* __restrict__ bias,
    __nv_bfloat16* __restrict__ C, int ldc, int M, int brow, int bcol)
{
    const int t    = threadIdx.x;
    const int lane = t & 31;
    const int warp = t >> 5;
    const int mw   = warp & 1;
    const int nw   = warp >> 1;
    const int g    = lane >> 2;
    const int t4   = lane & 3;

    // ---- stage B: linear copy of pre-padded blob ----
    {
        const uint4* src = (const uint4*)Wblob;
        uint4* dst = (uint4*)Bs;
        #pragma unroll
        for (int i = 0; i < 9; i++) {
            int idx = t + i * 256;
            if (idx < B_U32 / 4) dst[idx] = src[idx];
        }
    }
    // ---- stage A: 2048 uint4, row-major padded ----
    #pragma unroll
    for (int i = 0; i < 8; i++) {
        int lin = t + i * 256;
        int row = lin >> 4;
        int c   = lin & 15;
        uint4 val = make_uint4(0u, 0u, 0u, 0u);
        if (brow + row < M) {
            if (MODE == 1) {
                const float* s = (const float*)Av + (size_t)ridx[brow + row] * H + c * 8;
                float4 f0 = *(const float4*)s;
                float4 f1 = *(const float4*)(s + 4);
                val.x = f2b2(f0.x, f0.y); val.y = f2b2(f0.z, f0.w);
                val.z = f2b2(f1.x, f1.y); val.w = f2b2(f1.z, f1.w);
            } else if (MODE == 0) {
                val = *(const uint4*)((const __nv_bfloat16*)Av + (size_t)(brow + row) * H + c * 8);
            } else {
                const __nv_bfloat16* p0 = (const __nv_bfloat16*)Av + (size_t)(2 * (brow + row)) * H + c * 8;
                uint4 u = *(const uint4*)p0;
                uint4 v = *(const uint4*)(p0 + H);
                val.x = badd2(u.x, v.x); val.y = badd2(u.y, v.y);
                val.z = badd2(u.z, v.z); val.w = badd2(u.w, v.w);
            }
        }
        *(uint4*)&As[row * ALD + c * 4] = val;
    }
    __syncthreads();

    float acc[4][4][4];
    #pragma unroll
    for (int i = 0; i < 4; i++)
        #pragma unroll
        for (int j = 0; j < 4; j++)
            #pragma unroll
            for (int q = 0; q < 4; q++) acc[i][j][q] = 0.f;

    #pragma unroll
    for (int kb = 0; kb < 8; kb++) {
        uint32_t bf[4][2];
        #pragma unroll
        for (int nf = 0; nf < 4; nf++) {
            int ncol = nw * 32 + nf * 8 + g;
            bf[nf][0] = Bs[(kb * 8 + t4) * BLD + ncol];
            bf[nf][1] = Bs[(kb * 8 + t4 + 4) * BLD + ncol];
        }
        #pragma unroll
        for (int mf = 0; mf < 4; mf++) {
            int rb = (mw * 64 + mf * 16 + g) * ALD + kb * 8 + t4;
            uint32_t a0 = As[rb];
            uint32_t a1 = As[rb + 8 * ALD];
            uint32_t a2 = As[rb + 4];
            uint32_t a3 = As[rb + 8 * ALD + 4];
            #pragma unroll
            for (int nf = 0; nf < 4; nf++)
                mma_bf16(acc[mf][nf], a0, a1, a2, a3, bf[nf][0], bf[nf][1]);
        }
    }

    // ---- epilogue: packed bf16x2 stores ----
    #pragma unroll
    for (int mf = 0; mf < 4; mf++) {
        #pragma unroll
        for (int nf = 0; nf < 4; nf++) {
            int row = brow + mw * 64 + mf * 16 + g;
            int col = bcol + nw * 32 + nf * 8 + 2 * t4;
            float b0 = 0.f, b1 = 0.f;
            if (BIAS) { b0 = bias[col]; b1 = bias[col + 1]; }
            if (row < M) {
                uint32_t* p = (uint32_t*)(C + (size_t)row * ldc + col);
                float v0 = acc[mf][nf][0] + b0;
                float v1 = acc[mf][nf][1] + b1;
                if (ACC) { uint32_t o = *p; v0 += bf_lo(o); v1 += bf_hi(o); }
                *p = f2b2(v0, v1);
            }
            if (row + 8 < M) {
                uint32_t* p = (uint32_t*)(C + (size_t)(row + 8) * ldc + col);
                float v0 = acc[mf][nf][2] + b0;
                float v1 = acc[mf][nf][3] + b1;
                if (ACC) { uint32_t o = *p; v0 += bf_lo(o); v1 += bf_hi(o); }
                *p = f2b2(v0, v1);
            }
        }
    }
}

// ---------------- one-shot x-GEMM over ALL nodes (leaf tiles skip f-gate) ----------------
__global__ void __launch_bounds__(256, 2) xgemm_mm(
    const float* __restrict__ embeds, const int* __restrict__ words)
{
    extern __shared__ uint32_t smu[];
    uint32_t* As = smu;
    uint32_t* Bs = smu + A_U32;
    int bx = blockIdx.x, m, nt;
    if (bx < NITILE * 4) { m = bx >> 2; nt = bx & 3; }
    else { int r2 = bx - NITILE * 4; m = NITILE + r2 / 3; nt = r2 % 3; }
    gemm_tile<1, false, true>(As, Bs, embeds, words, g_WxS + (size_t)nt * B_U32,
                              g_b2, g_XG, 512, NNODES, m * 128, nt * 128);
}

// ---------------- per-level h-GEMM (pairsum, acc) + f-GEMM fused launch ----------------
__global__ void __launch_bounds__(256, 2) level_mm(int n, int off, int chd)
{
    extern __shared__ uint32_t smu[];
    uint32_t* As = smu;
    uint32_t* Bs = smu + A_U32;
    const __nv_bfloat16* h_ch = g_hbuf[chd];
    int nbm = n >> 7;
    int bx = blockIdx.x;
    if (bx < nbm * 3) {
        int m = bx / 3, nt = bx % 3;
        gemm_tile<2, true, false>(As, Bs, h_ch, nullptr, g_WhS + (size_t)nt * B_U32, nullptr,
                                  g_XG + (size_t)off * 512, 512, n, m * 128, nt * 128);
    } else {
        int m = bx - nbm * 3;
        gemm_tile<0, false, true>(As, Bs, h_ch, nullptr, g_WfS, g_bfh,
                                  g_FH, 128, 2 * n, m * 128, 0);
    }
}

// ---------------- logits + log-softmax loss (per node, 128 threads) ----------------
__device__ __forceinline__ void logits_loss(
    float h, int k, int slot,
    const float* __restrict__ Wout, const float* __restrict__ bout,
    int label, float* __restrict__ logp_out)
{
    float p[NLABEL];
    #pragma unroll
    for (int l = 0; l < NLABEL; l++) p[l] = h * Wout[l * H + k];
    #pragma unroll
    for (int offx = 16; offx; offx >>= 1) {
        #pragma unroll
        for (int l = 0; l < NLABEL; l++)
            p[l] += __shfl_down_sync(0xffffffffu, p[l], offx);
    }
    __shared__ float sw[4][NLABEL];
    int wid = k >> 5, lane = k & 31;
    if (lane == 0) {
        #pragma unroll
        for (int l = 0; l < NLABEL; l++) sw[wid][l] = p[l];
    }
    __syncthreads();
    if (k == 0) {
        float lg[NLABEL], m = -1e30f;
        #pragma unroll
        for (int l = 0; l < NLABEL; l++) {
            lg[l] = sw[0][l] + sw[1][l] + sw[2][l] + sw[3][l] + bout[l];
            m = fmaxf(m, lg[l]);
        }
        float s = 0.f;
        #pragma unroll
        for (int l = 0; l < NLABEL; l++) s += expf(lg[l] - m);
        float lse = m + logf(s);
        atomicAdd(&g_loss[slot & 1023], (double)(lse - lg[label]));
        if (logp_out) {
            #pragma unroll
            for (int l = 0; l < NLABEL; l++) logp_out[l] = lg[l] - lse;
        }
    }
}

// ---------------- per-node gates + cell + loss (big levels) ----------------
__global__ void __launch_bounds__(128) node_update(
    int off, int cur, int chd, int isLeaf,
    const int* __restrict__ labels,
    const float* __restrict__ Wout, const float* __restrict__ bout,
    float* __restrict__ logp_out)
{
    const int j = blockIdx.x;
    const int k = threadIdx.x;
    const __nv_bfloat16* xg = g_XG + (size_t)(off + j) * 512;

    float gi = sigm(__bfloat162float(xg[k]));
    float go = sigm(__bfloat162float(xg[128 + k]));
    float gu = tanhf(__bfloat162float(xg[256 + k]));
    float c = gi * gu;
    if (!isLeaf) {
        float xf = __bfloat162float(xg[384 + k]);
        size_t c0 = (size_t)(2 * j) * H + k;
        c += sigm(xf + __bfloat162float(g_FH[c0]))     * g_cbuf[chd][c0]
           + sigm(xf + __bfloat162float(g_FH[c0 + H])) * g_cbuf[chd][c0 + H];
    }
    float h = go * tanhf(c);
    g_cbuf[cur][(size_t)j * H + k] = c;
    g_hbuf[cur][(size_t)j * H + k] = __float2bfloat16(h);

    logits_loss(h, k, off + j, Wout, bout, labels[j], logp_out);
}

// ---------------- fully fused small level (n <= 64): GEMV + gates + loss ----------------
__global__ void __launch_bounds__(128) small_level(
    int off, int cur, int chd,
    const int* __restrict__ labels,
    const float* __restrict__ Wout, const float* __restrict__ bout,
    float* __restrict__ logp_out)
{
    const int j = blockIdx.x;
    const int k = threadIdx.x;
    __shared__ float hs[H], h0s[H], h1s[H];

    size_t cb = (size_t)(2 * j) * H + k;
    float h0 = __bfloat162float(g_hbuf[chd][cb]);
    float h1 = __bfloat162float(g_hbuf[chd][cb + H]);
    h0s[k] = h0; h1s[k] = h1; hs[k] = h0 + h1;
    __syncthreads();

    const __nv_bfloat16* xg = g_XG + (size_t)(off + j) * 512;
    float ai = __bfloat162float(xg[k]);
    float ao = __bfloat162float(xg[128 + k]);
    float au = __bfloat162float(xg[256 + k]);
    float xf = __bfloat162float(xg[384 + k]);
    float f0 = g_bfh[k], f1 = g_bfh[k];
    #pragma unroll 8
    for (int d = 0; d < H; d++) {
        float hd = hs[d];
        ai += hd * g_WhT[d * 384 + k];
        ao += hd * g_WhT[d * 384 + 128 + k];
        au += hd * g_WhT[d * 384 + 256 + k];
        float w = g_WfhT[d * 128 + k];
        f0 += h0s[d] * w;
        f1 += h1s[d] * w;
    }
    float gi = sigm(ai), go = sigm(ao), gu = tanhf(au);
    float c = gi * gu + sigm(xf + f0) * g_cbuf[chd][cb]
                      + sigm(xf + f1) * g_cbuf[chd][cb + H];
    float h = go * tanhf(c);
    g_cbuf[cur][(size_t)j * H + k] = c;
    g_hbuf[cur][(size_t)j * H + k] = __float2bfloat16(h);

    logits_loss(h, k, off + j, Wout, bout, labels[j], logp_out);
}

// ---------------- loss reduction ----------------
__global__ void finalize_kernel(float* __restrict__ d_out, int out_size)
{
    __shared__ double s[256];
    int t = threadIdx.x;
    s[t] = g_loss[t] + g_loss[t + 256] + g_loss[t + 512] + g_loss[t + 768];
    __syncthreads();
    for (int offx = 128; offx; offx >>= 1) {
        if (t < offx) s[t] += s[t + offx];
        __syncthreads();
    }
    if (t == 0) {
        if (out_size >= NLABEL + 1) d_out[NLABEL] = (float)s[0];
        else                        d_out[0]      = (float)s[0];
    }
}

// ---------------- launch ----------------
extern "C" void kernel_launch(void* const* d_in, const int* in_sizes, int n_in,
                              void* d_out, int out_size)
{
    const float* embeds = (const float*)d_in[0];
    const int*   words  = (const int*)d_in[1];
    const int*   labels = (const int*)d_in[2];
    const float* Wix = (const float*)d_in[5];
    const float* bix = (const float*)d_in[6];
    const float* Wih = (const float*)d_in[7];
    const float* bih = (const float*)d_in[8];
    const float* Wfx = (const float*)d_in[9];
    const float* bfx = (const float*)d_in[10];
    const float* Wfh = (const float*)d_in[11];
    const float* bfh = (const float*)d_in[12];
    const float* Wox = (const float*)d_in[13];
    const float* box_ = (const float*)d_in[14];
    const float* Woh = (const float*)d_in[15];
    const float* boh = (const float*)d_in[16];
    const float* Wux = (const float*)d_in[17];
    const float* bux = (const float*)d_in[18];
    const float* Wuh = (const float*)d_in[19];
    const float* buh = (const float*)d_in[20];
    const float* Wout = (const float*)d_in[21];
    const float* bout = (const float*)d_in[22];
    float* out = (float*)d_out;

    cudaFuncSetAttribute(xgemm_mm, cudaFuncAttributeMaxDynamicSharedMemorySize, SMEM_DYN);
    cudaFuncSetAttribute(level_mm, cudaFuncAttributeMaxDynamicSharedMemorySize, SMEM_DYN);

    pack_kernel<<<256, 256>>>(Wix, Wox, Wux, Wfx, bix, box_, bux, bfx,
                              Wih, Woh, Wuh, Wfh, bih, boh, buh, bfh);

    xgemm_mm<<<NITILE * 4 + (NMTILE - NITILE) * 3, 256, SMEM_DYN>>>(embeds, words);

    for (int l = DEPTH - 1; l >= 0; --l) {
        int n   = 1 << l;
        int off = n - 1;
        int cur = l & 1, chd = cur ^ 1;
        float* logp_dst = (l == 0 && out_size >= NLABEL + 1) ? out : nullptr;

        if (l == DEPTH - 1) {
            node_update<<<n, 128>>>(off, cur, chd, 1, labels + off, Wout, bout, nullptr);
        } else if (n >= 128) {
            int nbm = n >> 7;
            level_mm<<<nbm * 5, 256, SMEM_DYN>>>(n, off, chd);
            node_update<<<n, 128>>>(off, cur, chd, 0, labels + off, Wout, bout, logp_dst);
        } else {
            small_level<<<n, 128>>>(off, cur, chd, labels + off, Wout, bout, logp_dst);
        }
    }
    finalize_kernel<<<1, 256>>>(out, out_size);
}

// round 12
// speedup vs baseline: 4.3885x; 1.0106x over previous
#include <cuda_runtime.h>
#include <cuda_bf16.h>
#include <cstdint>

#define H 128
#define NLABEL 5
#define DEPTH 18
#define VOCAB 50000
#define NNODES ((1 << DEPTH) - 1)   /* 262143 */
#define NLEAF  (1 << (DEPTH - 1))   /* 131072 */
#define NITILE 1024                 /* m-tiles fully covering internal nodes */
#define NMTILE 2048                 /* ceil(NNODES/128) */

#define ALD 68                      /* u32 per A smem row (64 + 4 pad) */
#define BLD 68                      /* u32 per B smem n-row (64 + 4 pad) */
#define A_U32 (128 * ALD)           /* 8704 */
#define B_U32 (128 * BLD)           /* 8704 */
#define SMEM_DYN ((A_U32 + B_U32) * 4)   /* 69632 B */

// ---------------- device scratch (static, no allocation) ----------------
// Pre-padded bf16-pair weight blobs, n-major (matches SMEM B image):
// blob[n * BLD + kp] = {W[n][2kp], W[n][2kp+1]}
__device__ __align__(16) uint32_t g_WxS[4 * B_U32];   // gates i,o,u,f
__device__ __align__(16) uint32_t g_WhS[3 * B_U32];   // gates i,o,u
__device__ __align__(16) uint32_t g_WfS[B_U32];       // Wfh
__device__ __align__(16) uint32_t g_embB[(size_t)VOCAB * 64];  // bf16 embeds table
__device__ float g_WhT[H * 384];     // fp32 k-major for scalar small levels
__device__ float g_WfhT[H * H];
__device__ float g_b2[512];          // bix+bih, box+boh, bux+buh, bfx
__device__ float g_bfh[H];
__device__ __align__(16) __nv_bfloat16 g_XG[(size_t)NNODES * 512];  // preacts, bf16
__device__ __align__(16) __nv_bfloat16 g_FH[(size_t)NLEAF * H];     // f contributions, bf16
__device__ __align__(16) __nv_bfloat16 g_hbuf[2][(size_t)NLEAF * H];
__device__ float g_cbuf[2][(size_t)NLEAF * H];
__device__ double g_loss[1024];

__device__ __forceinline__ float sigm(float x) { return 1.f / (1.f + expf(-x)); }
__device__ __forceinline__ uint32_t f2b2(float lo, float hi) {
    __nv_bfloat162 r = __floats2bfloat162_rn(lo, hi);
    return *(uint32_t*)&r;
}
__device__ __forceinline__ uint32_t badd2(uint32_t a, uint32_t b) {
    __nv_bfloat162 r = __hadd2(*(__nv_bfloat162*)&a, *(__nv_bfloat162*)&b);
    return *(uint32_t*)&r;
}
__device__ __forceinline__ float bf_lo(uint32_t u) {
    return __bfloat162float(((__nv_bfloat162*)&u)->x);
}
__device__ __forceinline__ float bf_hi(uint32_t u) {
    return __bfloat162float(((__nv_bfloat162*)&u)->y);
}
__device__ __forceinline__ void mma_bf16(float c[4],
    uint32_t a0, uint32_t a1, uint32_t a2, uint32_t a3,
    uint32_t b0, uint32_t b1)
{
    asm volatile(
        "mma.sync.aligned.m16n8k16.row.col.f32.bf16.bf16.f32 "
        "{%0,%1,%2,%3},{%4,%5,%6,%7},{%8,%9},{%0,%1,%2,%3};"
        : "+f"(c[0]), "+f"(c[1]), "+f"(c[2]), "+f"(c[3])
        : "r"(a0), "r"(a1), "r"(a2), "r"(a3), "r"(b0), "r"(b1));
}
__device__ __forceinline__ void ldsm_x4(uint32_t& r0, uint32_t& r1,
                                        uint32_t& r2, uint32_t& r3, uint32_t addr)
{
    asm volatile("ldmatrix.sync.aligned.m8n8.x4.shared.b16 {%0,%1,%2,%3}, [%4];"
        : "=r"(r0), "=r"(r1), "=r"(r2), "=r"(r3) : "r"(addr));
}

// ---------------- embeds fp32 -> bf16 table ----------------
__global__ void conv_embeds(const float* __restrict__ e)
{
    int i = blockIdx.x * blockDim.x + threadIdx.x;
    if (i < VOCAB * 64) g_embB[i] = f2b2(e[2 * i], e[2 * i + 1]);
}

// ---------------- weight packing + loss zeroing ----------------
__global__ void pack_kernel(
    const float* __restrict__ Wix, const float* __restrict__ Wox,
    const float* __restrict__ Wux, const float* __restrict__ Wfx,
    const float* __restrict__ bix, const float* __restrict__ box_,
    const float* __restrict__ bux, const float* __restrict__ bfx,
    const float* __restrict__ Wih, const float* __restrict__ Woh,
    const float* __restrict__ Wuh, const float* __restrict__ Wfh,
    const float* __restrict__ bih, const float* __restrict__ boh,
    const float* __restrict__ buh, const float* __restrict__ bfh)
{
    int idx = blockIdx.x * blockDim.x + threadIdx.x;
    if (idx < 4 * 128 * 64) {        // Wx blobs (n-major)
        int nt = idx >> 13, rem = idx & 8191, n = rem >> 6, kp = rem & 63;
        const float* W = (nt == 0) ? Wix : (nt == 1) ? Wox : (nt == 2) ? Wux : Wfx;
        g_WxS[(size_t)nt * B_U32 + n * BLD + kp] = f2b2(W[n * H + 2 * kp], W[n * H + 2 * kp + 1]);
    }
    if (idx < 3 * 128 * 64) {        // Wh blobs
        int nt = idx >> 13, rem = idx & 8191, n = rem >> 6, kp = rem & 63;
        const float* W = (nt == 0) ? Wih : (nt == 1) ? Woh : Wuh;
        g_WhS[(size_t)nt * B_U32 + n * BLD + kp] = f2b2(W[n * H + 2 * kp], W[n * H + 2 * kp + 1]);
    }
    if (idx < 128 * 64) {            // Wfh blob
        int n = idx >> 6, kp = idx & 63;
        g_WfS[n * BLD + kp] = f2b2(Wfh[n * H + 2 * kp], Wfh[n * H + 2 * kp + 1]);
    }
    if (idx < H * 384) {
        int d = idx / 384, c = idx % 384, g = c >> 7, r = c & 127;
        const float* W = (g == 0) ? Wih : (g == 1) ? Woh : Wuh;
        g_WhT[idx] = W[r * H + d];
    }
    if (idx < H * H) {
        int d = idx >> 7, r = idx & 127;
        g_WfhT[idx] = Wfh[r * H + d];
    }
    if (idx < 1024) g_loss[idx] = 0.0;
    if (idx < 512) {
        int g = idx >> 7, r = idx & 127;
        float v;
        if (g == 0) v = bix[r] + bih[r];
        else if (g == 1) v = box_[r] + boh[r];
        else if (g == 2) v = bux[r] + buh[r];
        else v = bfx[r];
        g_b2[idx] = v;
    }
    if (idx < H) g_bfh[idx] = bfh[idx];
}

// ---------------- bf16 MMA tile: C_bf16[128 x 128] = op(A) @ W^T (+bias) ----------------
// Single-stage full-K staging, one __syncthreads, 8 barrier-free K-chunks,
// ldmatrix fragment loads (6 LDSM per chunk vs 24 LDS.32).
// MODE 0: A row m = hbuf bf16 row m
// MODE 1: A row m = g_embB bf16 row ridx[m]  (gather)
// MODE 2: A row m = hbuf[2m] + hbuf[2m+1]    (bf16 pair sum)
template <int MODE, bool ACC, bool BIAS>
__device__ __forceinline__ void gemm_tile(
    uint32_t* As, uint32_t* Bs,
    const void* Av, const int* __restrict__ ridx,
    const uint32_t* __restrict__ Wblob, const float* __restrict__ bias,
    __nv_bfloat16* __restrict__ C, int ldc, int M, int brow, int bcol)
{
    const int t    = threadIdx.x;
    const int lane = t & 31;
    const int warp = t >> 5;
    const int mw   = warp & 1;
    const int nw   = warp >> 1;
    const int g    = lane >> 2;
    const int t4   = lane & 3;

    // ---- stage B: linear copy of pre-padded blob (2176 uint4) ----
    {
        const uint4* src = (const uint4*)Wblob;
        uint4* dst = (uint4*)Bs;
        #pragma unroll
        for (int i = 0; i < 9; i++) {
            int idx = t + i * 256;
            if (idx < B_U32 / 4) dst[idx] = src[idx];
        }
    }
    // ---- stage A: 2048 uint4, row-major padded ----
    #pragma unroll
    for (int i = 0; i < 8; i++) {
        int lin = t + i * 256;
        int row = lin >> 4;
        int c   = lin & 15;
        uint4 val = make_uint4(0u, 0u, 0u, 0u);
        if (brow + row < M) {
            if (MODE == 1) {
                val = ((const uint4*)Av)[(size_t)ridx[brow + row] * 16 + c];
            } else if (MODE == 0) {
                val = *(const uint4*)((const __nv_bfloat16*)Av + (size_t)(brow + row) * H + c * 8);
            } else {
                const __nv_bfloat16* p0 = (const __nv_bfloat16*)Av + (size_t)(2 * (brow + row)) * H + c * 8;
                uint4 u = *(const uint4*)p0;
                uint4 v = *(const uint4*)(p0 + H);
                val.x = badd2(u.x, v.x); val.y = badd2(u.y, v.y);
                val.z = badd2(u.z, v.z); val.w = badd2(u.w, v.w);
            }
        }
        *(uint4*)&As[row * ALD + c * 4] = val;
    }
    __syncthreads();

    float acc[4][4][4];
    #pragma unroll
    for (int i = 0; i < 4; i++)
        #pragma unroll
        for (int j = 0; j < 4; j++)
            #pragma unroll
            for (int q = 0; q < 4; q++) acc[i][j][q] = 0.f;

    // ldmatrix lane addresses
    const uint32_t sA = (uint32_t)__cvta_generic_to_shared(As);
    const uint32_t sB = (uint32_t)__cvta_generic_to_shared(Bs);
    // A: lane -> row = mwbase + (lane&15), k-half = lane>>4
    const uint32_t aBase = sA + (uint32_t)(((mw * 64 + (lane & 15)) * ALD + (lane >> 4) * 4) << 2);
    // B: lane -> n-row = nwbase + (lane&7) + 8*(lane>>4), k-half = (lane>>3)&1
    const uint32_t bBase = sB + (uint32_t)(((nw * 32 + (lane & 7) + ((lane >> 4) << 3)) * BLD) << 2)
                              + (uint32_t)(((lane >> 3) & 1) << 4);

    #pragma unroll
    for (int kb = 0; kb < 8; kb++) {
        uint32_t bf[4][2];
        ldsm_x4(bf[0][0], bf[0][1], bf[1][0], bf[1][1], bBase + kb * 32);
        ldsm_x4(bf[2][0], bf[2][1], bf[3][0], bf[3][1], bBase + 16 * BLD * 4 + kb * 32);
        #pragma unroll
        for (int mf = 0; mf < 4; mf++) {
            uint32_t a0, a1, a2, a3;
            ldsm_x4(a0, a1, a2, a3, aBase + mf * (16 * ALD * 4) + kb * 32);
            #pragma unroll
            for (int nf = 0; nf < 4; nf++)
                mma_bf16(acc[mf][nf], a0, a1, a2, a3, bf[nf][0], bf[nf][1]);
        }
    }

    // ---- epilogue: packed bf16x2 stores ----
    #pragma unroll
    for (int mf = 0; mf < 4; mf++) {
        #pragma unroll
        for (int nf = 0; nf < 4; nf++) {
            int row = brow + mw * 64 + mf * 16 + g;
            int col = bcol + nw * 32 + nf * 8 + 2 * t4;
            float b0 = 0.f, b1 = 0.f;
            if (BIAS) { b0 = bias[col]; b1 = bias[col + 1]; }
            if (row < M) {
                uint32_t* p = (uint32_t*)(C + (size_t)row * ldc + col);
                float v0 = acc[mf][nf][0] + b0;
                float v1 = acc[mf][nf][1] + b1;
                if (ACC) { uint32_t o = *p; v0 += bf_lo(o); v1 += bf_hi(o); }
                *p = f2b2(v0, v1);
            }
            if (row + 8 < M) {
                uint32_t* p = (uint32_t*)(C + (size_t)(row + 8) * ldc + col);
                float v0 = acc[mf][nf][2] + b0;
                float v1 = acc[mf][nf][3] + b1;
                if (ACC) { uint32_t o = *p; v0 += bf_lo(o); v1 += bf_hi(o); }
                *p = f2b2(v0, v1);
            }
        }
    }
}

// ---------------- one-shot x-GEMM over ALL nodes (leaf tiles skip f-gate) ----------------
__global__ void __launch_bounds__(256, 2) xgemm_mm(const int* __restrict__ words)
{
    extern __shared__ uint32_t smu[];
    uint32_t* As = smu;
    uint32_t* Bs = smu + A_U32;
    int bx = blockIdx.x, m, nt;
    if (bx < NITILE * 4) { m = bx >> 2; nt = bx & 3; }
    else { int r2 = bx - NITILE * 4; m = NITILE + r2 / 3; nt = r2 % 3; }
    gemm_tile<1, false, true>(As, Bs, g_embB, words, g_WxS + (size_t)nt * B_U32,
                              g_b2, g_XG, 512, NNODES, m * 128, nt * 128);
}

// ---------------- per-level h-GEMM (pairsum, acc) + f-GEMM fused launch ----------------
__global__ void __launch_bounds__(256, 2) level_mm(int n, int off, int chd)
{
    extern __shared__ uint32_t smu[];
    uint32_t* As = smu;
    uint32_t* Bs = smu + A_U32;
    const __nv_bfloat16* h_ch = g_hbuf[chd];
    int nbm = n >> 7;
    int bx = blockIdx.x;
    if (bx < nbm * 3) {
        int m = bx / 3, nt = bx % 3;
        gemm_tile<2, true, false>(As, Bs, h_ch, nullptr, g_WhS + (size_t)nt * B_U32, nullptr,
                                  g_XG + (size_t)off * 512, 512, n, m * 128, nt * 128);
    } else {
        int m = bx - nbm * 3;
        gemm_tile<0, false, true>(As, Bs, h_ch, nullptr, g_WfS, g_bfh,
                                  g_FH, 128, 2 * n, m * 128, 0);
    }
}

// ---------------- logits + log-softmax loss (per node, 128 threads) ----------------
__device__ __forceinline__ void logits_loss(
    float h, int k, int slot,
    const float* __restrict__ Wout, const float* __restrict__ bout,
    int label, float* __restrict__ logp_out)
{
    float p[NLABEL];
    #pragma unroll
    for (int l = 0; l < NLABEL; l++) p[l] = h * Wout[l * H + k];
    #pragma unroll
    for (int offx = 16; offx; offx >>= 1) {
        #pragma unroll
        for (int l = 0; l < NLABEL; l++)
            p[l] += __shfl_down_sync(0xffffffffu, p[l], offx);
    }
    __shared__ float sw[4][NLABEL];
    int wid = k >> 5, lane = k & 31;
    if (lane == 0) {
        #pragma unroll
        for (int l = 0; l < NLABEL; l++) sw[wid][l] = p[l];
    }
    __syncthreads();
    if (k == 0) {
        float lg[NLABEL], m = -1e30f;
        #pragma unroll
        for (int l = 0; l < NLABEL; l++) {
            lg[l] = sw[0][l] + sw[1][l] + sw[2][l] + sw[3][l] + bout[l];
            m = fmaxf(m, lg[l]);
        }
        float s = 0.f;
        #pragma unroll
        for (int l = 0; l < NLABEL; l++) s += expf(lg[l] - m);
        float lse = m + logf(s);
        atomicAdd(&g_loss[slot & 1023], (double)(lse - lg[label]));
        if (logp_out) {
            #pragma unroll
            for (int l = 0; l < NLABEL; l++) logp_out[l] = lg[l] - lse;
        }
    }
}

// ---------------- per-node gates + cell + loss (big levels) ----------------
__global__ void __launch_bounds__(128) node_update(
    int off, int cur, int chd, int isLeaf,
    const int* __restrict__ labels,
    const float* __restrict__ Wout, const float* __restrict__ bout,
    float* __restrict__ logp_out)
{
    const int j = blockIdx.x;
    const int k = threadIdx.x;
    const __nv_bfloat16* xg = g_XG + (size_t)(off + j) * 512;

    float gi = sigm(__bfloat162float(xg[k]));
    float go = sigm(__bfloat162float(xg[128 + k]));
    float gu = tanhf(__bfloat162float(xg[256 + k]));
    float c = gi * gu;
    if (!isLeaf) {
        float xf = __bfloat162float(xg[384 + k]);
        size_t c0 = (size_t)(2 * j) * H + k;
        c += sigm(xf + __bfloat162float(g_FH[c0]))     * g_cbuf[chd][c0]
           + sigm(xf + __bfloat162float(g_FH[c0 + H])) * g_cbuf[chd][c0 + H];
    }
    float h = go * tanhf(c);
    g_cbuf[cur][(size_t)j * H + k] = c;
    g_hbuf[cur][(size_t)j * H + k] = __float2bfloat16(h);

    logits_loss(h, k, off + j, Wout, bout, labels[j], logp_out);
}

// ---------------- fully fused small level (n <= 64): GEMV + gates + loss ----------------
__global__ void __launch_bounds__(128) small_level(
    int off, int cur, int chd,
    const int* __restrict__ labels,
    const float* __restrict__ Wout, const float* __restrict__ bout,
    float* __restrict__ logp_out)
{
    const int j = blockIdx.x;
    const int k = threadIdx.x;
    __shared__ float hs[H], h0s[H], h1s[H];

    size_t cb = (size_t)(2 * j) * H + k;
    float h0 = __bfloat162float(g_hbuf[chd][cb]);
    float h1 = __bfloat162float(g_hbuf[chd][cb + H]);
    h0s[k] = h0; h1s[k] = h1; hs[k] = h0 + h1;
    __syncthreads();

    const __nv_bfloat16* xg = g_XG + (size_t)(off + j) * 512;
    float ai = __bfloat162float(xg[k]);
    float ao = __bfloat162float(xg[128 + k]);
    float au = __bfloat162float(xg[256 + k]);
    float xf = __bfloat162float(xg[384 + k]);
    float f0 = g_bfh[k], f1 = g_bfh[k];
    #pragma unroll 8
    for (int d = 0; d < H; d++) {
        float hd = hs[d];
        ai += hd * g_WhT[d * 384 + k];
        ao += hd * g_WhT[d * 384 + 128 + k];
        au += hd * g_WhT[d * 384 + 256 + k];
        float w = g_WfhT[d * 128 + k];
        f0 += h0s[d] * w;
        f1 += h1s[d] * w;
    }
    float gi = sigm(ai), go = sigm(ao), gu = tanhf(au);
    float c = gi * gu + sigm(xf + f0) * g_cbuf[chd][cb]
                      + sigm(xf + f1) * g_cbuf[chd][cb + H];
    float h = go * tanhf(c);
    g_cbuf[cur][(size_t)j * H + k] = c;
    g_hbuf[cur][(size_t)j * H + k] = __float2bfloat16(h);

    logits_loss(h, k, off + j, Wout, bout, labels[j], logp_out);
}

// ---------------- loss reduction ----------------
__global__ void finalize_kernel(float* __restrict__ d_out, int out_size)
{
    __shared__ double s[256];
    int t = threadIdx.x;
    s[t] = g_loss[t] + g_loss[t + 256] + g_loss[t + 512] + g_loss[t + 768];
    __syncthreads();
    for (int offx = 128; offx; offx >>= 1) {
        if (t < offx) s[t] += s[t + offx];
        __syncthreads();
    }
    if (t == 0) {
        if (out_size >= NLABEL + 1) d_out[NLABEL] = (float)s[0];
        else                        d_out[0]      = (float)s[0];
    }
}

// ---------------- launch ----------------
extern "C" void kernel_launch(void* const* d_in, const int* in_sizes, int n_in,
                              void* d_out, int out_size)
{
    const float* embeds = (const float*)d_in[0];
    const int*   words  = (const int*)d_in[1];
    const int*   labels = (const int*)d_in[2];
    const float* Wix = (const float*)d_in[5];
    const float* bix = (const float*)d_in[6];
    const float* Wih = (const float*)d_in[7];
    const float* bih = (const float*)d_in[8];
    const float* Wfx = (const float*)d_in[9];
    const float* bfx = (const float*)d_in[10];
    const float* Wfh = (const float*)d_in[11];
    const float* bfh = (const float*)d_in[12];
    const float* Wox = (const float*)d_in[13];
    const float* box_ = (const float*)d_in[14];
    const float* Woh = (const float*)d_in[15];
    const float* boh = (const float*)d_in[16];
    const float* Wux = (const float*)d_in[17];
    const float* bux = (const float*)d_in[18];
    const float* Wuh = (const float*)d_in[19];
    const float* buh = (const float*)d_in[20];
    const float* Wout = (const float*)d_in[21];
    const float* bout = (const float*)d_in[22];
    float* out = (float*)d_out;

    cudaFuncSetAttribute(xgemm_mm, cudaFuncAttributeMaxDynamicSharedMemorySize, SMEM_DYN);
    cudaFuncSetAttribute(level_mm, cudaFuncAttributeMaxDynamicSharedMemorySize, SMEM_DYN);

    pack_kernel<<<256, 256>>>(Wix, Wox, Wux, Wfx, bix, box_, bux, bfx,
                              Wih, Woh, Wuh, Wfh, bih, boh, buh, bfh);
    conv_embeds<<<(VOCAB * 64 + 255) / 256, 256>>>(embeds);

    xgemm_mm<<<NITILE * 4 + (NMTILE - NITILE) * 3, 256, SMEM_DYN>>>(words);

    for (int l = DEPTH - 1; l >= 0; --l) {
        int n   = 1 << l;
        int off = n - 1;
        int cur = l & 1, chd = cur ^ 1;
        float* logp_dst = (l == 0 && out_size >= NLABEL + 1) ? out : nullptr;

        if (l == DEPTH - 1) {
            node_update<<<n, 128>>>(off, cur, chd, 1, labels + off, Wout, bout, nullptr);
        } else if (n >= 128) {
            int nbm = n >> 7;
            level_mm<<<nbm * 5, 256, SMEM_DYN>>>(n, off, chd);
            node_update<<<n, 128>>>(off, cur, chd, 0, labels + off, Wout, bout, logp_dst);
        } else {
            small_level<<<n, 128>>>(off, cur, chd, labels + off, Wout, bout, logp_dst);
        }
    }
    finalize_kernel<<<1, 256>>>(out, out_size);
}

// round 13
// speedup vs baseline: 5.2207x; 1.1896x over previous
#include <cuda_runtime.h>
#include <cuda_bf16.h>
#include <cstdint>

#define H 128
#define NLABEL 5
#define DEPTH 18
#define VOCAB 50000
#define NNODES ((1 << DEPTH) - 1)   /* 262143 */
#define NLEAF  (1 << (DEPTH - 1))   /* 131072 */
#define NITILE 1024                 /* m-tiles fully covering internal nodes */
#define NMTILE 2048                 /* ceil(NNODES/128) */

#define ALD 68                      /* u32 per A smem row (64 + 4 pad) */
#define BLD 68                      /* u32 per B smem n-row (64 + 4 pad) */
#define A_U32 (128 * ALD)           /* 8704 */
#define B_U32 (128 * BLD)           /* 8704 */
#define SMEM_DYN ((A_U32 + B_U32) * 4)        /* 69632 B */
#define SMEM_LG  ((A_U32 + 8 * BLD) * 4)      /* 36992 B */

// ---------------- device scratch (static, no allocation) ----------------
__device__ __align__(16) uint32_t g_WxS[4 * B_U32];   // gates i,o,u,f (n-major blobs)
__device__ __align__(16) uint32_t g_WhS[3 * B_U32];   // gates i,o,u
__device__ __align__(16) uint32_t g_WfS[B_U32];       // Wfh
__device__ __align__(16) uint32_t g_WoS[8 * BLD];     // Wout padded to 8 rows
__device__ __align__(16) uint32_t g_embB[(size_t)VOCAB * 64];  // bf16 embeds table
__device__ float g_WhT[H * 384];     // fp32 k-major for scalar small levels
__device__ float g_WfhT[H * H];
__device__ float g_b2[512];          // bix+bih, box+boh, bux+buh, bfx
__device__ float g_bfh[H];
__device__ float g_bo8[8];
__device__ __align__(16) __nv_bfloat16 g_XG[(size_t)NNODES * 512];  // preacts, bf16
__device__ __align__(16) __nv_bfloat16 g_FH[(size_t)NLEAF * H];     // f contributions
__device__ __align__(16) __nv_bfloat16 g_hAll[(size_t)NNODES * H];  // h for ALL nodes
__device__ float g_cbuf[2][(size_t)NLEAF * H];
__device__ float g_LG[(size_t)NNODES * 8];   // logits fp32 (cols 0..4 valid)
__device__ double g_loss[1024];

__device__ __forceinline__ float fsigm(float x) { return __fdividef(1.f, 1.f + __expf(-x)); }
__device__ __forceinline__ float ftanh(float x) {
    float r; asm("tanh.approx.f32 %0, %1;" : "=f"(r) : "f"(x)); return r;
}
__device__ __forceinline__ uint32_t f2b2(float lo, float hi) {
    __nv_bfloat162 r = __floats2bfloat162_rn(lo, hi);
    return *(uint32_t*)&r;
}
__device__ __forceinline__ uint32_t badd2(uint32_t a, uint32_t b) {
    __nv_bfloat162 r = __hadd2(*(__nv_bfloat162*)&a, *(__nv_bfloat162*)&b);
    return *(uint32_t*)&r;
}
__device__ __forceinline__ float bf_lo(uint32_t u) {
    return __bfloat162float(((__nv_bfloat162*)&u)->x);
}
__device__ __forceinline__ float bf_hi(uint32_t u) {
    return __bfloat162float(((__nv_bfloat162*)&u)->y);
}
__device__ __forceinline__ void mma_bf16(float c[4],
    uint32_t a0, uint32_t a1, uint32_t a2, uint32_t a3,
    uint32_t b0, uint32_t b1)
{
    asm volatile(
        "mma.sync.aligned.m16n8k16.row.col.f32.bf16.bf16.f32 "
        "{%0,%1,%2,%3},{%4,%5,%6,%7},{%8,%9},{%0,%1,%2,%3};"
        : "+f"(c[0]), "+f"(c[1]), "+f"(c[2]), "+f"(c[3])
        : "r"(a0), "r"(a1), "r"(a2), "r"(a3), "r"(b0), "r"(b1));
}
__device__ __forceinline__ void ldsm_x4(uint32_t& r0, uint32_t& r1,
                                        uint32_t& r2, uint32_t& r3, uint32_t addr)
{
    asm volatile("ldmatrix.sync.aligned.m8n8.x4.shared.b16 {%0,%1,%2,%3}, [%4];"
        : "=r"(r0), "=r"(r1), "=r"(r2), "=r"(r3) : "r"(addr));
}

// ---------------- embeds fp32 -> bf16 table ----------------
__global__ void conv_embeds(const float* __restrict__ e)
{
    int i = blockIdx.x * blockDim.x + threadIdx.x;
    if (i < VOCAB * 64) g_embB[i] = f2b2(e[2 * i], e[2 * i + 1]);
}

// ---------------- weight packing + loss zeroing ----------------
__global__ void pack_kernel(
    const float* __restrict__ Wix, const float* __restrict__ Wox,
    const float* __restrict__ Wux, const float* __restrict__ Wfx,
    const float* __restrict__ bix, const float* __restrict__ box_,
    const float* __restrict__ bux, const float* __restrict__ bfx,
    const float* __restrict__ Wih, const float* __restrict__ Woh,
    const float* __restrict__ Wuh, const float* __restrict__ Wfh,
    const float* __restrict__ bih, const float* __restrict__ boh,
    const float* __restrict__ buh, const float* __restrict__ bfh,
    const float* __restrict__ Wout, const float* __restrict__ bout)
{
    int idx = blockIdx.x * blockDim.x + threadIdx.x;
    if (idx < 4 * 128 * 64) {        // Wx blobs (n-major)
        int nt = idx >> 13, rem = idx & 8191, n = rem >> 6, kp = rem & 63;
        const float* W = (nt == 0) ? Wix : (nt == 1) ? Wox : (nt == 2) ? Wux : Wfx;
        g_WxS[(size_t)nt * B_U32 + n * BLD + kp] = f2b2(W[n * H + 2 * kp], W[n * H + 2 * kp + 1]);
    }
    if (idx < 3 * 128 * 64) {        // Wh blobs
        int nt = idx >> 13, rem = idx & 8191, n = rem >> 6, kp = rem & 63;
        const float* W = (nt == 0) ? Wih : (nt == 1) ? Woh : Wuh;
        g_WhS[(size_t)nt * B_U32 + n * BLD + kp] = f2b2(W[n * H + 2 * kp], W[n * H + 2 * kp + 1]);
    }
    if (idx < 128 * 64) {            // Wfh blob
        int n = idx >> 6, kp = idx & 63;
        g_WfS[n * BLD + kp] = f2b2(Wfh[n * H + 2 * kp], Wfh[n * H + 2 * kp + 1]);
    }
    if (idx < 8 * 64) {              // Wout blob (rows 5..7 zero)
        int n = idx >> 6, kp = idx & 63;
        g_WoS[n * BLD + kp] = (n < NLABEL)
            ? f2b2(Wout[n * H + 2 * kp], Wout[n * H + 2 * kp + 1]) : 0u;
    }
    if (idx < 8) g_bo8[idx] = (idx < NLABEL) ? bout[idx] : 0.f;
    if (idx < H * 384) {
        int d = idx / 384, c = idx % 384, g = c >> 7, r = c & 127;
        const float* W = (g == 0) ? Wih : (g == 1) ? Woh : Wuh;
        g_WhT[idx] = W[r * H + d];
    }
    if (idx < H * H) {
        int d = idx >> 7, r = idx & 127;
        g_WfhT[idx] = Wfh[r * H + d];
    }
    if (idx < 1024) g_loss[idx] = 0.0;
    if (idx < 512) {
        int g = idx >> 7, r = idx & 127;
        float v;
        if (g == 0) v = bix[r] + bih[r];
        else if (g == 1) v = box_[r] + boh[r];
        else if (g == 2) v = bux[r] + buh[r];
        else v = bfx[r];
        g_b2[idx] = v;
    }
    if (idx < H) g_bfh[idx] = bfh[idx];
}

// ---------------- bf16 MMA tile: C_bf16[128 x 128] = op(A) @ W^T (+bias) ----------------
// Single-stage full-K staging, one __syncthreads, 8 barrier-free K-chunks,
// ldmatrix fragment loads.
// MODE 0: A row m = hAll bf16 row m
// MODE 1: A row m = g_embB bf16 row ridx[m]  (gather)
// MODE 2: A row m = hAll[2m] + hAll[2m+1]    (bf16 pair sum)
template <int MODE, bool ACC, bool BIAS>
__device__ __forceinline__ void gemm_tile(
    uint32_t* As, uint32_t* Bs,
    const void* Av, const int* __restrict__ ridx,
    const uint32_t* __restrict__ Wblob, const float* __restrict__ bias,
    __nv_bfloat16* __restrict__ C, int ldc, int M, int brow, int bcol)
{
    const int t    = threadIdx.x;
    const int lane = t & 31;
    const int warp = t >> 5;
    const int mw   = warp & 1;
    const int nw   = warp >> 1;
    const int g    = lane >> 2;
    const int t4   = lane & 3;

    // ---- stage B: linear copy of pre-padded blob ----
    {
        const uint4* src = (const uint4*)Wblob;
        uint4* dst = (uint4*)Bs;
        #pragma unroll
        for (int i = 0; i < 9; i++) {
            int idx = t + i * 256;
            if (idx < B_U32 / 4) dst[idx] = src[idx];
        }
    }
    // ---- stage A: 2048 uint4, row-major padded ----
    #pragma unroll
    for (int i = 0; i < 8; i++) {
        int lin = t + i * 256;
        int row = lin >> 4;
        int c   = lin & 15;
        uint4 val = make_uint4(0u, 0u, 0u, 0u);
        if (brow + row < M) {
            if (MODE == 1) {
                val = ((const uint4*)Av)[(size_t)ridx[brow + row] * 16 + c];
            } else if (MODE == 0) {
                val = *(const uint4*)((const __nv_bfloat16*)Av + (size_t)(brow + row) * H + c * 8);
            } else {
                const __nv_bfloat16* p0 = (const __nv_bfloat16*)Av + (size_t)(2 * (brow + row)) * H + c * 8;
                uint4 u = *(const uint4*)p0;
                uint4 v = *(const uint4*)(p0 + H);
                val.x = badd2(u.x, v.x); val.y = badd2(u.y, v.y);
                val.z = badd2(u.z, v.z); val.w = badd2(u.w, v.w);
            }
        }
        *(uint4*)&As[row * ALD + c * 4] = val;
    }
    __syncthreads();

    float acc[4][4][4];
    #pragma unroll
    for (int i = 0; i < 4; i++)
        #pragma unroll
        for (int j = 0; j < 4; j++)
            #pragma unroll
            for (int q = 0; q < 4; q++) acc[i][j][q] = 0.f;

    const uint32_t sA = (uint32_t)__cvta_generic_to_shared(As);
    const uint32_t sB = (uint32_t)__cvta_generic_to_shared(Bs);
    const uint32_t aBase = sA + (uint32_t)(((mw * 64 + (lane & 15)) * ALD + (lane >> 4) * 4) << 2);
    const uint32_t bBase = sB + (uint32_t)(((nw * 32 + (lane & 7) + ((lane >> 4) << 3)) * BLD) << 2)
                              + (uint32_t)(((lane >> 3) & 1) << 4);

    #pragma unroll
    for (int kb = 0; kb < 8; kb++) {
        uint32_t bf[4][2];
        ldsm_x4(bf[0][0], bf[0][1], bf[1][0], bf[1][1], bBase + kb * 32);
        ldsm_x4(bf[2][0], bf[2][1], bf[3][0], bf[3][1], bBase + 16 * BLD * 4 + kb * 32);
        #pragma unroll
        for (int mf = 0; mf < 4; mf++) {
            uint32_t a0, a1, a2, a3;
            ldsm_x4(a0, a1, a2, a3, aBase + mf * (16 * ALD * 4) + kb * 32);
            #pragma unroll
            for (int nf = 0; nf < 4; nf++)
                mma_bf16(acc[mf][nf], a0, a1, a2, a3, bf[nf][0], bf[nf][1]);
        }
    }

    // ---- epilogue: packed bf16x2 stores ----
    #pragma unroll
    for (int mf = 0; mf < 4; mf++) {
        #pragma unroll
        for (int nf = 0; nf < 4; nf++) {
            int row = brow + mw * 64 + mf * 16 + g;
            int col = bcol + nw * 32 + nf * 8 + 2 * t4;
            float b0 = 0.f, b1 = 0.f;
            if (BIAS) { b0 = bias[col]; b1 = bias[col + 1]; }
            if (row < M) {
                uint32_t* p = (uint32_t*)(C + (size_t)row * ldc + col);
                float v0 = acc[mf][nf][0] + b0;
                float v1 = acc[mf][nf][1] + b1;
                if (ACC) { uint32_t o = *p; v0 += bf_lo(o); v1 += bf_hi(o); }
                *p = f2b2(v0, v1);
            }
            if (row + 8 < M) {
                uint32_t* p = (uint32_t*)(C + (size_t)(row + 8) * ldc + col);
                float v0 = acc[mf][nf][2] + b0;
                float v1 = acc[mf][nf][3] + b1;
                if (ACC) { uint32_t o = *p; v0 += bf_lo(o); v1 += bf_hi(o); }
                *p = f2b2(v0, v1);
            }
        }
    }
}

// ---------------- one-shot x-GEMM over ALL nodes (leaf tiles skip f-gate) ----------------
__global__ void __launch_bounds__(256, 2) xgemm_mm(const int* __restrict__ words)
{
    extern __shared__ uint32_t smu[];
    uint32_t* As = smu;
    uint32_t* Bs = smu + A_U32;
    int bx = blockIdx.x, m, nt;
    if (bx < NITILE * 4) { m = bx >> 2; nt = bx & 3; }
    else { int r2 = bx - NITILE * 4; m = NITILE + r2 / 3; nt = r2 % 3; }
    gemm_tile<1, false, true>(As, Bs, g_embB, words, g_WxS + (size_t)nt * B_U32,
                              g_b2, g_XG, 512, NNODES, m * 128, nt * 128);
}

// ---------------- per-level h-GEMM (pairsum, acc) + f-GEMM fused launch ----------------
__global__ void __launch_bounds__(256, 2) level_mm(int n, int off, int chd)
{
    extern __shared__ uint32_t smu[];
    uint32_t* As = smu;
    uint32_t* Bs = smu + A_U32;
    const __nv_bfloat16* h_ch = g_hAll + (size_t)(2 * n - 1) * H;
    int nbm = n >> 7;
    int bx = blockIdx.x;
    if (bx < nbm * 3) {
        int m = bx / 3, nt = bx % 3;
        gemm_tile<2, true, false>(As, Bs, h_ch, nullptr, g_WhS + (size_t)nt * B_U32, nullptr,
                                  g_XG + (size_t)off * 512, 512, n, m * 128, nt * 128);
    } else {
        int m = bx - nbm * 3;
        gemm_tile<0, false, true>(As, Bs, h_ch, nullptr, g_WfS, g_bfh,
                                  g_FH, 128, 2 * n, m * 128, 0);
    }
}

// ---------------- per-node gates + cell (big levels; pure elementwise) ----------------
__global__ void __launch_bounds__(128) node_update(int off, int cur, int chd, int isLeaf)
{
    const int j = blockIdx.x;
    const int k = threadIdx.x;
    const __nv_bfloat16* xg = g_XG + (size_t)(off + j) * 512;

    float gi = fsigm(__bfloat162float(xg[k]));
    float go = fsigm(__bfloat162float(xg[128 + k]));
    float gu = ftanh(__bfloat162float(xg[256 + k]));
    float c = gi * gu;
    if (!isLeaf) {
        float xf = __bfloat162float(xg[384 + k]);
        size_t c0 = (size_t)(2 * j) * H + k;
        c += fsigm(xf + __bfloat162float(g_FH[c0]))     * g_cbuf[chd][c0]
           + fsigm(xf + __bfloat162float(g_FH[c0 + H])) * g_cbuf[chd][c0 + H];
    }
    float h = go * ftanh(c);
    g_cbuf[cur][(size_t)j * H + k] = c;
    g_hAll[(size_t)(off + j) * H + k] = __float2bfloat16(h);
}

// ---------------- fully fused small level (n <= 64): GEMV + gates ----------------
__global__ void __launch_bounds__(128) small_level(int off, int cur, int chd)
{
    const int j = blockIdx.x;
    const int k = threadIdx.x;
    __shared__ float hs[H], h0s[H], h1s[H];

    const __nv_bfloat16* h_ch = g_hAll + (size_t)(2 * (off + j) + 1) * H;  /* children of node off+j */
    float h0 = __bfloat162float(h_ch[k]);
    float h1 = __bfloat162float(h_ch[H + k]);
    h0s[k] = h0; h1s[k] = h1; hs[k] = h0 + h1;
    __syncthreads();

    const __nv_bfloat16* xg = g_XG + (size_t)(off + j) * 512;
    float ai = __bfloat162float(xg[k]);
    float ao = __bfloat162float(xg[128 + k]);
    float au = __bfloat162float(xg[256 + k]);
    float xf = __bfloat162float(xg[384 + k]);
    float f0 = g_bfh[k], f1 = g_bfh[k];
    #pragma unroll 8
    for (int d = 0; d < H; d++) {
        float hd = hs[d];
        ai += hd * g_WhT[d * 384 + k];
        ao += hd * g_WhT[d * 384 + 128 + k];
        au += hd * g_WhT[d * 384 + 256 + k];
        float w = g_WfhT[d * 128 + k];
        f0 += h0s[d] * w;
        f1 += h1s[d] * w;
    }
    size_t cb = (size_t)(2 * j) * H + k;
    float gi = fsigm(ai), go = fsigm(ao), gu = ftanh(au);
    float c = gi * gu + fsigm(xf + f0) * g_cbuf[chd][cb]
                      + fsigm(xf + f1) * g_cbuf[chd][cb + H];
    float h = go * ftanh(c);
    g_cbuf[cur][(size_t)j * H + k] = c;
    g_hAll[(size_t)(off + j) * H + k] = __float2bfloat16(h);
}

// ---------------- one-shot logits GEMM: LG[N x 8] = hAll @ Wout^T + bout ----------------
__global__ void __launch_bounds__(256) lgits_mm()
{
    extern __shared__ uint32_t smu[];
    uint32_t* As = smu;           // 128 * ALD
    uint32_t* Bs = smu + A_U32;   // 8 * BLD
    const int t = threadIdx.x, lane = t & 31, w = t >> 5;
    const int brow = blockIdx.x * 128;

    if (t < 8 * BLD / 4) ((uint4*)Bs)[t] = ((const uint4*)g_WoS)[t];
    #pragma unroll
    for (int i = 0; i < 8; i++) {
        int lin = t + i * 256, row = lin >> 4, c = lin & 15;
        uint4 val = make_uint4(0u, 0u, 0u, 0u);
        if (brow + row < NNODES)
            val = *(const uint4*)(g_hAll + (size_t)(brow + row) * H + c * 8);
        *(uint4*)&As[row * ALD + c * 4] = val;
    }
    __syncthreads();

    float acc[4] = {0.f, 0.f, 0.f, 0.f};
    const uint32_t sA = (uint32_t)__cvta_generic_to_shared(As);
    const uint32_t sB = (uint32_t)__cvta_generic_to_shared(Bs);
    const uint32_t aBase = sA + (uint32_t)(((w * 16 + (lane & 15)) * ALD + (lane >> 4) * 4) << 2);
    const uint32_t bBase = sB + (uint32_t)(((lane & 7) * BLD) << 2)
                              + (uint32_t)(((lane >> 3) & 1) << 4);
    #pragma unroll
    for (int kb = 0; kb < 8; kb++) {
        uint32_t a0, a1, a2, a3, b0, b1;
        ldsm_x4(a0, a1, a2, a3, aBase + kb * 32);
        asm volatile("ldmatrix.sync.aligned.m8n8.x2.shared.b16 {%0,%1}, [%2];"
            : "=r"(b0), "=r"(b1) : "r"(bBase + kb * 32));
        mma_bf16(acc, a0, a1, a2, a3, b0, b1);
    }
    const int g = lane >> 2, t4 = lane & 3;
    const int row0 = brow + w * 16 + g;
    const int col = 2 * t4;
    if (row0 < NNODES) {
        float* p = g_LG + (size_t)row0 * 8 + col;
        p[0] = acc[0] + g_bo8[col]; p[1] = acc[1] + g_bo8[col + 1];
    }
    if (row0 + 8 < NNODES) {
        float* p = g_LG + (size_t)(row0 + 8) * 8 + col;
        p[0] = acc[2] + g_bo8[col]; p[1] = acc[3] + g_bo8[col + 1];
    }
}

// ---------------- flat loss over all nodes (+ root logp) ----------------
__global__ void loss_kernel(const int* __restrict__ labels,
                            float* __restrict__ out, int out_size)
{
    int idx = blockIdx.x * blockDim.x + threadIdx.x;
    if (idx >= NNODES) return;
    const float* lg = g_LG + (size_t)idx * 8;
    float l0 = lg[0], l1 = lg[1], l2 = lg[2], l3 = lg[3], l4 = lg[4];
    float m = fmaxf(fmaxf(fmaxf(l0, l1), fmaxf(l2, l3)), l4);
    float s = __expf(l0 - m) + __expf(l1 - m) + __expf(l2 - m)
            + __expf(l3 - m) + __expf(l4 - m);
    float lse = m + __logf(s);
    int lab = labels[idx];
    float lgl = (lab == 0) ? l0 : (lab == 1) ? l1 : (lab == 2) ? l2 : (lab == 3) ? l3 : l4;
    atomicAdd(&g_loss[idx & 1023], (double)(lse - lgl));
    if (idx == 0 && out_size >= NLABEL + 1) {
        out[0] = l0 - lse; out[1] = l1 - lse; out[2] = l2 - lse;
        out[3] = l3 - lse; out[4] = l4 - lse;
    }
}

// ---------------- loss reduction ----------------
__global__ void finalize_kernel(float* __restrict__ d_out, int out_size)
{
    __shared__ double s[256];
    int t = threadIdx.x;
    s[t] = g_loss[t] + g_loss[t + 256] + g_loss[t + 512] + g_loss[t + 768];
    __syncthreads();
    for (int offx = 128; offx; offx >>= 1) {
        if (t < offx) s[t] += s[t + offx];
        __syncthreads();
    }
    if (t == 0) {
        if (out_size >= NLABEL + 1) d_out[NLABEL] = (float)s[0];
        else                        d_out[0]      = (float)s[0];
    }
}

// ---------------- launch ----------------
extern "C" void kernel_launch(void* const* d_in, const int* in_sizes, int n_in,
                              void* d_out, int out_size)
{
    const float* embeds = (const float*)d_in[0];
    const int*   words  = (const int*)d_in[1];
    const int*   labels = (const int*)d_in[2];
    const float* Wix = (const float*)d_in[5];
    const float* bix = (const float*)d_in[6];
    const float* Wih = (const float*)d_in[7];
    const float* bih = (const float*)d_in[8];
    const float* Wfx = (const float*)d_in[9];
    const float* bfx = (const float*)d_in[10];
    const float* Wfh = (const float*)d_in[11];
    const float* bfh = (const float*)d_in[12];
    const float* Wox = (const float*)d_in[13];
    const float* box_ = (const float*)d_in[14];
    const float* Woh = (const float*)d_in[15];
    const float* boh = (const float*)d_in[16];
    const float* Wux = (const float*)d_in[17];
    const float* bux = (const float*)d_in[18];
    const float* Wuh = (const float*)d_in[19];
    const float* buh = (const float*)d_in[20];
    const float* Wout = (const float*)d_in[21];
    const float* bout = (const float*)d_in[22];
    float* out = (float*)d_out;

    cudaFuncSetAttribute(xgemm_mm, cudaFuncAttributeMaxDynamicSharedMemorySize, SMEM_DYN);
    cudaFuncSetAttribute(level_mm, cudaFuncAttributeMaxDynamicSharedMemorySize, SMEM_DYN);

    pack_kernel<<<256, 256>>>(Wix, Wox, Wux, Wfx, bix, box_, bux, bfx,
                              Wih, Woh, Wuh, Wfh, bih, boh, buh, bfh, Wout, bout);
    conv_embeds<<<(VOCAB * 64 + 255) / 256, 256>>>(embeds);

    xgemm_mm<<<NITILE * 4 + (NMTILE - NITILE) * 3, 256, SMEM_DYN>>>(words);

    for (int l = DEPTH - 1; l >= 0; --l) {
        int n   = 1 << l;
        int off = n - 1;
        int cur = l & 1, chd = cur ^ 1;

        if (l == DEPTH - 1) {
            node_update<<<n, 128>>>(off, cur, chd, 1);
        } else if (n >= 128) {
            int nbm = n >> 7;
            level_mm<<<nbm * 5, 256, SMEM_DYN>>>(n, off, chd);
            node_update<<<n, 128>>>(off, cur, chd, 0);
        } else {
            small_level<<<n, 128>>>(off, cur, chd);
        }
    }

    lgits_mm<<<NMTILE, 256, SMEM_LG>>>();
    loss_kernel<<<(NNODES + 255) / 256, 256>>>(labels, out, out_size);
    finalize_kernel<<<1, 256>>>(out, out_size);
}

// round 14
// speedup vs baseline: 5.2437x; 1.0044x over previous
#include <cuda_runtime.h>
#include <cuda_bf16.h>
#include <cuda_fp16.h>
#include <cstdint>

#define H 128
#define NLABEL 5
#define DEPTH 18
#define VOCAB 50000
#define NNODES ((1 << DEPTH) - 1)   /* 262143 */
#define NLEAF  (1 << (DEPTH - 1))   /* 131072 */
#define NITILE 1024                 /* m-tiles fully covering internal nodes */
#define NMTILE 2048                 /* ceil(NNODES/128) */

#define ALD 68                      /* u32 per A smem row (64 + 4 pad) */
#define BLD 68                      /* u32 per B smem n-row (64 + 4 pad) */
#define A_U32 (128 * ALD)           /* 8704 */
#define B_U32 (128 * BLD)           /* 8704 */
#define SMEM_DYN ((A_U32 + B_U32) * 4)        /* 69632 B */
#define SMEM_LG  ((A_U32 + 8 * BLD) * 4)      /* 36992 B */

// ---------------- device scratch (static, no allocation) ----------------
__device__ __align__(16) uint32_t g_WxS[4 * B_U32];   // gates i,o,u,f (n-major blobs)
__device__ __align__(16) uint32_t g_WhS[3 * B_U32];   // gates i,o,u
__device__ __align__(16) uint32_t g_WfS[B_U32];       // Wfh
__device__ __align__(16) uint32_t g_WoS[8 * BLD];     // Wout padded to 8 rows
__device__ __align__(16) uint32_t g_embB[(size_t)VOCAB * 64];  // bf16 embeds table
__device__ float g_WhT[H * 384];     // fp32 k-major for scalar small levels
__device__ float g_WfhT[H * H];
__device__ float g_b2[512];          // bix+bih, box+boh, bux+buh, bfx
__device__ float g_bfh[H];
__device__ float g_bo8[8];
__device__ __align__(16) __nv_bfloat16 g_XG[(size_t)NNODES * 512];  // preacts, bf16
__device__ __align__(16) __nv_bfloat16 g_FH[(size_t)NLEAF * H];     // f contributions
__device__ __align__(16) __nv_bfloat16 g_hAll[(size_t)NNODES * H];  // h for ALL nodes
__device__ __align__(16) __half g_cbuf[2][(size_t)NLEAF * H];       // cell state, fp16
__device__ float g_LG[(size_t)NNODES * 8];   // logits fp32 (cols 0..4 valid)
__device__ double g_loss[1024];
__device__ unsigned g_barCnt;
__device__ volatile unsigned g_barGen;

__device__ __forceinline__ float fsigm(float x) { return __fdividef(1.f, 1.f + __expf(-x)); }
__device__ __forceinline__ float ftanh(float x) {
    float r; asm("tanh.approx.f32 %0, %1;" : "=f"(r) : "f"(x)); return r;
}
__device__ __forceinline__ uint32_t f2b2(float lo, float hi) {
    __nv_bfloat162 r = __floats2bfloat162_rn(lo, hi);
    return *(uint32_t*)&r;
}
__device__ __forceinline__ uint32_t badd2(uint32_t a, uint32_t b) {
    __nv_bfloat162 r = __hadd2(*(__nv_bfloat162*)&a, *(__nv_bfloat162*)&b);
    return *(uint32_t*)&r;
}
__device__ __forceinline__ float bf_lo(uint32_t u) {
    return __bfloat162float(((__nv_bfloat162*)&u)->x);
}
__device__ __forceinline__ float bf_hi(uint32_t u) {
    return __bfloat162float(((__nv_bfloat162*)&u)->y);
}
__device__ __forceinline__ void mma_bf16(float c[4],
    uint32_t a0, uint32_t a1, uint32_t a2, uint32_t a3,
    uint32_t b0, uint32_t b1)
{
    asm volatile(
        "mma.sync.aligned.m16n8k16.row.col.f32.bf16.bf16.f32 "
        "{%0,%1,%2,%3},{%4,%5,%6,%7},{%8,%9},{%0,%1,%2,%3};"
        : "+f"(c[0]), "+f"(c[1]), "+f"(c[2]), "+f"(c[3])
        : "r"(a0), "r"(a1), "r"(a2), "r"(a3), "r"(b0), "r"(b1));
}
__device__ __forceinline__ void ldsm_x4(uint32_t& r0, uint32_t& r1,
                                        uint32_t& r2, uint32_t& r3, uint32_t addr)
{
    asm volatile("ldmatrix.sync.aligned.m8n8.x4.shared.b16 {%0,%1,%2,%3}, [%4];"
        : "=r"(r0), "=r"(r1), "=r"(r2), "=r"(r3) : "r"(addr));
}

// ---------------- embeds fp32 -> bf16 table ----------------
__global__ void conv_embeds(const float* __restrict__ e)
{
    int i = blockIdx.x * blockDim.x + threadIdx.x;
    if (i < VOCAB * 64) g_embB[i] = f2b2(e[2 * i], e[2 * i + 1]);
}

// ---------------- weight packing + loss zeroing ----------------
__global__ void pack_kernel(
    const float* __restrict__ Wix, const float* __restrict__ Wox,
    const float* __restrict__ Wux, const float* __restrict__ Wfx,
    const float* __restrict__ bix, const float* __restrict__ box_,
    const float* __restrict__ bux, const float* __restrict__ bfx,
    const float* __restrict__ Wih, const float* __restrict__ Woh,
    const float* __restrict__ Wuh, const float* __restrict__ Wfh,
    const float* __restrict__ bih, const float* __restrict__ boh,
    const float* __restrict__ buh, const float* __restrict__ bfh,
    const float* __restrict__ Wout, const float* __restrict__ bout)
{
    int idx = blockIdx.x * blockDim.x + threadIdx.x;
    if (idx < 4 * 128 * 64) {        // Wx blobs (n-major)
        int nt = idx >> 13, rem = idx & 8191, n = rem >> 6, kp = rem & 63;
        const float* W = (nt == 0) ? Wix : (nt == 1) ? Wox : (nt == 2) ? Wux : Wfx;
        g_WxS[(size_t)nt * B_U32 + n * BLD + kp] = f2b2(W[n * H + 2 * kp], W[n * H + 2 * kp + 1]);
    }
    if (idx < 3 * 128 * 64) {        // Wh blobs
        int nt = idx >> 13, rem = idx & 8191, n = rem >> 6, kp = rem & 63;
        const float* W = (nt == 0) ? Wih : (nt == 1) ? Woh : Wuh;
        g_WhS[(size_t)nt * B_U32 + n * BLD + kp] = f2b2(W[n * H + 2 * kp], W[n * H + 2 * kp + 1]);
    }
    if (idx < 128 * 64) {            // Wfh blob
        int n = idx >> 6, kp = idx & 63;
        g_WfS[n * BLD + kp] = f2b2(Wfh[n * H + 2 * kp], Wfh[n * H + 2 * kp + 1]);
    }
    if (idx < 8 * 64) {              // Wout blob (rows 5..7 zero)
        int n = idx >> 6, kp = idx & 63;
        g_WoS[n * BLD + kp] = (n < NLABEL)
            ? f2b2(Wout[n * H + 2 * kp], Wout[n * H + 2 * kp + 1]) : 0u;
    }
    if (idx < 8) g_bo8[idx] = (idx < NLABEL) ? bout[idx] : 0.f;
    if (idx == 0) { g_barCnt = 0; g_barGen = 0; }
    if (idx < H * 384) {
        int d = idx / 384, c = idx % 384, g = c >> 7, r = c & 127;
        const float* W = (g == 0) ? Wih : (g == 1) ? Woh : Wuh;
        g_WhT[idx] = W[r * H + d];
    }
    if (idx < H * H) {
        int d = idx >> 7, r = idx & 127;
        g_WfhT[idx] = Wfh[r * H + d];
    }
    if (idx < 1024) g_loss[idx] = 0.0;
    if (idx < 512) {
        int g = idx >> 7, r = idx & 127;
        float v;
        if (g == 0) v = bix[r] + bih[r];
        else if (g == 1) v = box_[r] + boh[r];
        else if (g == 2) v = bux[r] + buh[r];
        else v = bfx[r];
        g_b2[idx] = v;
    }
    if (idx < H) g_bfh[idx] = bfh[idx];
}

// ---------------- bf16 MMA tile: C_bf16[128 x 128] = op(A) @ W^T (+bias) ----------------
// Single-stage full-K staging, one __syncthreads, 8 barrier-free K-chunks,
// ldmatrix fragment loads.
// MODE 0: A row m = hAll bf16 row m
// MODE 1: A row m = g_embB bf16 row ridx[m]  (gather)
// MODE 2: A row m = hAll[2m] + hAll[2m+1]    (bf16 pair sum)
template <int MODE, bool ACC, bool BIAS>
__device__ __forceinline__ void gemm_tile(
    uint32_t* As, uint32_t* Bs,
    const void* Av, const int* __restrict__ ridx,
    const uint32_t* __restrict__ Wblob, const float* __restrict__ bias,
    __nv_bfloat16* __restrict__ C, int ldc, int M, int brow, int bcol)
{
    const int t    = threadIdx.x;
    const int lane = t & 31;
    const int warp = t >> 5;
    const int mw   = warp & 1;
    const int nw   = warp >> 1;
    const int g    = lane >> 2;
    const int t4   = lane & 3;

    // ---- stage B: linear copy of pre-padded blob ----
    {
        const uint4* src = (const uint4*)Wblob;
        uint4* dst = (uint4*)Bs;
        #pragma unroll
        for (int i = 0; i < 9; i++) {
            int idx = t + i * 256;
            if (idx < B_U32 / 4) dst[idx] = src[idx];
        }
    }
    // ---- stage A: 2048 uint4, row-major padded ----
    #pragma unroll
    for (int i = 0; i < 8; i++) {
        int lin = t + i * 256;
        int row = lin >> 4;
        int c   = lin & 15;
        uint4 val = make_uint4(0u, 0u, 0u, 0u);
        if (brow + row < M) {
            if (MODE == 1) {
                val = ((const uint4*)Av)[(size_t)ridx[brow + row] * 16 + c];
            } else if (MODE == 0) {
                val = *(const uint4*)((const __nv_bfloat16*)Av + (size_t)(brow + row) * H + c * 8);
            } else {
                const __nv_bfloat16* p0 = (const __nv_bfloat16*)Av + (size_t)(2 * (brow + row)) * H + c * 8;
                uint4 u = *(const uint4*)p0;
                uint4 v = *(const uint4*)(p0 + H);
                val.x = badd2(u.x, v.x); val.y = badd2(u.y, v.y);
                val.z = badd2(u.z, v.z); val.w = badd2(u.w, v.w);
            }
        }
        *(uint4*)&As[row * ALD + c * 4] = val;
    }
    __syncthreads();

    float acc[4][4][4];
    #pragma unroll
    for (int i = 0; i < 4; i++)
        #pragma unroll
        for (int j = 0; j < 4; j++)
            #pragma unroll
            for (int q = 0; q < 4; q++) acc[i][j][q] = 0.f;

    const uint32_t sA = (uint32_t)__cvta_generic_to_shared(As);
    const uint32_t sB = (uint32_t)__cvta_generic_to_shared(Bs);
    const uint32_t aBase = sA + (uint32_t)(((mw * 64 + (lane & 15)) * ALD + (lane >> 4) * 4) << 2);
    const uint32_t bBase = sB + (uint32_t)(((nw * 32 + (lane & 7) + ((lane >> 4) << 3)) * BLD) << 2)
                              + (uint32_t)(((lane >> 3) & 1) << 4);

    #pragma unroll
    for (int kb = 0; kb < 8; kb++) {
        uint32_t bf[4][2];
        ldsm_x4(bf[0][0], bf[0][1], bf[1][0], bf[1][1], bBase + kb * 32);
        ldsm_x4(bf[2][0], bf[2][1], bf[3][0], bf[3][1], bBase + 16 * BLD * 4 + kb * 32);
        #pragma unroll
        for (int mf = 0; mf < 4; mf++) {
            uint32_t a0, a1, a2, a3;
            ldsm_x4(a0, a1, a2, a3, aBase + mf * (16 * ALD * 4) + kb * 32);
            #pragma unroll
            for (int nf = 0; nf < 4; nf++)
                mma_bf16(acc[mf][nf], a0, a1, a2, a3, bf[nf][0], bf[nf][1]);
        }
    }

    // ---- epilogue: packed bf16x2 stores ----
    #pragma unroll
    for (int mf = 0; mf < 4; mf++) {
        #pragma unroll
        for (int nf = 0; nf < 4; nf++) {
            int row = brow + mw * 64 + mf * 16 + g;
            int col = bcol + nw * 32 + nf * 8 + 2 * t4;
            float b0 = 0.f, b1 = 0.f;
            if (BIAS) { b0 = bias[col]; b1 = bias[col + 1]; }
            if (row < M) {
                uint32_t* p = (uint32_t*)(C + (size_t)row * ldc + col);
                float v0 = acc[mf][nf][0] + b0;
                float v1 = acc[mf][nf][1] + b1;
                if (ACC) { uint32_t o = *p; v0 += bf_lo(o); v1 += bf_hi(o); }
                *p = f2b2(v0, v1);
            }
            if (row + 8 < M) {
                uint32_t* p = (uint32_t*)(C + (size_t)(row + 8) * ldc + col);
                float v0 = acc[mf][nf][2] + b0;
                float v1 = acc[mf][nf][3] + b1;
                if (ACC) { uint32_t o = *p; v0 += bf_lo(o); v1 += bf_hi(o); }
                *p = f2b2(v0, v1);
            }
        }
    }
}

// ---------------- one-shot x-GEMM over ALL nodes (leaf tiles skip f-gate) ----------------
__global__ void __launch_bounds__(256, 2) xgemm_mm(const int* __restrict__ words)
{
    extern __shared__ uint32_t smu[];
    uint32_t* As = smu;
    uint32_t* Bs = smu + A_U32;
    int bx = blockIdx.x, m, nt;
    if (bx < NITILE * 4) { m = bx >> 2; nt = bx & 3; }
    else { int r2 = bx - NITILE * 4; m = NITILE + r2 / 3; nt = r2 % 3; }
    gemm_tile<1, false, true>(As, Bs, g_embB, words, g_WxS + (size_t)nt * B_U32,
                              g_b2, g_XG, 512, NNODES, m * 128, nt * 128);
}

// ---------------- per-level h-GEMM (pairsum, acc) + f-GEMM fused launch ----------------
__global__ void __launch_bounds__(256, 2) level_mm(int n, int off, int chd)
{
    extern __shared__ uint32_t smu[];
    uint32_t* As = smu;
    uint32_t* Bs = smu + A_U32;
    const __nv_bfloat16* h_ch = g_hAll + (size_t)(2 * n - 1) * H;
    int nbm = n >> 7;
    int bx = blockIdx.x;
    if (bx < nbm * 3) {
        int m = bx / 3, nt = bx % 3;
        gemm_tile<2, true, false>(As, Bs, h_ch, nullptr, g_WhS + (size_t)nt * B_U32, nullptr,
                                  g_XG + (size_t)off * 512, 512, n, m * 128, nt * 128);
    } else {
        int m = bx - nbm * 3;
        gemm_tile<0, false, true>(As, Bs, h_ch, nullptr, g_WfS, g_bfh,
                                  g_FH, 128, 2 * n, m * 128, 0);
    }
}

// ---------------- per-node gates + cell (big levels; pure elementwise) ----------------
__global__ void __launch_bounds__(128) node_update(int off, int cur, int chd, int isLeaf)
{
    const int j = blockIdx.x;
    const int k = threadIdx.x;
    const __nv_bfloat16* xg = g_XG + (size_t)(off + j) * 512;

    float gi = fsigm(__bfloat162float(xg[k]));
    float go = fsigm(__bfloat162float(xg[128 + k]));
    float gu = ftanh(__bfloat162float(xg[256 + k]));
    float c = gi * gu;
    if (!isLeaf) {
        float xf = __bfloat162float(xg[384 + k]);
        size_t c0 = (size_t)(2 * j) * H + k;
        c += fsigm(xf + __bfloat162float(g_FH[c0]))     * __half2float(g_cbuf[chd][c0])
           + fsigm(xf + __bfloat162float(g_FH[c0 + H])) * __half2float(g_cbuf[chd][c0 + H]);
    }
    float h = go * ftanh(c);
    g_cbuf[cur][(size_t)j * H + k] = __float2half(c);
    g_hAll[(size_t)(off + j) * H + k] = __float2bfloat16(h);
}

// ---------------- fused small levels (l = 6..0, n = 64..1): one launch ----------------
// 64 blocks (co-resident on 148 SMs) with a generation-counting global barrier.
__global__ void __launch_bounds__(128) small_fused()
{
    const int j = blockIdx.x;
    const int k = threadIdx.x;
    __shared__ float hs[H], h0s[H], h1s[H];

    for (int l = 6; l >= 0; --l) {
        const int n = 1 << l;
        const int off = n - 1;
        const int cur = l & 1, chd = cur ^ 1;
        if (j < n) {
            const __nv_bfloat16* h_ch = g_hAll + (size_t)(2 * (off + j) + 1) * H;
            float h0 = __bfloat162float(h_ch[k]);
            float h1 = __bfloat162float(h_ch[H + k]);
            h0s[k] = h0; h1s[k] = h1; hs[k] = h0 + h1;
            __syncthreads();

            const __nv_bfloat16* xg = g_XG + (size_t)(off + j) * 512;
            float ai = __bfloat162float(xg[k]);
            float ao = __bfloat162float(xg[128 + k]);
            float au = __bfloat162float(xg[256 + k]);
            float xf = __bfloat162float(xg[384 + k]);
            float f0 = g_bfh[k], f1 = g_bfh[k];
            #pragma unroll 8
            for (int d = 0; d < H; d++) {
                float hd = hs[d];
                ai += hd * g_WhT[d * 384 + k];
                ao += hd * g_WhT[d * 384 + 128 + k];
                au += hd * g_WhT[d * 384 + 256 + k];
                float w = g_WfhT[d * 128 + k];
                f0 += h0s[d] * w;
                f1 += h1s[d] * w;
            }
            size_t cb = (size_t)(2 * j) * H + k;
            float gi = fsigm(ai), go = fsigm(ao), gu = ftanh(au);
            float c = gi * gu + fsigm(xf + f0) * __half2float(g_cbuf[chd][cb])
                              + fsigm(xf + f1) * __half2float(g_cbuf[chd][cb + H]);
            float h = go * ftanh(c);
            g_cbuf[cur][(size_t)j * H + k] = __float2half(c);
            g_hAll[(size_t)(off + j) * H + k] = __float2bfloat16(h);
            __syncthreads();   // hs reuse safety for next level
        }
        if (l == 0) break;
        // ---- global barrier across the 64 blocks ----
        __threadfence();
        __syncthreads();
        if (k == 0) {
            unsigned gen = g_barGen;
            if (atomicAdd(&g_barCnt, 1u) == 63u) {
                g_barCnt = 0u;
                __threadfence();
                g_barGen = gen + 1u;
            } else {
                while (g_barGen == gen) { }
            }
        }
        __syncthreads();
        __threadfence();
    }
}

// ---------------- one-shot logits GEMM: LG[N x 8] = hAll @ Wout^T + bout ----------------
__global__ void __launch_bounds__(256) lgits_mm()
{
    extern __shared__ uint32_t smu[];
    uint32_t* As = smu;           // 128 * ALD
    uint32_t* Bs = smu + A_U32;   // 8 * BLD
    const int t = threadIdx.x, lane = t & 31, w = t >> 5;
    const int brow = blockIdx.x * 128;

    if (t < 8 * BLD / 4) ((uint4*)Bs)[t] = ((const uint4*)g_WoS)[t];
    #pragma unroll
    for (int i = 0; i < 8; i++) {
        int lin = t + i * 256, row = lin >> 4, c = lin & 15;
        uint4 val = make_uint4(0u, 0u, 0u, 0u);
        if (brow + row < NNODES)
            val = *(const uint4*)(g_hAll + (size_t)(brow + row) * H + c * 8);
        *(uint4*)&As[row * ALD + c * 4] = val;
    }
    __syncthreads();

    float acc[4] = {0.f, 0.f, 0.f, 0.f};
    const uint32_t sA = (uint32_t)__cvta_generic_to_shared(As);
    const uint32_t sB = (uint32_t)__cvta_generic_to_shared(Bs);
    const uint32_t aBase = sA + (uint32_t)(((w * 16 + (lane & 15)) * ALD + (lane >> 4) * 4) << 2);
    const uint32_t bBase = sB + (uint32_t)(((lane & 7) * BLD) << 2)
                              + (uint32_t)(((lane >> 3) & 1) << 4);
    #pragma unroll
    for (int kb = 0; kb < 8; kb++) {
        uint32_t a0, a1, a2, a3, b0, b1;
        ldsm_x4(a0, a1, a2, a3, aBase + kb * 32);
        asm volatile("ldmatrix.sync.aligned.m8n8.x2.shared.b16 {%0,%1}, [%2];"
            : "=r"(b0), "=r"(b1) : "r"(bBase + kb * 32));
        mma_bf16(acc, a0, a1, a2, a3, b0, b1);
    }
    const int g = lane >> 2, t4 = lane & 3;
    const int row0 = brow + w * 16 + g;
    const int col = 2 * t4;
    if (row0 < NNODES) {
        float* p = g_LG + (size_t)row0 * 8 + col;
        p[0] = acc[0] + g_bo8[col]; p[1] = acc[1] + g_bo8[col + 1];
    }
    if (row0 + 8 < NNODES) {
        float* p = g_LG + (size_t)(row0 + 8) * 8 + col;
        p[0] = acc[2] + g_bo8[col]; p[1] = acc[3] + g_bo8[col + 1];
    }
}

// ---------------- flat loss over all nodes (+ root logp) ----------------
__global__ void loss_kernel(const int* __restrict__ labels,
                            float* __restrict__ out, int out_size)
{
    int idx = blockIdx.x * blockDim.x + threadIdx.x;
    if (idx >= NNODES) return;
    const float* lg = g_LG + (size_t)idx * 8;
    float l0 = lg[0], l1 = lg[1], l2 = lg[2], l3 = lg[3], l4 = lg[4];
    float m = fmaxf(fmaxf(fmaxf(l0, l1), fmaxf(l2, l3)), l4);
    float s = __expf(l0 - m) + __expf(l1 - m) + __expf(l2 - m)
            + __expf(l3 - m) + __expf(l4 - m);
    float lse = m + __logf(s);
    int lab = labels[idx];
    float lgl = (lab == 0) ? l0 : (lab == 1) ? l1 : (lab == 2) ? l2 : (lab == 3) ? l3 : l4;
    atomicAdd(&g_loss[idx & 1023], (double)(lse - lgl));
    if (idx == 0 && out_size >= NLABEL + 1) {
        out[0] = l0 - lse; out[1] = l1 - lse; out[2] = l2 - lse;
        out[3] = l3 - lse; out[4] = l4 - lse;
    }
}

// ---------------- loss reduction ----------------
__global__ void finalize_kernel(float* __restrict__ d_out, int out_size)
{
    __shared__ double s[256];
    int t = threadIdx.x;
    s[t] = g_loss[t] + g_loss[t + 256] + g_loss[t + 512] + g_loss[t + 768];
    __syncthreads();
    for (int offx = 128; offx; offx >>= 1) {
        if (t < offx) s[t] += s[t + offx];
        __syncthreads();
    }
    if (t == 0) {
        if (out_size >= NLABEL + 1) d_out[NLABEL] = (float)s[0];
        else                        d_out[0]      = (float)s[0];
    }
}

// ---------------- launch ----------------
extern "C" void kernel_launch(void* const* d_in, const int* in_sizes, int n_in,
                              void* d_out, int out_size)
{
    const float* embeds = (const float*)d_in[0];
    const int*   words  = (const int*)d_in[1];
    const int*   labels = (const int*)d_in[2];
    const float* Wix = (const float*)d_in[5];
    const float* bix = (const float*)d_in[6];
    const float* Wih = (const float*)d_in[7];
    const float* bih = (const float*)d_in[8];
    const float* Wfx = (const float*)d_in[9];
    const float* bfx = (const float*)d_in[10];
    const float* Wfh = (const float*)d_in[11];
    const float* bfh = (const float*)d_in[12];
    const float* Wox = (const float*)d_in[13];
    const float* box_ = (const float*)d_in[14];
    const float* Woh = (const float*)d_in[15];
    const float* boh = (const float*)d_in[16];
    const float* Wux = (const float*)d_in[17];
    const float* bux = (const float*)d_in[18];
    const float* Wuh = (const float*)d_in[19];
    const float* buh = (const float*)d_in[20];
    const float* Wout = (const float*)d_in[21];
    const float* bout = (const float*)d_in[22];
    float* out = (float*)d_out;

    cudaFuncSetAttribute(xgemm_mm, cudaFuncAttributeMaxDynamicSharedMemorySize, SMEM_DYN);
    cudaFuncSetAttribute(level_mm, cudaFuncAttributeMaxDynamicSharedMemorySize, SMEM_DYN);

    pack_kernel<<<256, 256>>>(Wix, Wox, Wux, Wfx, bix, box_, bux, bfx,
                              Wih, Woh, Wuh, Wfh, bih, boh, buh, bfh, Wout, bout);
    conv_embeds<<<(VOCAB * 64 + 255) / 256, 256>>>(embeds);

    xgemm_mm<<<NITILE * 4 + (NMTILE - NITILE) * 3, 256, SMEM_DYN>>>(words);

    for (int l = DEPTH - 1; l >= 7; --l) {
        int n   = 1 << l;
        int off = n - 1;
        int cur = l & 1, chd = cur ^ 1;

        if (l == DEPTH - 1) {
            node_update<<<n, 128>>>(off, cur, chd, 1);
        } else {
            int nbm = n >> 7;
            level_mm<<<nbm * 5, 256, SMEM_DYN>>>(n, off, chd);
            node_update<<<n, 128>>>(off, cur, chd, 0);
        }
    }
    small_fused<<<64, 128>>>();

    lgits_mm<<<NMTILE, 256, SMEM_LG>>>();
    loss_kernel<<<(NNODES + 255) / 256, 256>>>(labels, out, out_size);
    finalize_kernel<<<1, 256>>>(out, out_size);
}

// round 15
// speedup vs baseline: 5.8194x; 1.1098x over previous
#include <cuda_runtime.h>
#include <cuda_bf16.h>
#include <cuda_fp16.h>
#include <cstdint>

#define H 128
#define NLABEL 5
#define DEPTH 18
#define VOCAB 50000
#define NNODES ((1 << DEPTH) - 1)   /* 262143 */
#define NLEAF  (1 << (DEPTH - 1))   /* 131072 */
#define NITILE 1024                 /* m-tiles fully covering internal nodes */
#define NMTILE 2048                 /* ceil(NNODES/128) */

#define ALD 68                      /* u32 per A smem row (64 + 4 pad) */
#define BLD 68                      /* u32 per B smem n-row (64 + 4 pad) */
#define A_U32 (128 * ALD)           /* 8704 */
#define B_U32 (128 * BLD)           /* 8704 */
#define SMEM_DYN ((A_U32 + B_U32) * 4)        /* 69632 B */
#define SMEM_LG  ((A_U32 + 8 * BLD) * 4)      /* 36992 B */

// ---------------- device scratch (static, no allocation) ----------------
__device__ __align__(16) uint32_t g_WxS[4 * B_U32];   // gates i,o,u,f (n-major blobs)
__device__ __align__(16) uint32_t g_WhS[3 * B_U32];   // gates i,o,u
__device__ __align__(16) uint32_t g_WfS[B_U32];       // Wfh
__device__ __align__(16) uint32_t g_WoS[8 * BLD];     // Wout padded to 8 rows
__device__ __align__(16) uint32_t g_embB[(size_t)VOCAB * 64];  // bf16 embeds table
__device__ float g_WhT[H * 384];     // fp32 k-major for scalar small levels
__device__ float g_WfhT[H * H];
__device__ float g_b2[512];          // bix+bih, box+boh, bux+buh, bfx
__device__ float g_bfh[H];
__device__ float g_bo8[8];
__device__ __align__(16) __nv_bfloat16 g_XG[(size_t)NNODES * 512];  // preacts, bf16
__device__ __align__(16) __nv_bfloat16 g_FH[(size_t)NLEAF * H];     // f contributions
__device__ __align__(16) __nv_bfloat16 g_hAll[(size_t)NNODES * H];  // h for ALL nodes
__device__ __align__(16) __half g_cbuf[2][(size_t)NLEAF * H];       // cell state, fp16
__device__ float g_LG[(size_t)NNODES * 8];   // logits fp32 (cols 0..4 valid)
__device__ double g_loss[1024];
__device__ unsigned g_barCnt;
__device__ volatile unsigned g_barGen;

__device__ __forceinline__ float fsigm(float x) { return __fdividef(1.f, 1.f + __expf(-x)); }
__device__ __forceinline__ float ftanh(float x) {
    float r; asm("tanh.approx.f32 %0, %1;" : "=f"(r) : "f"(x)); return r;
}
__device__ __forceinline__ uint32_t f2b2(float lo, float hi) {
    __nv_bfloat162 r = __floats2bfloat162_rn(lo, hi);
    return *(uint32_t*)&r;
}
__device__ __forceinline__ uint32_t badd2(uint32_t a, uint32_t b) {
    __nv_bfloat162 r = __hadd2(*(__nv_bfloat162*)&a, *(__nv_bfloat162*)&b);
    return *(uint32_t*)&r;
}
__device__ __forceinline__ float bf_lo(uint32_t u) {
    return __bfloat162float(((__nv_bfloat162*)&u)->x);
}
__device__ __forceinline__ float bf_hi(uint32_t u) {
    return __bfloat162float(((__nv_bfloat162*)&u)->y);
}
__device__ __forceinline__ float hf_lo(uint32_t u) {
    return __half2float(((__half2*)&u)->x);
}
__device__ __forceinline__ float hf_hi(uint32_t u) {
    return __half2float(((__half2*)&u)->y);
}
__device__ __forceinline__ void unp8b(uint4 u, float* f) {
    f[0] = bf_lo(u.x); f[1] = bf_hi(u.x); f[2] = bf_lo(u.y); f[3] = bf_hi(u.y);
    f[4] = bf_lo(u.z); f[5] = bf_hi(u.z); f[6] = bf_lo(u.w); f[7] = bf_hi(u.w);
}
__device__ __forceinline__ void unp8h(uint4 u, float* f) {
    f[0] = hf_lo(u.x); f[1] = hf_hi(u.x); f[2] = hf_lo(u.y); f[3] = hf_hi(u.y);
    f[4] = hf_lo(u.z); f[5] = hf_hi(u.z); f[6] = hf_lo(u.w); f[7] = hf_hi(u.w);
}
__device__ __forceinline__ uint4 pack8b(const float* f) {
    return make_uint4(f2b2(f[0], f[1]), f2b2(f[2], f[3]),
                      f2b2(f[4], f[5]), f2b2(f[6], f[7]));
}
__device__ __forceinline__ uint32_t h2u(__half2 h) { return *(uint32_t*)&h; }
__device__ __forceinline__ uint4 pack8h(const float* f) {
    return make_uint4(h2u(__floats2half2_rn(f[0], f[1])), h2u(__floats2half2_rn(f[2], f[3])),
                      h2u(__floats2half2_rn(f[4], f[5])), h2u(__floats2half2_rn(f[6], f[7])));
}
__device__ __forceinline__ void mma_bf16(float c[4],
    uint32_t a0, uint32_t a1, uint32_t a2, uint32_t a3,
    uint32_t b0, uint32_t b1)
{
    asm volatile(
        "mma.sync.aligned.m16n8k16.row.col.f32.bf16.bf16.f32 "
        "{%0,%1,%2,%3},{%4,%5,%6,%7},{%8,%9},{%0,%1,%2,%3};"
        : "+f"(c[0]), "+f"(c[1]), "+f"(c[2]), "+f"(c[3])
        : "r"(a0), "r"(a1), "r"(a2), "r"(a3), "r"(b0), "r"(b1));
}
__device__ __forceinline__ void ldsm_x4(uint32_t& r0, uint32_t& r1,
                                        uint32_t& r2, uint32_t& r3, uint32_t addr)
{
    asm volatile("ldmatrix.sync.aligned.m8n8.x4.shared.b16 {%0,%1,%2,%3}, [%4];"
        : "=r"(r0), "=r"(r1), "=r"(r2), "=r"(r3) : "r"(addr));
}

// ---------------- embeds fp32 -> bf16 table (vectorized) ----------------
__global__ void conv_embeds(const float* __restrict__ e)
{
    int i = blockIdx.x * blockDim.x + threadIdx.x;
    if (i < VOCAB * 16) {
        float4 a = *(const float4*)(e + (size_t)i * 8);
        float4 b = *(const float4*)(e + (size_t)i * 8 + 4);
        ((uint4*)g_embB)[i] = make_uint4(f2b2(a.x, a.y), f2b2(a.z, a.w),
                                         f2b2(b.x, b.y), f2b2(b.z, b.w));
    }
}

// ---------------- weight packing + loss zeroing ----------------
__global__ void pack_kernel(
    const float* __restrict__ Wix, const float* __restrict__ Wox,
    const float* __restrict__ Wux, const float* __restrict__ Wfx,
    const float* __restrict__ bix, const float* __restrict__ box_,
    const float* __restrict__ bux, const float* __restrict__ bfx,
    const float* __restrict__ Wih, const float* __restrict__ Woh,
    const float* __restrict__ Wuh, const float* __restrict__ Wfh,
    const float* __restrict__ bih, const float* __restrict__ boh,
    const float* __restrict__ buh, const float* __restrict__ bfh,
    const float* __restrict__ Wout, const float* __restrict__ bout)
{
    int idx = blockIdx.x * blockDim.x + threadIdx.x;
    if (idx < 4 * 128 * 64) {        // Wx blobs (n-major)
        int nt = idx >> 13, rem = idx & 8191, n = rem >> 6, kp = rem & 63;
        const float* W = (nt == 0) ? Wix : (nt == 1) ? Wox : (nt == 2) ? Wux : Wfx;
        g_WxS[(size_t)nt * B_U32 + n * BLD + kp] = f2b2(W[n * H + 2 * kp], W[n * H + 2 * kp + 1]);
    }
    if (idx < 3 * 128 * 64) {        // Wh blobs
        int nt = idx >> 13, rem = idx & 8191, n = rem >> 6, kp = rem & 63;
        const float* W = (nt == 0) ? Wih : (nt == 1) ? Woh : Wuh;
        g_WhS[(size_t)nt * B_U32 + n * BLD + kp] = f2b2(W[n * H + 2 * kp], W[n * H + 2 * kp + 1]);
    }
    if (idx < 128 * 64) {            // Wfh blob
        int n = idx >> 6, kp = idx & 63;
        g_WfS[n * BLD + kp] = f2b2(Wfh[n * H + 2 * kp], Wfh[n * H + 2 * kp + 1]);
    }
    if (idx < 8 * 64) {              // Wout blob (rows 5..7 zero)
        int n = idx >> 6, kp = idx & 63;
        g_WoS[n * BLD + kp] = (n < NLABEL)
            ? f2b2(Wout[n * H + 2 * kp], Wout[n * H + 2 * kp + 1]) : 0u;
    }
    if (idx < 8) g_bo8[idx] = (idx < NLABEL) ? bout[idx] : 0.f;
    if (idx == 0) { g_barCnt = 0; g_barGen = 0; }
    if (idx < H * 384) {
        int d = idx / 384, c = idx % 384, g = c >> 7, r = c & 127;
        const float* W = (g == 0) ? Wih : (g == 1) ? Woh : Wuh;
        g_WhT[idx] = W[r * H + d];
    }
    if (idx < H * H) {
        int d = idx >> 7, r = idx & 127;
        g_WfhT[idx] = Wfh[r * H + d];
    }
    if (idx < 1024) g_loss[idx] = 0.0;
    if (idx < 512) {
        int g = idx >> 7, r = idx & 127;
        float v;
        if (g == 0) v = bix[r] + bih[r];
        else if (g == 1) v = box_[r] + boh[r];
        else if (g == 2) v = bux[r] + buh[r];
        else v = bfx[r];
        g_b2[idx] = v;
    }
    if (idx < H) g_bfh[idx] = bfh[idx];
}

// ---------------- bf16 MMA tile: C_bf16[128 x 128] = op(A) @ W^T (+bias) ----------------
// Single-stage full-K staging, one __syncthreads, 8 barrier-free K-chunks,
// ldmatrix fragment loads.
// MODE 0: A row m = hAll bf16 row m
// MODE 1: A row m = g_embB bf16 row ridx[m]  (gather)
// MODE 2: A row m = hAll[2m] + hAll[2m+1]    (bf16 pair sum)
template <int MODE, bool ACC, bool BIAS>
__device__ __forceinline__ void gemm_tile(
    uint32_t* As, uint32_t* Bs,
    const void* Av, const int* __restrict__ ridx,
    const uint32_t* __restrict__ Wblob, const float* __restrict__ bias,
    __nv_bfloat16* __restrict__ C, int ldc, int M, int brow, int bcol)
{
    const int t    = threadIdx.x;
    const int lane = t & 31;
    const int warp = t >> 5;
    const int mw   = warp & 1;
    const int nw   = warp >> 1;
    const int g    = lane >> 2;
    const int t4   = lane & 3;

    // ---- stage B: linear copy of pre-padded blob ----
    {
        const uint4* src = (const uint4*)Wblob;
        uint4* dst = (uint4*)Bs;
        #pragma unroll
        for (int i = 0; i < 9; i++) {
            int idx = t + i * 256;
            if (idx < B_U32 / 4) dst[idx] = src[idx];
        }
    }
    // ---- stage A: 2048 uint4, row-major padded ----
    #pragma unroll
    for (int i = 0; i < 8; i++) {
        int lin = t + i * 256;
        int row = lin >> 4;
        int c   = lin & 15;
        uint4 val = make_uint4(0u, 0u, 0u, 0u);
        if (brow + row < M) {
            if (MODE == 1) {
                val = ((const uint4*)Av)[(size_t)ridx[brow + row] * 16 + c];
            } else if (MODE == 0) {
                val = *(const uint4*)((const __nv_bfloat16*)Av + (size_t)(brow + row) * H + c * 8);
            } else {
                const __nv_bfloat16* p0 = (const __nv_bfloat16*)Av + (size_t)(2 * (brow + row)) * H + c * 8;
                uint4 u = *(const uint4*)p0;
                uint4 v = *(const uint4*)(p0 + H);
                val.x = badd2(u.x, v.x); val.y = badd2(u.y, v.y);
                val.z = badd2(u.z, v.z); val.w = badd2(u.w, v.w);
            }
        }
        *(uint4*)&As[row * ALD + c * 4] = val;
    }
    __syncthreads();

    float acc[4][4][4];
    #pragma unroll
    for (int i = 0; i < 4; i++)
        #pragma unroll
        for (int j = 0; j < 4; j++)
            #pragma unroll
            for (int q = 0; q < 4; q++) acc[i][j][q] = 0.f;

    const uint32_t sA = (uint32_t)__cvta_generic_to_shared(As);
    const uint32_t sB = (uint32_t)__cvta_generic_to_shared(Bs);
    const uint32_t aBase = sA + (uint32_t)(((mw * 64 + (lane & 15)) * ALD + (lane >> 4) * 4) << 2);
    const uint32_t bBase = sB + (uint32_t)(((nw * 32 + (lane & 7) + ((lane >> 4) << 3)) * BLD) << 2)
                              + (uint32_t)(((lane >> 3) & 1) << 4);

    #pragma unroll
    for (int kb = 0; kb < 8; kb++) {
        uint32_t bf[4][2];
        ldsm_x4(bf[0][0], bf[0][1], bf[1][0], bf[1][1], bBase + kb * 32);
        ldsm_x4(bf[2][0], bf[2][1], bf[3][0], bf[3][1], bBase + 16 * BLD * 4 + kb * 32);
        #pragma unroll
        for (int mf = 0; mf < 4; mf++) {
            uint32_t a0, a1, a2, a3;
            ldsm_x4(a0, a1, a2, a3, aBase + mf * (16 * ALD * 4) + kb * 32);
            #pragma unroll
            for (int nf = 0; nf < 4; nf++)
                mma_bf16(acc[mf][nf], a0, a1, a2, a3, bf[nf][0], bf[nf][1]);
        }
    }

    // ---- epilogue: packed bf16x2 stores ----
    #pragma unroll
    for (int mf = 0; mf < 4; mf++) {
        #pragma unroll
        for (int nf = 0; nf < 4; nf++) {
            int row = brow + mw * 64 + mf * 16 + g;
            int col = bcol + nw * 32 + nf * 8 + 2 * t4;
            float b0 = 0.f, b1 = 0.f;
            if (BIAS) { b0 = bias[col]; b1 = bias[col + 1]; }
            if (row < M) {
                uint32_t* p = (uint32_t*)(C + (size_t)row * ldc + col);
                float v0 = acc[mf][nf][0] + b0;
                float v1 = acc[mf][nf][1] + b1;
                if (ACC) { uint32_t o = *p; v0 += bf_lo(o); v1 += bf_hi(o); }
                *p = f2b2(v0, v1);
            }
            if (row + 8 < M) {
                uint32_t* p = (uint32_t*)(C + (size_t)(row + 8) * ldc + col);
                float v0 = acc[mf][nf][2] + b0;
                float v1 = acc[mf][nf][3] + b1;
                if (ACC) { uint32_t o = *p; v0 += bf_lo(o); v1 += bf_hi(o); }
                *p = f2b2(v0, v1);
            }
        }
    }
}

// ---------------- one-shot x-GEMM over ALL nodes (leaf tiles skip f-gate) ----------------
__global__ void __launch_bounds__(256, 2) xgemm_mm(const int* __restrict__ words)
{
    extern __shared__ uint32_t smu[];
    uint32_t* As = smu;
    uint32_t* Bs = smu + A_U32;
    int bx = blockIdx.x, m, nt;
    if (bx < NITILE * 4) { m = bx >> 2; nt = bx & 3; }
    else { int r2 = bx - NITILE * 4; m = NITILE + r2 / 3; nt = r2 % 3; }
    gemm_tile<1, false, true>(As, Bs, g_embB, words, g_WxS + (size_t)nt * B_U32,
                              g_b2, g_XG, 512, NNODES, m * 128, nt * 128);
}

// ---------------- per-level h-GEMM (pairsum, acc) + f-GEMM fused launch ----------------
__global__ void __launch_bounds__(256, 2) level_mm(int n, int off, int chd)
{
    extern __shared__ uint32_t smu[];
    uint32_t* As = smu;
    uint32_t* Bs = smu + A_U32;
    const __nv_bfloat16* h_ch = g_hAll + (size_t)(2 * n - 1) * H;
    int nbm = n >> 7;
    int bx = blockIdx.x;
    if (bx < nbm * 3) {
        int m = bx / 3, nt = bx % 3;
        gemm_tile<2, true, false>(As, Bs, h_ch, nullptr, g_WhS + (size_t)nt * B_U32, nullptr,
                                  g_XG + (size_t)off * 512, 512, n, m * 128, nt * 128);
    } else {
        int m = bx - nbm * 3;
        gemm_tile<0, false, true>(As, Bs, h_ch, nullptr, g_WfS, g_bfh,
                                  g_FH, 128, 2 * n, m * 128, 0);
    }
}

// ---------------- per-node gates + cell (vectorized: 8 elems/thread) ----------------
__global__ void __launch_bounds__(256) node_update(int off, int cur, int chd, int isLeaf, int n)
{
    int idx = blockIdx.x * blockDim.x + threadIdx.x;
    if (idx >= n * 16) return;
    const int j = idx >> 4;      // node within level
    const int q = idx & 15;      // uint4 slot (8 elems)

    const __nv_bfloat16* xg = g_XG + (size_t)(off + j) * 512 + q * 8;
    uint4 ui = *(const uint4*)xg;
    uint4 uo = *(const uint4*)(xg + 128);
    uint4 uu = *(const uint4*)(xg + 256);
    float xi[8], xo[8], xu[8], cc[8], hh[8];
    unp8b(ui, xi); unp8b(uo, xo); unp8b(uu, xu);
    #pragma unroll
    for (int e = 0; e < 8; e++) cc[e] = fsigm(xi[e]) * ftanh(xu[e]);

    if (!isLeaf) {
        uint4 uf = *(const uint4*)(xg + 384);
        const __nv_bfloat16* fh = g_FH + (size_t)(2 * j) * H + q * 8;
        uint4 f0u = *(const uint4*)fh;
        uint4 f1u = *(const uint4*)(fh + H);
        const __half* cb = g_cbuf[chd] + (size_t)(2 * j) * H + q * 8;
        uint4 c0u = *(const uint4*)cb;
        uint4 c1u = *(const uint4*)(cb + H);
        float xf[8], g0[8], g1[8], d0[8], d1[8];
        unp8b(uf, xf); unp8b(f0u, g0); unp8b(f1u, g1);
        unp8h(c0u, d0); unp8h(c1u, d1);
        #pragma unroll
        for (int e = 0; e < 8; e++)
            cc[e] += fsigm(xf[e] + g0[e]) * d0[e] + fsigm(xf[e] + g1[e]) * d1[e];
    }
    #pragma unroll
    for (int e = 0; e < 8; e++) hh[e] = fsigm(xo[e]) * ftanh(cc[e]);

    *(uint4*)(g_cbuf[cur] + (size_t)j * H + q * 8) = pack8h(cc);
    *(uint4*)(g_hAll + (size_t)(off + j) * H + q * 8) = pack8b(hh);
}

// ---------------- fused small levels (l = 6..0, n = 64..1): one launch ----------------
__global__ void __launch_bounds__(128) small_fused()
{
    const int j = blockIdx.x;
    const int k = threadIdx.x;
    __shared__ float hs[H], h0s[H], h1s[H];

    for (int l = 6; l >= 0; --l) {
        const int n = 1 << l;
        const int off = n - 1;
        const int cur = l & 1, chd = cur ^ 1;
        if (j < n) {
            const __nv_bfloat16* h_ch = g_hAll + (size_t)(2 * (off + j) + 1) * H;
            float h0 = __bfloat162float(h_ch[k]);
            float h1 = __bfloat162float(h_ch[H + k]);
            h0s[k] = h0; h1s[k] = h1; hs[k] = h0 + h1;
            __syncthreads();

            const __nv_bfloat16* xg = g_XG + (size_t)(off + j) * 512;
            float ai = __bfloat162float(xg[k]);
            float ao = __bfloat162float(xg[128 + k]);
            float au = __bfloat162float(xg[256 + k]);
            float xf = __bfloat162float(xg[384 + k]);
            float f0 = g_bfh[k], f1 = g_bfh[k];
            #pragma unroll 8
            for (int d = 0; d < H; d++) {
                float hd = hs[d];
                ai += hd * g_WhT[d * 384 + k];
                ao += hd * g_WhT[d * 384 + 128 + k];
                au += hd * g_WhT[d * 384 + 256 + k];
                float w = g_WfhT[d * 128 + k];
                f0 += h0s[d] * w;
                f1 += h1s[d] * w;
            }
            size_t cb = (size_t)(2 * j) * H + k;
            float gi = fsigm(ai), go = fsigm(ao), gu = ftanh(au);
            float c = gi * gu + fsigm(xf + f0) * __half2float(g_cbuf[chd][cb])
                              + fsigm(xf + f1) * __half2float(g_cbuf[chd][cb + H]);
            float h = go * ftanh(c);
            g_cbuf[cur][(size_t)j * H + k] = __float2half(c);
            g_hAll[(size_t)(off + j) * H + k] = __float2bfloat16(h);
            __syncthreads();
        }
        if (l == 0) break;
        __threadfence();
        __syncthreads();
        if (k == 0) {
            unsigned gen = g_barGen;
            if (atomicAdd(&g_barCnt, 1u) == 63u) {
                g_barCnt = 0u;
                __threadfence();
                g_barGen = gen + 1u;
            } else {
                while (g_barGen == gen) { }
            }
        }
        __syncthreads();
        __threadfence();
    }
}

// ---------------- one-shot logits GEMM: LG[N x 8] = hAll @ Wout^T + bout ----------------
__global__ void __launch_bounds__(256) lgits_mm()
{
    extern __shared__ uint32_t smu[];
    uint32_t* As = smu;           // 128 * ALD
    uint32_t* Bs = smu + A_U32;   // 8 * BLD
    const int t = threadIdx.x, lane = t & 31, w = t >> 5;
    const int brow = blockIdx.x * 128;

    if (t < 8 * BLD / 4) ((uint4*)Bs)[t] = ((const uint4*)g_WoS)[t];
    #pragma unroll
    for (int i = 0; i < 8; i++) {
        int lin = t + i * 256, row = lin >> 4, c = lin & 15;
        uint4 val = make_uint4(0u, 0u, 0u, 0u);
        if (brow + row < NNODES)
            val = *(const uint4*)(g_hAll + (size_t)(brow + row) * H + c * 8);
        *(uint4*)&As[row * ALD + c * 4] = val;
    }
    __syncthreads();

    float acc[4] = {0.f, 0.f, 0.f, 0.f};
    const uint32_t sA = (uint32_t)__cvta_generic_to_shared(As);
    const uint32_t sB = (uint32_t)__cvta_generic_to_shared(Bs);
    const uint32_t aBase = sA + (uint32_t)(((w * 16 + (lane & 15)) * ALD + (lane >> 4) * 4) << 2);
    const uint32_t bBase = sB + (uint32_t)(((lane & 7) * BLD) << 2)
                              + (uint32_t)(((lane >> 3) & 1) << 4);
    #pragma unroll
    for (int kb = 0; kb < 8; kb++) {
        uint32_t a0, a1, a2, a3, b0, b1;
        ldsm_x4(a0, a1, a2, a3, aBase + kb * 32);
        asm volatile("ldmatrix.sync.aligned.m8n8.x2.shared.b16 {%0,%1}, [%2];"
            : "=r"(b0), "=r"(b1) : "r"(bBase + kb * 32));
        mma_bf16(acc, a0, a1, a2, a3, b0, b1);
    }
    const int g = lane >> 2, t4 = lane & 3;
    const int row0 = brow + w * 16 + g;
    const int col = 2 * t4;
    if (row0 < NNODES) {
        float* p = g_LG + (size_t)row0 * 8 + col;
        p[0] = acc[0] + g_bo8[col]; p[1] = acc[1] + g_bo8[col + 1];
    }
    if (row0 + 8 < NNODES) {
        float* p = g_LG + (size_t)(row0 + 8) * 8 + col;
        p[0] = acc[2] + g_bo8[col]; p[1] = acc[3] + g_bo8[col + 1];
    }
}

// ---------------- flat loss over all nodes (+ root logp) ----------------
__global__ void loss_kernel(const int* __restrict__ labels,
                            float* __restrict__ out, int out_size)
{
    int idx = blockIdx.x * blockDim.x + threadIdx.x;
    if (idx >= NNODES) return;
    const float* lg = g_LG + (size_t)idx * 8;
    float l0 = lg[0], l1 = lg[1], l2 = lg[2], l3 = lg[3], l4 = lg[4];
    float m = fmaxf(fmaxf(fmaxf(l0, l1), fmaxf(l2, l3)), l4);
    float s = __expf(l0 - m) + __expf(l1 - m) + __expf(l2 - m)
            + __expf(l3 - m) + __expf(l4 - m);
    float lse = m + __logf(s);
    int lab = labels[idx];
    float lgl = (lab == 0) ? l0 : (lab == 1) ? l1 : (lab == 2) ? l2 : (lab == 3) ? l3 : l4;
    atomicAdd(&g_loss[idx & 1023], (double)(lse - lgl));
    if (idx == 0 && out_size >= NLABEL + 1) {
        out[0] = l0 - lse; out[1] = l1 - lse; out[2] = l2 - lse;
        out[3] = l3 - lse; out[4] = l4 - lse;
    }
}

// ---------------- loss reduction ----------------
__global__ void finalize_kernel(float* __restrict__ d_out, int out_size)
{
    __shared__ double s[256];
    int t = threadIdx.x;
    s[t] = g_loss[t] + g_loss[t + 256] + g_loss[t + 512] + g_loss[t + 768];
    __syncthreads();
    for (int offx = 128; offx; offx >>= 1) {
        if (t < offx) s[t] += s[t + offx];
        __syncthreads();
    }
    if (t == 0) {
        if (out_size >= NLABEL + 1) d_out[NLABEL] = (float)s[0];
        else                        d_out[0]      = (float)s[0];
    }
}

// ---------------- launch ----------------
extern "C" void kernel_launch(void* const* d_in, const int* in_sizes, int n_in,
                              void* d_out, int out_size)
{
    const float* embeds = (const float*)d_in[0];
    const int*   words  = (const int*)d_in[1];
    const int*   labels = (const int*)d_in[2];
    const float* Wix = (const float*)d_in[5];
    const float* bix = (const float*)d_in[6];
    const float* Wih = (const float*)d_in[7];
    const float* bih = (const float*)d_in[8];
    const float* Wfx = (const float*)d_in[9];
    const float* bfx = (const float*)d_in[10];
    const float* Wfh = (const float*)d_in[11];
    const float* bfh = (const float*)d_in[12];
    const float* Wox = (const float*)d_in[13];
    const float* box_ = (const float*)d_in[14];
    const float* Woh = (const float*)d_in[15];
    const float* boh = (const float*)d_in[16];
    const float* Wux = (const float*)d_in[17];
    const float* bux = (const float*)d_in[18];
    const float* Wuh = (const float*)d_in[19];
    const float* buh = (const float*)d_in[20];
    const float* Wout = (const float*)d_in[21];
    const float* bout = (const float*)d_in[22];
    float* out = (float*)d_out;

    cudaFuncSetAttribute(xgemm_mm, cudaFuncAttributeMaxDynamicSharedMemorySize, SMEM_DYN);
    cudaFuncSetAttribute(level_mm, cudaFuncAttributeMaxDynamicSharedMemorySize, SMEM_DYN);

    pack_kernel<<<256, 256>>>(Wix, Wox, Wux, Wfx, bix, box_, bux, bfx,
                              Wih, Woh, Wuh, Wfh, bih, boh, buh, bfh, Wout, bout);
    conv_embeds<<<(VOCAB * 16 + 255) / 256, 256>>>(embeds);

    xgemm_mm<<<NITILE * 4 + (NMTILE - NITILE) * 3, 256, SMEM_DYN>>>(words);

    for (int l = DEPTH - 1; l >= 7; --l) {
        int n   = 1 << l;
        int off = n - 1;
        int cur = l & 1, chd = cur ^ 1;

        if (l == DEPTH - 1) {
            node_update<<<(n * 16 + 255) / 256, 256>>>(off, cur, chd, 1, n);
        } else {
            int nbm = n >> 7;
            level_mm<<<nbm * 5, 256, SMEM_DYN>>>(n, off, chd);
            node_update<<<(n * 16 + 255) / 256, 256>>>(off, cur, chd, 0, n);
        }
    }
    small_fused<<<64, 128>>>();

    lgits_mm<<<NMTILE, 256, SMEM_LG>>>();
    loss_kernel<<<(NNODES + 255) / 256, 256>>>(labels, out, out_size);
    finalize_kernel<<<1, 256>>>(out, out_size);
}

// round 16
// speedup vs baseline: 6.0822x; 1.0452x over previous
#include <cuda_runtime.h>
#include <cuda_bf16.h>
#include <cuda_fp16.h>
#include <cstdint>

#define H 128
#define NLABEL 5
#define DEPTH 18
#define VOCAB 50000
#define NNODES ((1 << DEPTH) - 1)   /* 262143 */
#define NLEAF  (1 << (DEPTH - 1))   /* 131072 */
#define NMTILE 2048                 /* ceil(NNODES/128) */

#define ALD 68
#define BLD 68
#define A_U32 (128 * ALD)
#define B_U32 (128 * BLD)
#define SMEM_DYN ((A_U32 + B_U32) * 4)        /* 69632 B */

// grid split constants
#define XG1_MT0   511                          /* first xgemm: m-tiles 511..2047 */
#define XG1_N4    513                          /* tiles 511..1023: 4 gate tiles  */
#define XG1_BLKS  (XG1_N4 * 4 + 1024 * 3)      /* 5124 */
#define MID_XG    (XG1_MT0 * 4)                /* 2044: m-tiles 0..510, 4 nt */
#define L16_N     65536
#define L16_OFF   65535
#define L16_BLKS  2560                         /* 512*3 h + 1024 f */
#define MID_L16_END (MID_XG + L16_BLKS)        /* 4604 */
#define MID_BLKS  (MID_L16_END + 1024)         /* 5628: + leaf lgits tiles */

// ---------------- device scratch (static, no allocation) ----------------
__device__ __align__(16) uint32_t g_WxS[4 * B_U32];
__device__ __align__(16) uint32_t g_WhS[3 * B_U32];
__device__ __align__(16) uint32_t g_WfS[B_U32];
__device__ __align__(16) uint32_t g_WoS[8 * BLD];
__device__ __align__(16) uint32_t g_embB[(size_t)VOCAB * 64];
__device__ float g_WhT[H * 384];
__device__ float g_WfhT[H * H];
__device__ float g_b2[512];
__device__ float g_bfh[H];
__device__ float g_bo8[8];
__device__ __align__(16) __nv_bfloat16 g_XG[(size_t)NNODES * 512];
__device__ __align__(16) __nv_bfloat16 g_FH[(size_t)NLEAF * H];
__device__ __align__(16) __nv_bfloat16 g_hAll[(size_t)NNODES * H];
__device__ __align__(16) __half g_cbuf[2][(size_t)NLEAF * H];
__device__ float g_LG[(size_t)NNODES * 8];
__device__ double g_loss[1024];
__device__ unsigned g_barCnt;
__device__ volatile unsigned g_barGen;

__device__ __forceinline__ float fsigm(float x) { return __fdividef(1.f, 1.f + __expf(-x)); }
__device__ __forceinline__ float ftanh(float x) {
    float r; asm("tanh.approx.f32 %0, %1;" : "=f"(r) : "f"(x)); return r;
}
__device__ __forceinline__ uint32_t f2b2(float lo, float hi) {
    __nv_bfloat162 r = __floats2bfloat162_rn(lo, hi);
    return *(uint32_t*)&r;
}
__device__ __forceinline__ uint32_t badd2(uint32_t a, uint32_t b) {
    __nv_bfloat162 r = __hadd2(*(__nv_bfloat162*)&a, *(__nv_bfloat162*)&b);
    return *(uint32_t*)&r;
}
__device__ __forceinline__ float bf_lo(uint32_t u) { return __bfloat162float(((__nv_bfloat162*)&u)->x); }
__device__ __forceinline__ float bf_hi(uint32_t u) { return __bfloat162float(((__nv_bfloat162*)&u)->y); }
__device__ __forceinline__ float hf_lo(uint32_t u) { return __half2float(((__half2*)&u)->x); }
__device__ __forceinline__ float hf_hi(uint32_t u) { return __half2float(((__half2*)&u)->y); }
__device__ __forceinline__ void unp8b(uint4 u, float* f) {
    f[0] = bf_lo(u.x); f[1] = bf_hi(u.x); f[2] = bf_lo(u.y); f[3] = bf_hi(u.y);
    f[4] = bf_lo(u.z); f[5] = bf_hi(u.z); f[6] = bf_lo(u.w); f[7] = bf_hi(u.w);
}
__device__ __forceinline__ void unp8h(uint4 u, float* f) {
    f[0] = hf_lo(u.x); f[1] = hf_hi(u.x); f[2] = hf_lo(u.y); f[3] = hf_hi(u.y);
    f[4] = hf_lo(u.z); f[5] = hf_hi(u.z); f[6] = hf_lo(u.w); f[7] = hf_hi(u.w);
}
__device__ __forceinline__ uint4 pack8b(const float* f) {
    return make_uint4(f2b2(f[0], f[1]), f2b2(f[2], f[3]), f2b2(f[4], f[5]), f2b2(f[6], f[7]));
}
__device__ __forceinline__ uint32_t h2u(__half2 h) { return *(uint32_t*)&h; }
__device__ __forceinline__ uint4 pack8h(const float* f) {
    return make_uint4(h2u(__floats2half2_rn(f[0], f[1])), h2u(__floats2half2_rn(f[2], f[3])),
                      h2u(__floats2half2_rn(f[4], f[5])), h2u(__floats2half2_rn(f[6], f[7])));
}
__device__ __forceinline__ void mma_bf16(float c[4],
    uint32_t a0, uint32_t a1, uint32_t a2, uint32_t a3, uint32_t b0, uint32_t b1)
{
    asm volatile(
        "mma.sync.aligned.m16n8k16.row.col.f32.bf16.bf16.f32 "
        "{%0,%1,%2,%3},{%4,%5,%6,%7},{%8,%9},{%0,%1,%2,%3};"
        : "+f"(c[0]), "+f"(c[1]), "+f"(c[2]), "+f"(c[3])
        : "r"(a0), "r"(a1), "r"(a2), "r"(a3), "r"(b0), "r"(b1));
}
__device__ __forceinline__ void ldsm_x4(uint32_t& r0, uint32_t& r1,
                                        uint32_t& r2, uint32_t& r3, uint32_t addr)
{
    asm volatile("ldmatrix.sync.aligned.m8n8.x4.shared.b16 {%0,%1,%2,%3}, [%4];"
        : "=r"(r0), "=r"(r1), "=r"(r2), "=r"(r3) : "r"(addr));
}

// ---------------- embeds fp32 -> bf16 table ----------------
__global__ void conv_embeds(const float* __restrict__ e)
{
    int i = blockIdx.x * blockDim.x + threadIdx.x;
    if (i < VOCAB * 16) {
        float4 a = *(const float4*)(e + (size_t)i * 8);
        float4 b = *(const float4*)(e + (size_t)i * 8 + 4);
        ((uint4*)g_embB)[i] = make_uint4(f2b2(a.x, a.y), f2b2(a.z, a.w),
                                         f2b2(b.x, b.y), f2b2(b.z, b.w));
    }
}

// ---------------- weight packing + loss zeroing ----------------
__global__ void pack_kernel(
    const float* __restrict__ Wix, const float* __restrict__ Wox,
    const float* __restrict__ Wux, const float* __restrict__ Wfx,
    const float* __restrict__ bix, const float* __restrict__ box_,
    const float* __restrict__ bux, const float* __restrict__ bfx,
    const float* __restrict__ Wih, const float* __restrict__ Woh,
    const float* __restrict__ Wuh, const float* __restrict__ Wfh,
    const float* __restrict__ bih, const float* __restrict__ boh,
    const float* __restrict__ buh, const float* __restrict__ bfh,
    const float* __restrict__ Wout, const float* __restrict__ bout)
{
    int idx = blockIdx.x * blockDim.x + threadIdx.x;
    if (idx < 4 * 128 * 64) {
        int nt = idx >> 13, rem = idx & 8191, n = rem >> 6, kp = rem & 63;
        const float* W = (nt == 0) ? Wix : (nt == 1) ? Wox : (nt == 2) ? Wux : Wfx;
        g_WxS[(size_t)nt * B_U32 + n * BLD + kp] = f2b2(W[n * H + 2 * kp], W[n * H + 2 * kp + 1]);
    }
    if (idx < 3 * 128 * 64) {
        int nt = idx >> 13, rem = idx & 8191, n = rem >> 6, kp = rem & 63;
        const float* W = (nt == 0) ? Wih : (nt == 1) ? Woh : Wuh;
        g_WhS[(size_t)nt * B_U32 + n * BLD + kp] = f2b2(W[n * H + 2 * kp], W[n * H + 2 * kp + 1]);
    }
    if (idx < 128 * 64) {
        int n = idx >> 6, kp = idx & 63;
        g_WfS[n * BLD + kp] = f2b2(Wfh[n * H + 2 * kp], Wfh[n * H + 2 * kp + 1]);
    }
    if (idx < 8 * 64) {
        int n = idx >> 6, kp = idx & 63;
        g_WoS[n * BLD + kp] = (n < NLABEL)
            ? f2b2(Wout[n * H + 2 * kp], Wout[n * H + 2 * kp + 1]) : 0u;
    }
    if (idx < 8) g_bo8[idx] = (idx < NLABEL) ? bout[idx] : 0.f;
    if (idx == 0) { g_barCnt = 0; g_barGen = 0; }
    if (idx < H * 384) {
        int d = idx / 384, c = idx % 384, g = c >> 7, r = c & 127;
        const float* W = (g == 0) ? Wih : (g == 1) ? Woh : Wuh;
        g_WhT[idx] = W[r * H + d];
    }
    if (idx < H * H) {
        int d = idx >> 7, r = idx & 127;
        g_WfhT[idx] = Wfh[r * H + d];
    }
    if (idx < 1024) g_loss[idx] = 0.0;
    if (idx < 512) {
        int g = idx >> 7, r = idx & 127;
        float v;
        if (g == 0) v = bix[r] + bih[r];
        else if (g == 1) v = box_[r] + boh[r];
        else if (g == 2) v = bux[r] + buh[r];
        else v = bfx[r];
        g_b2[idx] = v;
    }
    if (idx < H) g_bfh[idx] = bfh[idx];
}

// ---------------- bf16 MMA tile ----------------
template <int MODE, bool ACC, bool BIAS>
__device__ __forceinline__ void gemm_tile(
    uint32_t* As, uint32_t* Bs,
    const void* Av, const int* __restrict__ ridx,
    const uint32_t* __restrict__ Wblob, const float* __restrict__ bias,
    __nv_bfloat16* __restrict__ C, int ldc, int M, int brow, int bcol)
{
    const int t    = threadIdx.x;
    const int lane = t & 31;
    const int warp = t >> 5;
    const int mw   = warp & 1;
    const int nw   = warp >> 1;
    const int g    = lane >> 2;
    const int t4   = lane & 3;

    {
        const uint4* src = (const uint4*)Wblob;
        uint4* dst = (uint4*)Bs;
        #pragma unroll
        for (int i = 0; i < 9; i++) {
            int idx = t + i * 256;
            if (idx < B_U32 / 4) dst[idx] = src[idx];
        }
    }
    #pragma unroll
    for (int i = 0; i < 8; i++) {
        int lin = t + i * 256;
        int row = lin >> 4;
        int c   = lin & 15;
        uint4 val = make_uint4(0u, 0u, 0u, 0u);
        if (brow + row < M) {
            if (MODE == 1) {
                val = ((const uint4*)Av)[(size_t)ridx[brow + row] * 16 + c];
            } else if (MODE == 0) {
                val = *(const uint4*)((const __nv_bfloat16*)Av + (size_t)(brow + row) * H + c * 8);
            } else {
                const __nv_bfloat16* p0 = (const __nv_bfloat16*)Av + (size_t)(2 * (brow + row)) * H + c * 8;
                uint4 u = *(const uint4*)p0;
                uint4 v = *(const uint4*)(p0 + H);
                val.x = badd2(u.x, v.x); val.y = badd2(u.y, v.y);
                val.z = badd2(u.z, v.z); val.w = badd2(u.w, v.w);
            }
        }
        *(uint4*)&As[row * ALD + c * 4] = val;
    }
    __syncthreads();

    float acc[4][4][4];
    #pragma unroll
    for (int i = 0; i < 4; i++)
        #pragma unroll
        for (int j = 0; j < 4; j++)
            #pragma unroll
            for (int q = 0; q < 4; q++) acc[i][j][q] = 0.f;

    const uint32_t sA = (uint32_t)__cvta_generic_to_shared(As);
    const uint32_t sB = (uint32_t)__cvta_generic_to_shared(Bs);
    const uint32_t aBase = sA + (uint32_t)(((mw * 64 + (lane & 15)) * ALD + (lane >> 4) * 4) << 2);
    const uint32_t bBase = sB + (uint32_t)(((nw * 32 + (lane & 7) + ((lane >> 4) << 3)) * BLD) << 2)
                              + (uint32_t)(((lane >> 3) & 1) << 4);

    #pragma unroll
    for (int kb = 0; kb < 8; kb++) {
        uint32_t bf[4][2];
        ldsm_x4(bf[0][0], bf[0][1], bf[1][0], bf[1][1], bBase + kb * 32);
        ldsm_x4(bf[2][0], bf[2][1], bf[3][0], bf[3][1], bBase + 16 * BLD * 4 + kb * 32);
        #pragma unroll
        for (int mf = 0; mf < 4; mf++) {
            uint32_t a0, a1, a2, a3;
            ldsm_x4(a0, a1, a2, a3, aBase + mf * (16 * ALD * 4) + kb * 32);
            #pragma unroll
            for (int nf = 0; nf < 4; nf++)
                mma_bf16(acc[mf][nf], a0, a1, a2, a3, bf[nf][0], bf[nf][1]);
        }
    }

    #pragma unroll
    for (int mf = 0; mf < 4; mf++) {
        #pragma unroll
        for (int nf = 0; nf < 4; nf++) {
            int row = brow + mw * 64 + mf * 16 + g;
            int col = bcol + nw * 32 + nf * 8 + 2 * t4;
            float b0 = 0.f, b1 = 0.f;
            if (BIAS) { b0 = bias[col]; b1 = bias[col + 1]; }
            if (row < M) {
                uint32_t* p = (uint32_t*)(C + (size_t)row * ldc + col);
                float v0 = acc[mf][nf][0] + b0;
                float v1 = acc[mf][nf][1] + b1;
                if (ACC) { uint32_t o = *p; v0 += bf_lo(o); v1 += bf_hi(o); }
                *p = f2b2(v0, v1);
            }
            if (row + 8 < M) {
                uint32_t* p = (uint32_t*)(C + (size_t)(row + 8) * ldc + col);
                float v0 = acc[mf][nf][2] + b0;
                float v1 = acc[mf][nf][3] + b1;
                if (ACC) { uint32_t o = *p; v0 += bf_lo(o); v1 += bf_hi(o); }
                *p = f2b2(v0, v1);
            }
        }
    }
}

// ---------------- logits tile (LG[brow..brow+127][0..7] = h @ Wout^T + bout) ----------------
__device__ __forceinline__ void lgits_tile(uint32_t* As, uint32_t* Bs, int brow)
{
    const int t = threadIdx.x, lane = t & 31, w = t >> 5;
    if (t < 8 * BLD / 4) ((uint4*)Bs)[t] = ((const uint4*)g_WoS)[t];
    #pragma unroll
    for (int i = 0; i < 8; i++) {
        int lin = t + i * 256, row = lin >> 4, c = lin & 15;
        uint4 val = make_uint4(0u, 0u, 0u, 0u);
        if (brow + row < NNODES)
            val = *(const uint4*)(g_hAll + (size_t)(brow + row) * H + c * 8);
        *(uint4*)&As[row * ALD + c * 4] = val;
    }
    __syncthreads();

    float acc[4] = {0.f, 0.f, 0.f, 0.f};
    const uint32_t sA = (uint32_t)__cvta_generic_to_shared(As);
    const uint32_t sB = (uint32_t)__cvta_generic_to_shared(Bs);
    const uint32_t aBase = sA + (uint32_t)(((w * 16 + (lane & 15)) * ALD + (lane >> 4) * 4) << 2);
    const uint32_t bBase = sB + (uint32_t)(((lane & 7) * BLD) << 2)
                              + (uint32_t)(((lane >> 3) & 1) << 4);
    #pragma unroll
    for (int kb = 0; kb < 8; kb++) {
        uint32_t a0, a1, a2, a3, b0, b1;
        ldsm_x4(a0, a1, a2, a3, aBase + kb * 32);
        asm volatile("ldmatrix.sync.aligned.m8n8.x2.shared.b16 {%0,%1}, [%2];"
            : "=r"(b0), "=r"(b1) : "r"(bBase + kb * 32));
        mma_bf16(acc, a0, a1, a2, a3, b0, b1);
    }
    const int g = lane >> 2, t4 = lane & 3;
    const int row0 = brow + w * 16 + g;
    const int col = 2 * t4;
    if (row0 < NNODES) {
        float* p = g_LG + (size_t)row0 * 8 + col;
        p[0] = acc[0] + g_bo8[col]; p[1] = acc[1] + g_bo8[col + 1];
    }
    if (row0 + 8 < NNODES) {
        float* p = g_LG + (size_t)(row0 + 8) * 8 + col;
        p[0] = acc[2] + g_bo8[col]; p[1] = acc[3] + g_bo8[col + 1];
    }
}

// ---------------- xgemm phase 1: m-tiles 511..2047 (lvl15 boundary, lvl16, leaves) ----------------
__global__ void __launch_bounds__(256, 2) xgemm_mm(const int* __restrict__ words)
{
    extern __shared__ uint32_t smu[];
    uint32_t* As = smu;
    uint32_t* Bs = smu + A_U32;
    int bx = blockIdx.x, m, nt;
    if (bx < XG1_N4 * 4) { m = XG1_MT0 + (bx >> 2); nt = bx & 3; }
    else { int r2 = bx - XG1_N4 * 4; m = 1024 + r2 / 3; nt = r2 % 3; }
    gemm_tile<1, false, true>(As, Bs, g_embB, words, g_WxS + (size_t)nt * B_U32,
                              g_b2, g_XG, 512, NNODES, m * 128, nt * 128);
}

// ---------------- mid phase: xgemm tiles 0..510 + lvl16 h/f-GEMM + leaf logits ----------------
__global__ void __launch_bounds__(256, 2) mid_mm(const int* __restrict__ words)
{
    extern __shared__ uint32_t smu[];
    uint32_t* As = smu;
    uint32_t* Bs = smu + A_U32;
    int bx = blockIdx.x;
    if (bx < MID_XG) {
        int m = bx >> 2, nt = bx & 3;
        gemm_tile<1, false, true>(As, Bs, g_embB, words, g_WxS + (size_t)nt * B_U32,
                                  g_b2, g_XG, 512, NNODES, m * 128, nt * 128);
    } else if (bx < MID_L16_END) {
        int b2 = bx - MID_XG;
        const __nv_bfloat16* h_ch = g_hAll + (size_t)(2 * L16_N - 1) * H;
        if (b2 < 512 * 3) {
            int m = b2 / 3, nt = b2 % 3;
            gemm_tile<2, true, false>(As, Bs, h_ch, nullptr, g_WhS + (size_t)nt * B_U32, nullptr,
                                      g_XG + (size_t)L16_OFF * 512, 512, L16_N, m * 128, nt * 128);
        } else {
            int m = b2 - 512 * 3;
            gemm_tile<0, false, true>(As, Bs, h_ch, nullptr, g_WfS, g_bfh,
                                      g_FH, 128, 2 * L16_N, m * 128, 0);
        }
    } else {
        int m = 1024 + (bx - MID_L16_END);
        lgits_tile(As, Bs, m * 128);
    }
}

// ---------------- per-level h-GEMM (pairsum, acc) + f-GEMM fused launch ----------------
__global__ void __launch_bounds__(256, 2) level_mm(int n, int off, int chd)
{
    extern __shared__ uint32_t smu[];
    uint32_t* As = smu;
    uint32_t* Bs = smu + A_U32;
    const __nv_bfloat16* h_ch = g_hAll + (size_t)(2 * n - 1) * H;
    int nbm = n >> 7;
    int bx = blockIdx.x;
    if (bx < nbm * 3) {
        int m = bx / 3, nt = bx % 3;
        gemm_tile<2, true, false>(As, Bs, h_ch, nullptr, g_WhS + (size_t)nt * B_U32, nullptr,
                                  g_XG + (size_t)off * 512, 512, n, m * 128, nt * 128);
    } else {
        int m = bx - nbm * 3;
        gemm_tile<0, false, true>(As, Bs, h_ch, nullptr, g_WfS, g_bfh,
                                  g_FH, 128, 2 * n, m * 128, 0);
    }
}

// ---------------- per-node gates + cell (vectorized: 8 elems/thread) ----------------
__global__ void __launch_bounds__(256) node_update(int off, int cur, int chd, int isLeaf, int n)
{
    int idx = blockIdx.x * blockDim.x + threadIdx.x;
    if (idx >= n * 16) return;
    const int j = idx >> 4;
    const int q = idx & 15;

    const __nv_bfloat16* xg = g_XG + (size_t)(off + j) * 512 + q * 8;
    uint4 ui = *(const uint4*)xg;
    uint4 uo = *(const uint4*)(xg + 128);
    uint4 uu = *(const uint4*)(xg + 256);
    float xi[8], xo[8], xu[8], cc[8], hh[8];
    unp8b(ui, xi); unp8b(uo, xo); unp8b(uu, xu);
    #pragma unroll
    for (int e = 0; e < 8; e++) cc[e] = fsigm(xi[e]) * ftanh(xu[e]);

    if (!isLeaf) {
        uint4 uf = *(const uint4*)(xg + 384);
        const __nv_bfloat16* fh = g_FH + (size_t)(2 * j) * H + q * 8;
        uint4 f0u = *(const uint4*)fh;
        uint4 f1u = *(const uint4*)(fh + H);
        const __half* cb = g_cbuf[chd] + (size_t)(2 * j) * H + q * 8;
        uint4 c0u = *(const uint4*)cb;
        uint4 c1u = *(const uint4*)(cb + H);
        float xf[8], g0[8], g1[8], d0[8], d1[8];
        unp8b(uf, xf); unp8b(f0u, g0); unp8b(f1u, g1);
        unp8h(c0u, d0); unp8h(c1u, d1);
        #pragma unroll
        for (int e = 0; e < 8; e++)
            cc[e] += fsigm(xf[e] + g0[e]) * d0[e] + fsigm(xf[e] + g1[e]) * d1[e];
    }
    #pragma unroll
    for (int e = 0; e < 8; e++) hh[e] = fsigm(xo[e]) * ftanh(cc[e]);

    *(uint4*)(g_cbuf[cur] + (size_t)j * H + q * 8) = pack8h(cc);
    *(uint4*)(g_hAll + (size_t)(off + j) * H + q * 8) = pack8b(hh);
}

// ---------------- fused small levels (l = 6..0) ----------------
__global__ void __launch_bounds__(128) small_fused()
{
    const int j = blockIdx.x;
    const int k = threadIdx.x;
    __shared__ float hs[H], h0s[H], h1s[H];

    for (int l = 6; l >= 0; --l) {
        const int n = 1 << l;
        const int off = n - 1;
        const int cur = l & 1, chd = cur ^ 1;
        if (j < n) {
            const __nv_bfloat16* h_ch = g_hAll + (size_t)(2 * (off + j) + 1) * H;
            float h0 = __bfloat162float(h_ch[k]);
            float h1 = __bfloat162float(h_ch[H + k]);
            h0s[k] = h0; h1s[k] = h1; hs[k] = h0 + h1;
            __syncthreads();

            const __nv_bfloat16* xg = g_XG + (size_t)(off + j) * 512;
            float ai = __bfloat162float(xg[k]);
            float ao = __bfloat162float(xg[128 + k]);
            float au = __bfloat162float(xg[256 + k]);
            float xf = __bfloat162float(xg[384 + k]);
            float f0 = g_bfh[k], f1 = g_bfh[k];
            #pragma unroll 8
            for (int d = 0; d < H; d++) {
                float hd = hs[d];
                ai += hd * g_WhT[d * 384 + k];
                ao += hd * g_WhT[d * 384 + 128 + k];
                au += hd * g_WhT[d * 384 + 256 + k];
                float w = g_WfhT[d * 128 + k];
                f0 += h0s[d] * w;
                f1 += h1s[d] * w;
            }
            size_t cb = (size_t)(2 * j) * H + k;
            float gi = fsigm(ai), go = fsigm(ao), gu = ftanh(au);
            float c = gi * gu + fsigm(xf + f0) * __half2float(g_cbuf[chd][cb])
                              + fsigm(xf + f1) * __half2float(g_cbuf[chd][cb + H]);
            float h = go * ftanh(c);
            g_cbuf[cur][(size_t)j * H + k] = __float2half(c);
            g_hAll[(size_t)(off + j) * H + k] = __float2bfloat16(h);
            __syncthreads();
        }
        if (l == 0) break;
        __threadfence();
        __syncthreads();
        if (k == 0) {
            unsigned gen = g_barGen;
            if (atomicAdd(&g_barCnt, 1u) == 63u) {
                g_barCnt = 0u;
                __threadfence();
                g_barGen = gen + 1u;
            } else {
                while (g_barGen == gen) { }
            }
        }
        __syncthreads();
        __threadfence();
    }
}

// ---------------- final logits GEMM: internal nodes (m-tiles 0..1023) ----------------
__global__ void __launch_bounds__(256) lgits_mm()
{
    extern __shared__ uint32_t smu[];
    uint32_t* As = smu;
    uint32_t* Bs = smu + A_U32;
    lgits_tile(As, Bs, blockIdx.x * 128);
}

// ---------------- flat loss over all nodes (+ root logp) ----------------
__global__ void loss_kernel(const int* __restrict__ labels,
                            float* __restrict__ out, int out_size)
{
    int idx = blockIdx.x * blockDim.x + threadIdx.x;
    if (idx >= NNODES) return;
    const float* lg = g_LG + (size_t)idx * 8;
    float l0 = lg[0], l1 = lg[1], l2 = lg[2], l3 = lg[3], l4 = lg[4];
    float m = fmaxf(fmaxf(fmaxf(l0, l1), fmaxf(l2, l3)), l4);
    float s = __expf(l0 - m) + __expf(l1 - m) + __expf(l2 - m)
            + __expf(l3 - m) + __expf(l4 - m);
    float lse = m + __logf(s);
    int lab = labels[idx];
    float lgl = (lab == 0) ? l0 : (lab == 1) ? l1 : (lab == 2) ? l2 : (lab == 3) ? l3 : l4;
    atomicAdd(&g_loss[idx & 1023], (double)(lse - lgl));
    if (idx == 0 && out_size >= NLABEL + 1) {
        out[0] = l0 - lse; out[1] = l1 - lse; out[2] = l2 - lse;
        out[3] = l3 - lse; out[4] = l4 - lse;
    }
}

// ---------------- loss reduction ----------------
__global__ void finalize_kernel(float* __restrict__ d_out, int out_size)
{
    __shared__ double s[256];
    int t = threadIdx.x;
    s[t] = g_loss[t] + g_loss[t + 256] + g_loss[t + 512] + g_loss[t + 768];
    __syncthreads();
    for (int offx = 128; offx; offx >>= 1) {
        if (t < offx) s[t] += s[t + offx];
        __syncthreads();
    }
    if (t == 0) {
        if (out_size >= NLABEL + 1) d_out[NLABEL] = (float)s[0];
        else                        d_out[0]      = (float)s[0];
    }
}

// ---------------- launch ----------------
extern "C" void kernel_launch(void* const* d_in, const int* in_sizes, int n_in,
                              void* d_out, int out_size)
{
    const float* embeds = (const float*)d_in[0];
    const int*   words  = (const int*)d_in[1];
    const int*   labels = (const int*)d_in[2];
    const float* Wix = (const float*)d_in[5];
    const float* bix = (const float*)d_in[6];
    const float* Wih = (const float*)d_in[7];
    const float* bih = (const float*)d_in[8];
    const float* Wfx = (const float*)d_in[9];
    const float* bfx = (const float*)d_in[10];
    const float* Wfh = (const float*)d_in[11];
    const float* bfh = (const float*)d_in[12];
    const float* Wox = (const float*)d_in[13];
    const float* box_ = (const float*)d_in[14];
    const float* Woh = (const float*)d_in[15];
    const float* boh = (const float*)d_in[16];
    const float* Wux = (const float*)d_in[17];
    const float* bux = (const float*)d_in[18];
    const float* Wuh = (const float*)d_in[19];
    const float* buh = (const float*)d_in[20];
    const float* Wout = (const float*)d_in[21];
    const float* bout = (const float*)d_in[22];
    float* out = (float*)d_out;

    cudaFuncSetAttribute(xgemm_mm, cudaFuncAttributeMaxDynamicSharedMemorySize, SMEM_DYN);
    cudaFuncSetAttribute(mid_mm,   cudaFuncAttributeMaxDynamicSharedMemorySize, SMEM_DYN);
    cudaFuncSetAttribute(level_mm, cudaFuncAttributeMaxDynamicSharedMemorySize, SMEM_DYN);
    cudaFuncSetAttribute(lgits_mm, cudaFuncAttributeMaxDynamicSharedMemorySize, SMEM_DYN);

    pack_kernel<<<256, 256>>>(Wix, Wox, Wux, Wfx, bix, box_, bux, bfx,
                              Wih, Woh, Wuh, Wfh, bih, boh, buh, bfh, Wout, bout);
    conv_embeds<<<(VOCAB * 16 + 255) / 256, 256>>>(embeds);

    // phase 1: XG for rows 65408.. (lvl15 boundary tile, lvl16, leaves)
    xgemm_mm<<<XG1_BLKS, 256, SMEM_DYN>>>(words);
    // leaves (l=17): cur = 1
    node_update<<<(NLEAF * 16 + 255) / 256, 256>>>(NLEAF - 1, 1, 0, 1, NLEAF);
    // mid: XG rows 0..65407  +  lvl16 h/f-GEMM  +  leaf logits
    mid_mm<<<MID_BLKS, 256, SMEM_DYN>>>(words);
    // lvl16 node update (cur = 0, chd = 1)
    node_update<<<(L16_N * 16 + 255) / 256, 256>>>(L16_OFF, 0, 1, 0, L16_N);

    for (int l = 15; l >= 7; --l) {
        int n   = 1 << l;
        int off = n - 1;
        int cur = l & 1, chd = cur ^ 1;
        int nbm = n >> 7;
        level_mm<<<nbm * 5, 256, SMEM_DYN>>>(n, off, chd);
        node_update<<<(n * 16 + 255) / 256, 256>>>(off, cur, chd, 0, n);
    }
    small_fused<<<64, 128>>>();

    lgits_mm<<<1024, 256, SMEM_DYN>>>();
    loss_kernel<<<(NNODES + 255) / 256, 256>>>(labels, out, out_size);
    finalize_kernel<<<1, 256>>>(out, out_size);
}

// round 17
// speedup vs baseline: 6.1385x; 1.0093x over previous
#include <cuda_runtime.h>
#include <cuda_bf16.h>
#include <cuda_fp16.h>
#include <cstdint>

#define H 128
#define NLABEL 5
#define DEPTH 18
#define VOCAB 50000
#define NNODES ((1 << DEPTH) - 1)   /* 262143 */
#define NLEAF  (1 << (DEPTH - 1))   /* 131072 */
#define NMTILE 2048                 /* ceil(NNODES/128) */

#define ALD 68
#define BLD 68
#define A_U32 (128 * ALD)
#define B_U32 (128 * BLD)
#define SMEM_DYN ((A_U32 + B_U32) * 4)        /* 69632 B */

// grid split constants
#define XG1_MT0   511                          /* first xgemm: m-tiles 511..2047 */
#define XG1_N4    513                          /* tiles 511..1023: 4 gate tiles  */
#define XG1_BLKS  (XG1_N4 * 4 + 1024 * 3)      /* 5124 */
#define MID_XG    (XG1_MT0 * 4)                /* 2044: m-tiles 0..510, 4 nt */
#define L16_N     65536
#define L16_OFF   65535
#define L16_BLKS  2560                         /* 512*3 h + 1024 f */
#define MID_L16_END (MID_XG + L16_BLKS)        /* 4604 */
#define MID_BLKS  (MID_L16_END + 1024)         /* 5628: + leaf lgits tiles */

// ---------------- device scratch (static, no allocation) ----------------
__device__ __align__(16) uint32_t g_WxS[4 * B_U32];
__device__ __align__(16) uint32_t g_WhS[3 * B_U32];
__device__ __align__(16) uint32_t g_WfS[B_U32];
__device__ __align__(16) uint32_t g_WoS[8 * BLD];
__device__ __align__(16) uint32_t g_embB[(size_t)VOCAB * 64];
__device__ float g_WhT[H * 384];
__device__ float g_WfhT[H * H];
__device__ float g_b2[512];
__device__ float g_bfh[H];
__device__ float g_bo8[8];
__device__ __align__(16) __nv_bfloat16 g_XG[(size_t)NNODES * 512];
__device__ __align__(16) __nv_bfloat16 g_FH[(size_t)NLEAF * H];
__device__ __align__(16) __nv_bfloat16 g_hAll[(size_t)NNODES * H];
__device__ __align__(16) __half g_cbuf[2][(size_t)NLEAF * H];
__device__ float g_LG[(size_t)NNODES * 8];
__device__ double g_loss[1024];
__device__ unsigned g_barCnt;
__device__ volatile unsigned g_barGen;

__device__ __forceinline__ float fsigm(float x) { return __fdividef(1.f, 1.f + __expf(-x)); }
__device__ __forceinline__ float ftanh(float x) {
    float r; asm("tanh.approx.f32 %0, %1;" : "=f"(r) : "f"(x)); return r;
}
__device__ __forceinline__ uint32_t f2b2(float lo, float hi) {
    __nv_bfloat162 r = __floats2bfloat162_rn(lo, hi);
    return *(uint32_t*)&r;
}
__device__ __forceinline__ uint32_t badd2(uint32_t a, uint32_t b) {
    __nv_bfloat162 r = __hadd2(*(__nv_bfloat162*)&a, *(__nv_bfloat162*)&b);
    return *(uint32_t*)&r;
}
__device__ __forceinline__ float bf_lo(uint32_t u) { return __bfloat162float(((__nv_bfloat162*)&u)->x); }
__device__ __forceinline__ float bf_hi(uint32_t u) { return __bfloat162float(((__nv_bfloat162*)&u)->y); }
__device__ __forceinline__ float hf_lo(uint32_t u) { return __half2float(((__half2*)&u)->x); }
__device__ __forceinline__ float hf_hi(uint32_t u) { return __half2float(((__half2*)&u)->y); }
__device__ __forceinline__ void unp8b(uint4 u, float* f) {
    f[0] = bf_lo(u.x); f[1] = bf_hi(u.x); f[2] = bf_lo(u.y); f[3] = bf_hi(u.y);
    f[4] = bf_lo(u.z); f[5] = bf_hi(u.z); f[6] = bf_lo(u.w); f[7] = bf_hi(u.w);
}
__device__ __forceinline__ void unp8h(uint4 u, float* f) {
    f[0] = hf_lo(u.x); f[1] = hf_hi(u.x); f[2] = hf_lo(u.y); f[3] = hf_hi(u.y);
    f[4] = hf_lo(u.z); f[5] = hf_hi(u.z); f[6] = hf_lo(u.w); f[7] = hf_hi(u.w);
}
__device__ __forceinline__ uint4 pack8b(const float* f) {
    return make_uint4(f2b2(f[0], f[1]), f2b2(f[2], f[3]), f2b2(f[4], f[5]), f2b2(f[6], f[7]));
}
__device__ __forceinline__ uint32_t h2u(__half2 h) { return *(uint32_t*)&h; }
__device__ __forceinline__ uint4 pack8h(const float* f) {
    return make_uint4(h2u(__floats2half2_rn(f[0], f[1])), h2u(__floats2half2_rn(f[2], f[3])),
                      h2u(__floats2half2_rn(f[4], f[5])), h2u(__floats2half2_rn(f[6], f[7])));
}
__device__ __forceinline__ void mma_bf16(float c[4],
    uint32_t a0, uint32_t a1, uint32_t a2, uint32_t a3, uint32_t b0, uint32_t b1)
{
    asm volatile(
        "mma.sync.aligned.m16n8k16.row.col.f32.bf16.bf16.f32 "
        "{%0,%1,%2,%3},{%4,%5,%6,%7},{%8,%9},{%0,%1,%2,%3};"
        : "+f"(c[0]), "+f"(c[1]), "+f"(c[2]), "+f"(c[3])
        : "r"(a0), "r"(a1), "r"(a2), "r"(a3), "r"(b0), "r"(b1));
}
__device__ __forceinline__ void ldsm_x4(uint32_t& r0, uint32_t& r1,
                                        uint32_t& r2, uint32_t& r3, uint32_t addr)
{
    asm volatile("ldmatrix.sync.aligned.m8n8.x4.shared.b16 {%0,%1,%2,%3}, [%4];"
        : "=r"(r0), "=r"(r1), "=r"(r2), "=r"(r3) : "r"(addr));
}

// ---------------- embeds fp32 -> bf16 table ----------------
__global__ void conv_embeds(const float* __restrict__ e)
{
    int i = blockIdx.x * blockDim.x + threadIdx.x;
    if (i < VOCAB * 16) {
        float4 a = *(const float4*)(e + (size_t)i * 8);
        float4 b = *(const float4*)(e + (size_t)i * 8 + 4);
        ((uint4*)g_embB)[i] = make_uint4(f2b2(a.x, a.y), f2b2(a.z, a.w),
                                         f2b2(b.x, b.y), f2b2(b.z, b.w));
    }
}

// ---------------- weight packing + loss zeroing ----------------
__global__ void pack_kernel(
    const float* __restrict__ Wix, const float* __restrict__ Wox,
    const float* __restrict__ Wux, const float* __restrict__ Wfx,
    const float* __restrict__ bix, const float* __restrict__ box_,
    const float* __restrict__ bux, const float* __restrict__ bfx,
    const float* __restrict__ Wih, const float* __restrict__ Woh,
    const float* __restrict__ Wuh, const float* __restrict__ Wfh,
    const float* __restrict__ bih, const float* __restrict__ boh,
    const float* __restrict__ buh, const float* __restrict__ bfh,
    const float* __restrict__ Wout, const float* __restrict__ bout)
{
    int idx = blockIdx.x * blockDim.x + threadIdx.x;
    if (idx < 4 * 128 * 64) {
        int nt = idx >> 13, rem = idx & 8191, n = rem >> 6, kp = rem & 63;
        const float* W = (nt == 0) ? Wix : (nt == 1) ? Wox : (nt == 2) ? Wux : Wfx;
        g_WxS[(size_t)nt * B_U32 + n * BLD + kp] = f2b2(W[n * H + 2 * kp], W[n * H + 2 * kp + 1]);
    }
    if (idx < 3 * 128 * 64) {
        int nt = idx >> 13, rem = idx & 8191, n = rem >> 6, kp = rem & 63;
        const float* W = (nt == 0) ? Wih : (nt == 1) ? Woh : Wuh;
        g_WhS[(size_t)nt * B_U32 + n * BLD + kp] = f2b2(W[n * H + 2 * kp], W[n * H + 2 * kp + 1]);
    }
    if (idx < 128 * 64) {
        int n = idx >> 6, kp = idx & 63;
        g_WfS[n * BLD + kp] = f2b2(Wfh[n * H + 2 * kp], Wfh[n * H + 2 * kp + 1]);
    }
    if (idx < 8 * 64) {
        int n = idx >> 6, kp = idx & 63;
        g_WoS[n * BLD + kp] = (n < NLABEL)
            ? f2b2(Wout[n * H + 2 * kp], Wout[n * H + 2 * kp + 1]) : 0u;
    }
    if (idx < 8) g_bo8[idx] = (idx < NLABEL) ? bout[idx] : 0.f;
    if (idx == 0) { g_barCnt = 0; g_barGen = 0; }
    if (idx < H * 384) {
        int d = idx / 384, c = idx % 384, g = c >> 7, r = c & 127;
        const float* W = (g == 0) ? Wih : (g == 1) ? Woh : Wuh;
        g_WhT[idx] = W[r * H + d];
    }
    if (idx < H * H) {
        int d = idx >> 7, r = idx & 127;
        g_WfhT[idx] = Wfh[r * H + d];
    }
    if (idx < 1024) g_loss[idx] = 0.0;
    if (idx < 512) {
        int g = idx >> 7, r = idx & 127;
        float v;
        if (g == 0) v = bix[r] + bih[r];
        else if (g == 1) v = box_[r] + boh[r];
        else if (g == 2) v = bux[r] + buh[r];
        else v = bfx[r];
        g_b2[idx] = v;
    }
    if (idx < H) g_bfh[idx] = bfh[idx];
}

// ---------------- bf16 MMA tile ----------------
template <int MODE, bool ACC, bool BIAS>
__device__ __forceinline__ void gemm_tile(
    uint32_t* As, uint32_t* Bs,
    const void* Av, const int* __restrict__ ridx,
    const uint32_t* __restrict__ Wblob, const float* __restrict__ bias,
    __nv_bfloat16* __restrict__ C, int ldc, int M, int brow, int bcol)
{
    const int t    = threadIdx.x;
    const int lane = t & 31;
    const int warp = t >> 5;
    const int mw   = warp & 1;
    const int nw   = warp >> 1;
    const int g    = lane >> 2;
    const int t4   = lane & 3;

    {
        const uint4* src = (const uint4*)Wblob;
        uint4* dst = (uint4*)Bs;
        #pragma unroll
        for (int i = 0; i < 9; i++) {
            int idx = t + i * 256;
            if (idx < B_U32 / 4) dst[idx] = src[idx];
        }
    }
    #pragma unroll
    for (int i = 0; i < 8; i++) {
        int lin = t + i * 256;
        int row = lin >> 4;
        int c   = lin & 15;
        uint4 val = make_uint4(0u, 0u, 0u, 0u);
        if (brow + row < M) {
            if (MODE == 1) {
                val = ((const uint4*)Av)[(size_t)ridx[brow + row] * 16 + c];
            } else if (MODE == 0) {
                val = *(const uint4*)((const __nv_bfloat16*)Av + (size_t)(brow + row) * H + c * 8);
            } else {
                const __nv_bfloat16* p0 = (const __nv_bfloat16*)Av + (size_t)(2 * (brow + row)) * H + c * 8;
                uint4 u = *(const uint4*)p0;
                uint4 v = *(const uint4*)(p0 + H);
                val.x = badd2(u.x, v.x); val.y = badd2(u.y, v.y);
                val.z = badd2(u.z, v.z); val.w = badd2(u.w, v.w);
            }
        }
        *(uint4*)&As[row * ALD + c * 4] = val;
    }
    __syncthreads();

    float acc[4][4][4];
    #pragma unroll
    for (int i = 0; i < 4; i++)
        #pragma unroll
        for (int j = 0; j < 4; j++)
            #pragma unroll
            for (int q = 0; q < 4; q++) acc[i][j][q] = 0.f;

    const uint32_t sA = (uint32_t)__cvta_generic_to_shared(As);
    const uint32_t sB = (uint32_t)__cvta_generic_to_shared(Bs);
    const uint32_t aBase = sA + (uint32_t)(((mw * 64 + (lane & 15)) * ALD + (lane >> 4) * 4) << 2);
    const uint32_t bBase = sB + (uint32_t)(((nw * 32 + (lane & 7) + ((lane >> 4) << 3)) * BLD) << 2)
                              + (uint32_t)(((lane >> 3) & 1) << 4);

    #pragma unroll
    for (int kb = 0; kb < 8; kb++) {
        uint32_t bf[4][2];
        ldsm_x4(bf[0][0], bf[0][1], bf[1][0], bf[1][1], bBase + kb * 32);
        ldsm_x4(bf[2][0], bf[2][1], bf[3][0], bf[3][1], bBase + 16 * BLD * 4 + kb * 32);
        #pragma unroll
        for (int mf = 0; mf < 4; mf++) {
            uint32_t a0, a1, a2, a3;
            ldsm_x4(a0, a1, a2, a3, aBase + mf * (16 * ALD * 4) + kb * 32);
            #pragma unroll
            for (int nf = 0; nf < 4; nf++)
                mma_bf16(acc[mf][nf], a0, a1, a2, a3, bf[nf][0], bf[nf][1]);
        }
    }

    #pragma unroll
    for (int mf = 0; mf < 4; mf++) {
        #pragma unroll
        for (int nf = 0; nf < 4; nf++) {
            int row = brow + mw * 64 + mf * 16 + g;
            int col = bcol + nw * 32 + nf * 8 + 2 * t4;
            float b0 = 0.f, b1 = 0.f;
            if (BIAS) { b0 = bias[col]; b1 = bias[col + 1]; }
            if (row < M) {
                uint32_t* p = (uint32_t*)(C + (size_t)row * ldc + col);
                float v0 = acc[mf][nf][0] + b0;
                float v1 = acc[mf][nf][1] + b1;
                if (ACC) { uint32_t o = *p; v0 += bf_lo(o); v1 += bf_hi(o); }
                *p = f2b2(v0, v1);
            }
            if (row + 8 < M) {
                uint32_t* p = (uint32_t*)(C + (size_t)(row + 8) * ldc + col);
                float v0 = acc[mf][nf][2] + b0;
                float v1 = acc[mf][nf][3] + b1;
                if (ACC) { uint32_t o = *p; v0 += bf_lo(o); v1 += bf_hi(o); }
                *p = f2b2(v0, v1);
            }
        }
    }
}

// ---------------- logits tile (LG[brow..brow+127][0..7] = h @ Wout^T + bout) ----------------
__device__ __forceinline__ void lgits_tile(uint32_t* As, uint32_t* Bs, int brow)
{
    const int t = threadIdx.x, lane = t & 31, w = t >> 5;
    if (t < 8 * BLD / 4) ((uint4*)Bs)[t] = ((const uint4*)g_WoS)[t];
    #pragma unroll
    for (int i = 0; i < 8; i++) {
        int lin = t + i * 256, row = lin >> 4, c = lin & 15;
        uint4 val = make_uint4(0u, 0u, 0u, 0u);
        if (brow + row < NNODES)
            val = *(const uint4*)(g_hAll + (size_t)(brow + row) * H + c * 8);
        *(uint4*)&As[row * ALD + c * 4] = val;
    }
    __syncthreads();

    float acc[4] = {0.f, 0.f, 0.f, 0.f};
    const uint32_t sA = (uint32_t)__cvta_generic_to_shared(As);
    const uint32_t sB = (uint32_t)__cvta_generic_to_shared(Bs);
    const uint32_t aBase = sA + (uint32_t)(((w * 16 + (lane & 15)) * ALD + (lane >> 4) * 4) << 2);
    const uint32_t bBase = sB + (uint32_t)(((lane & 7) * BLD) << 2)
                              + (uint32_t)(((lane >> 3) & 1) << 4);
    #pragma unroll
    for (int kb = 0; kb < 8; kb++) {
        uint32_t a0, a1, a2, a3, b0, b1;
        ldsm_x4(a0, a1, a2, a3, aBase + kb * 32);
        asm volatile("ldmatrix.sync.aligned.m8n8.x2.shared.b16 {%0,%1}, [%2];"
            : "=r"(b0), "=r"(b1) : "r"(bBase + kb * 32));
        mma_bf16(acc, a0, a1, a2, a3, b0, b1);
    }
    const int g = lane >> 2, t4 = lane & 3;
    const int row0 = brow + w * 16 + g;
    const int col = 2 * t4;
    if (row0 < NNODES) {
        float* p = g_LG + (size_t)row0 * 8 + col;
        p[0] = acc[0] + g_bo8[col]; p[1] = acc[1] + g_bo8[col + 1];
    }
    if (row0 + 8 < NNODES) {
        float* p = g_LG + (size_t)(row0 + 8) * 8 + col;
        p[0] = acc[2] + g_bo8[col]; p[1] = acc[3] + g_bo8[col + 1];
    }
}

// ---------------- xgemm phase 1: m-tiles 511..2047 ----------------
__global__ void __launch_bounds__(256, 2) xgemm_mm(const int* __restrict__ words)
{
    extern __shared__ uint32_t smu[];
    uint32_t* As = smu;
    uint32_t* Bs = smu + A_U32;
    int bx = blockIdx.x, m, nt;
    if (bx < XG1_N4 * 4) { m = XG1_MT0 + (bx >> 2); nt = bx & 3; }
    else { int r2 = bx - XG1_N4 * 4; m = 1024 + r2 / 3; nt = r2 % 3; }
    gemm_tile<1, false, true>(As, Bs, g_embB, words, g_WxS + (size_t)nt * B_U32,
                              g_b2, g_XG, 512, NNODES, m * 128, nt * 128);
}

// ---------------- mid phase: xgemm tiles 0..510 + lvl16 h/f-GEMM + leaf logits ----------------
__global__ void __launch_bounds__(256, 2) mid_mm(const int* __restrict__ words)
{
    extern __shared__ uint32_t smu[];
    uint32_t* As = smu;
    uint32_t* Bs = smu + A_U32;
    int bx = blockIdx.x;
    if (bx < MID_XG) {
        int m = bx >> 2, nt = bx & 3;
        gemm_tile<1, false, true>(As, Bs, g_embB, words, g_WxS + (size_t)nt * B_U32,
                                  g_b2, g_XG, 512, NNODES, m * 128, nt * 128);
    } else if (bx < MID_L16_END) {
        int b2 = bx - MID_XG;
        const __nv_bfloat16* h_ch = g_hAll + (size_t)(2 * L16_N - 1) * H;
        if (b2 < 512 * 3) {
            int m = b2 / 3, nt = b2 % 3;
            gemm_tile<2, true, false>(As, Bs, h_ch, nullptr, g_WhS + (size_t)nt * B_U32, nullptr,
                                      g_XG + (size_t)L16_OFF * 512, 512, L16_N, m * 128, nt * 128);
        } else {
            int m = b2 - 512 * 3;
            gemm_tile<0, false, true>(As, Bs, h_ch, nullptr, g_WfS, g_bfh,
                                      g_FH, 128, 2 * L16_N, m * 128, 0);
        }
    } else {
        int m = 1024 + (bx - MID_L16_END);
        lgits_tile(As, Bs, m * 128);
    }
}

// ---------------- per-level h-GEMM + f-GEMM + folded lgits tiles ----------------
// lg_start: first lgits m-tile folded into this launch; blocks beyond nbm*5+nbf handle them.
__global__ void __launch_bounds__(256, 2) level_mm(int n, int off, int chd, int lg_start)
{
    extern __shared__ uint32_t smu[];
    uint32_t* As = smu;
    uint32_t* Bs = smu + A_U32;
    const __nv_bfloat16* h_ch = g_hAll + (size_t)(2 * n - 1) * H;
    int nbm = n >> 7;
    int bx = blockIdx.x;
    if (bx < nbm * 3) {
        int m = bx / 3, nt = bx % 3;
        gemm_tile<2, true, false>(As, Bs, h_ch, nullptr, g_WhS + (size_t)nt * B_U32, nullptr,
                                  g_XG + (size_t)off * 512, 512, n, m * 128, nt * 128);
    } else if (bx < nbm * 5) {
        int m = bx - nbm * 3;
        gemm_tile<0, false, true>(As, Bs, h_ch, nullptr, g_WfS, g_bfh,
                                  g_FH, 128, 2 * n, m * 128, 0);
    } else {
        int m = lg_start + (bx - nbm * 5);
        lgits_tile(As, Bs, m * 128);
    }
}

// ---------------- per-node gates + cell (vectorized: 8 elems/thread) ----------------
__global__ void __launch_bounds__(256) node_update(int off, int cur, int chd, int isLeaf, int n)
{
    int idx = blockIdx.x * blockDim.x + threadIdx.x;
    if (idx >= n * 16) return;
    const int j = idx >> 4;
    const int q = idx & 15;

    const __nv_bfloat16* xg = g_XG + (size_t)(off + j) * 512 + q * 8;
    uint4 ui = *(const uint4*)xg;
    uint4 uo = *(const uint4*)(xg + 128);
    uint4 uu = *(const uint4*)(xg + 256);
    float xi[8], xo[8], xu[8], cc[8], hh[8];
    unp8b(ui, xi); unp8b(uo, xo); unp8b(uu, xu);
    #pragma unroll
    for (int e = 0; e < 8; e++) cc[e] = fsigm(xi[e]) * ftanh(xu[e]);

    if (!isLeaf) {
        uint4 uf = *(const uint4*)(xg + 384);
        const __nv_bfloat16* fh = g_FH + (size_t)(2 * j) * H + q * 8;
        uint4 f0u = *(const uint4*)fh;
        uint4 f1u = *(const uint4*)(fh + H);
        const __half* cb = g_cbuf[chd] + (size_t)(2 * j) * H + q * 8;
        uint4 c0u = *(const uint4*)cb;
        uint4 c1u = *(const uint4*)(cb + H);
        float xf[8], g0[8], g1[8], d0[8], d1[8];
        unp8b(uf, xf); unp8b(f0u, g0); unp8b(f1u, g1);
        unp8h(c0u, d0); unp8h(c1u, d1);
        #pragma unroll
        for (int e = 0; e < 8; e++)
            cc[e] += fsigm(xf[e] + g0[e]) * d0[e] + fsigm(xf[e] + g1[e]) * d1[e];
    }
    #pragma unroll
    for (int e = 0; e < 8; e++) hh[e] = fsigm(xo[e]) * ftanh(cc[e]);

    *(uint4*)(g_cbuf[cur] + (size_t)j * H + q * 8) = pack8h(cc);
    *(uint4*)(g_hAll + (size_t)(off + j) * H + q * 8) = pack8b(hh);
}

// ---------------- fused small levels (l = 6..0) ----------------
__global__ void __launch_bounds__(128) small_fused()
{
    const int j = blockIdx.x;
    const int k = threadIdx.x;
    __shared__ float hs[H], h0s[H], h1s[H];

    for (int l = 6; l >= 0; --l) {
        const int n = 1 << l;
        const int off = n - 1;
        const int cur = l & 1, chd = cur ^ 1;
        if (j < n) {
            const __nv_bfloat16* h_ch = g_hAll + (size_t)(2 * (off + j) + 1) * H;
            float h0 = __bfloat162float(h_ch[k]);
            float h1 = __bfloat162float(h_ch[H + k]);
            h0s[k] = h0; h1s[k] = h1; hs[k] = h0 + h1;
            __syncthreads();

            const __nv_bfloat16* xg = g_XG + (size_t)(off + j) * 512;
            float ai = __bfloat162float(xg[k]);
            float ao = __bfloat162float(xg[128 + k]);
            float au = __bfloat162float(xg[256 + k]);
            float xf = __bfloat162float(xg[384 + k]);
            float f0 = g_bfh[k], f1 = g_bfh[k];
            #pragma unroll 8
            for (int d = 0; d < H; d++) {
                float hd = hs[d];
                ai += hd * g_WhT[d * 384 + k];
                ao += hd * g_WhT[d * 384 + 128 + k];
                au += hd * g_WhT[d * 384 + 256 + k];
                float w = g_WfhT[d * 128 + k];
                f0 += h0s[d] * w;
                f1 += h1s[d] * w;
            }
            size_t cb = (size_t)(2 * j) * H + k;
            float gi = fsigm(ai), go = fsigm(ao), gu = ftanh(au);
            float c = gi * gu + fsigm(xf + f0) * __half2float(g_cbuf[chd][cb])
                              + fsigm(xf + f1) * __half2float(g_cbuf[chd][cb + H]);
            float h = go * ftanh(c);
            g_cbuf[cur][(size_t)j * H + k] = __float2half(c);
            g_hAll[(size_t)(off + j) * H + k] = __float2bfloat16(h);
            __syncthreads();
        }
        if (l == 0) break;
        __threadfence();
        __syncthreads();
        if (k == 0) {
            unsigned gen = g_barGen;
            if (atomicAdd(&g_barCnt, 1u) == 63u) {
                g_barCnt = 0u;
                __threadfence();
                g_barGen = gen + 1u;
            } else {
                while (g_barGen == gen) { }
            }
        }
        __syncthreads();
        __threadfence();
    }
}

// ---------------- final logits GEMM: tiles 0..1 (rows 0..255) ----------------
__global__ void __launch_bounds__(256) lgits_mm()
{
    extern __shared__ uint32_t smu[];
    uint32_t* As = smu;
    uint32_t* Bs = smu + A_U32;
    lgits_tile(As, Bs, blockIdx.x * 128);
}

// ---------------- flat loss over all nodes (+ root logp) ----------------
__global__ void loss_kernel(const int* __restrict__ labels,
                            float* __restrict__ out, int out_size)
{
    int idx = blockIdx.x * blockDim.x + threadIdx.x;
    if (idx >= NNODES) return;
    const float* lg = g_LG + (size_t)idx * 8;
    float l0 = lg[0], l1 = lg[1], l2 = lg[2], l3 = lg[3], l4 = lg[4];
    float m = fmaxf(fmaxf(fmaxf(l0, l1), fmaxf(l2, l3)), l4);
    float s = __expf(l0 - m) + __expf(l1 - m) + __expf(l2 - m)
            + __expf(l3 - m) + __expf(l4 - m);
    float lse = m + __logf(s);
    int lab = labels[idx];
    float lgl = (lab == 0) ? l0 : (lab == 1) ? l1 : (lab == 2) ? l2 : (lab == 3) ? l3 : l4;
    atomicAdd(&g_loss[idx & 1023], (double)(lse - lgl));
    if (idx == 0 && out_size >= NLABEL + 1) {
        out[0] = l0 - lse; out[1] = l1 - lse; out[2] = l2 - lse;
        out[3] = l3 - lse; out[4] = l4 - lse;
    }
}

// ---------------- loss reduction ----------------
__global__ void finalize_kernel(float* __restrict__ d_out, int out_size)
{
    __shared__ double s[256];
    int t = threadIdx.x;
    s[t] = g_loss[t] + g_loss[t + 256] + g_loss[t + 512] + g_loss[t + 768];
    __syncthreads();
    for (int offx = 128; offx; offx >>= 1) {
        if (t < offx) s[t] += s[t + offx];
        __syncthreads();
    }
    if (t == 0) {
        if (out_size >= NLABEL + 1) d_out[NLABEL] = (float)s[0];
        else                        d_out[0]      = (float)s[0];
    }
}

// ---------------- launch ----------------
extern "C" void kernel_launch(void* const* d_in, const int* in_sizes, int n_in,
                              void* d_out, int out_size)
{
    const float* embeds = (const float*)d_in[0];
    const int*   words  = (const int*)d_in[1];
    const int*   labels = (const int*)d_in[2];
    const float* Wix = (const float*)d_in[5];
    const float* bix = (const float*)d_in[6];
    const float* Wih = (const float*)d_in[7];
    const float* bih = (const float*)d_in[8];
    const float* Wfx = (const float*)d_in[9];
    const float* bfx = (const float*)d_in[10];
    const float* Wfh = (const float*)d_in[11];
    const float* bfh = (const float*)d_in[12];
    const float* Wox = (const float*)d_in[13];
    const float* box_ = (const float*)d_in[14];
    const float* Woh = (const float*)d_in[15];
    const float* boh = (const float*)d_in[16];
    const float* Wux = (const float*)d_in[17];
    const float* bux = (const float*)d_in[18];
    const float* Wuh = (const float*)d_in[19];
    const float* buh = (const float*)d_in[20];
    const float* Wout = (const float*)d_in[21];
    const float* bout = (const float*)d_in[22];
    float* out = (float*)d_out;

    cudaFuncSetAttribute(xgemm_mm, cudaFuncAttributeMaxDynamicSharedMemorySize, SMEM_DYN);
    cudaFuncSetAttribute(mid_mm,   cudaFuncAttributeMaxDynamicSharedMemorySize, SMEM_DYN);
    cudaFuncSetAttribute(level_mm, cudaFuncAttributeMaxDynamicSharedMemorySize, SMEM_DYN);
    cudaFuncSetAttribute(lgits_mm, cudaFuncAttributeMaxDynamicSharedMemorySize, SMEM_DYN);

    pack_kernel<<<256, 256>>>(Wix, Wox, Wux, Wfx, bix, box_, bux, bfx,
                              Wih, Woh, Wuh, Wfh, bih, boh, buh, bfh, Wout, bout);
    conv_embeds<<<(VOCAB * 16 + 255) / 256, 256>>>(embeds);

    // phase 1: XG for rows 65408.. (lvl15 boundary tile, lvl16, leaves)
    xgemm_mm<<<XG1_BLKS, 256, SMEM_DYN>>>(words);
    // leaves (l=17): cur = 1
    node_update<<<(NLEAF * 16 + 255) / 256, 256>>>(NLEAF - 1, 1, 0, 1, NLEAF);
    // mid: XG rows 0..65407  +  lvl16 h/f-GEMM  +  leaf logits (tiles 1024..2047)
    mid_mm<<<MID_BLKS, 256, SMEM_DYN>>>(words);
    // lvl16 node update (cur = 0, chd = 1)
    node_update<<<(L16_N * 16 + 255) / 256, 256>>>(L16_OFF, 0, 1, 0, L16_N);

    // per-level chain; fold lgits tiles [s(l+1), 2*s(l+1)) of the just-finished
    // level l+1 into level_mm(l).  s(l) = 2^(l-7).
    for (int l = 15; l >= 7; --l) {
        int n   = 1 << l;
        int off = n - 1;
        int cur = l & 1, chd = cur ^ 1;
        int nbm = n >> 7;
        int lg_start = 1 << (l + 1 - 7);      // s(l+1)
        int lg_cnt   = lg_start;               // s(l+1) tiles
        level_mm<<<nbm * 5 + lg_cnt, 256, SMEM_DYN>>>(n, off, chd, lg_start);
        node_update<<<(n * 16 + 255) / 256, 256>>>(off, cur, chd, 0, n);
    }
    small_fused<<<64, 128>>>();

    // remaining lgits: tiles 0..1 (rows 0..255, levels <= 7 remainder)
    lgits_mm<<<2, 256, SMEM_DYN>>>();
    loss_kernel<<<(NNODES + 255) / 256, 256>>>(labels, out, out_size);
    finalize_kernel<<<1, 256>>>(out, out_size);
}